// round 8
// baseline (speedup 1.0000x reference)
#include <cuda_runtime.h>
#include <math.h>
#include <stdint.h>

#define BB   4
#define NN   16384
#define CIN  128
#define COUT 256
#define HH   256
#define WW   256
#define NP   65536      // N0 = H*W points
#define HD   128
#define WD   128
#define HC   64
#define WC   64
#define NS   4096       // HC*WC
#define EPSV 1e-6f
#define KTOT 1152       // 9*CIN
#define SLABS 36        // KTOT/32

// ---------------- scratch (device globals: no allocation allowed) ----------------
__device__ float  g_ssum[(size_t)BB*HH*WW*CIN];   // token2map sum -> normalized tf32 map (128MB)
__device__ float  g_cnt [(size_t)BB*HH*WW];       // token2map count
__device__ float  g_y   [(size_t)BB*HD*WD*COUT];  // conv output        (64MB)
__device__ float  g_num [(size_t)BB*NN*COUT];     // map2token num -> tok (64MB)
__device__ float  g_den [(size_t)BB*NN];
__device__ float  g_tokn[(size_t)BB*NN*COUT];     // BN-normalized tokens (64MB)
__device__ float  g_wexp[(size_t)BB*NN];          // exp(conf)
__device__ double g_bnsum[COUT];
__device__ double g_bnsq [COUT];
__device__ float  g_scale[COUT];
__device__ float  g_shift[COUT];
__device__ float  g_cnum[(size_t)BB*NS*COUT];     // cluster num (16MB)
__device__ float  g_cden[(size_t)BB*NS];
__device__ float  g_wpt [(size_t)BB*NP];          // per-point weight, reused
__device__ unsigned g_maxw[BB];
__device__ float  g_wT  [CIN*COUT];               // skip_w transposed [k][n]
__device__ float4 g_wBp [(size_t)SLABS*2048];     // conv weights, pre-swizzled smem image per slab

// ---------------- helpers ----------------
__device__ __forceinline__ void red_add4(float* p, float4 v) {
    asm volatile("red.global.add.v4.f32 [%0], {%1,%2,%3,%4};"
                 :: "l"(__cvta_generic_to_global(p)),
                    "f"(v.x), "f"(v.y), "f"(v.z), "f"(v.w) : "memory");
}

__device__ __forceinline__ int grid_cell(float lx, float ly, int Hg, int Wg) {
    lx = fminf(fmaxf(lx, -1.f), 1.f);
    ly = fminf(fmaxf(ly, -1.f), 1.f);
    int px = min(max(__float2int_rn(0.5f*(lx+1.f)*(float)Wg - 0.5f), 0), Wg-1);
    int py = min(max(__float2int_rn(0.5f*(ly+1.f)*(float)Hg - 0.5f), 0), Hg-1);
    return py*Wg + px;
}

__device__ __forceinline__ float to_tf32(float x) {
    uint32_t u; asm("cvt.rna.tf32.f32 %0, %1;" : "=r"(u) : "f"(x));
    return __uint_as_float(u);
}
__device__ __forceinline__ float4 tf4(float4 v) {
    return make_float4(to_tf32(v.x), to_tf32(v.y), to_tf32(v.z), to_tf32(v.w));
}

__device__ __forceinline__ uint32_t smem_u32(const void* p) {
    uint32_t a;
    asm("{ .reg .u64 t; cvta.to.shared.u64 t, %1; cvt.u32.u64 %0, t; }" : "=r"(a) : "l"(p));
    return a;
}

__device__ __forceinline__ void cpa16(uint32_t dst, const float* src, int srcsz) {
    asm volatile("cp.async.cg.shared.global [%0], [%1], 16, %2;"
                 :: "r"(dst), "l"(__cvta_generic_to_global(src)), "r"(srcsz) : "memory");
}

__device__ __forceinline__ void mma8(float& d0, float& d1, float& d2, float& d3,
                                     float a0, float a1, float a2, float a3,
                                     float b0, float b1) {
    asm volatile("mma.sync.aligned.m16n8k8.row.col.f32.tf32.tf32.f32 "
                 "{%0,%1,%2,%3},{%4,%5,%6,%7},{%8,%9},{%0,%1,%2,%3};"
                 : "+f"(d0), "+f"(d1), "+f"(d2), "+f"(d3)
                 : "r"(__float_as_uint(a0)), "r"(__float_as_uint(a1)),
                   "r"(__float_as_uint(a2)), "r"(__float_as_uint(a3)),
                   "r"(__float_as_uint(b0)), "r"(__float_as_uint(b1)));
}

// ---------------- kernels ----------------
// fused: zero all accumulators + transpose skip_w + build pre-swizzled conv-B image
__global__ void k_init(const float* __restrict__ skw, const float* __restrict__ cw) {
    size_t t = (size_t)blockIdx.x*blockDim.x + threadIdx.x;
    size_t stride = (size_t)gridDim.x*blockDim.x;
    float4 z = make_float4(0.f,0.f,0.f,0.f);
    for (size_t i=t; i < (size_t)BB*HH*WW*CIN/4; i+=stride) ((float4*)g_ssum)[i]=z;
    for (size_t i=t; i < (size_t)BB*HH*WW/4;     i+=stride) ((float4*)g_cnt )[i]=z;
    for (size_t i=t; i < (size_t)BB*NN*COUT/4;   i+=stride) ((float4*)g_num )[i]=z;
    for (size_t i=t; i < (size_t)BB*NN/4;        i+=stride) ((float4*)g_den )[i]=z;
    for (size_t i=t; i < (size_t)BB*NS*COUT/4;   i+=stride) ((float4*)g_cnum)[i]=z;
    for (size_t i=t; i < (size_t)BB*NS/4;        i+=stride) ((float4*)g_cden)[i]=z;
    if (t < COUT) { g_bnsum[t]=0.0; g_bnsq[t]=0.0; }
    if (t < BB)   g_maxw[t]=0u;
    if (t < CIN*COUT)
        g_wT[t] = skw[((int)t % COUT)*CIN + ((int)t / COUT)];
    if (t < (size_t)SLABS*2048) {
        int fi = (int)t;
        int s  = fi >> 11, r = fi & 2047;
        int nt = r >> 6, h2 = (r >> 5) & 1, g = (r >> 2) & 7, c = r & 3;
        int n  = nt*8 + g;
        int k0 = s*32 + h2*16 + c;
        float4 v = make_float4(cw[(size_t)k0*COUT + n],      cw[(size_t)(k0+4)*COUT + n],
                               cw[(size_t)(k0+8)*COUT + n],  cw[(size_t)(k0+12)*COUT + n]);
        g_wBp[fi] = tf4(v);
    }
}

// scatter token features to H x W map (sum + count)
__global__ void k_token2map(const float* __restrict__ x, const float* __restrict__ loc,
                            const int* __restrict__ idx_agg) {
    int p    = blockIdx.x*8 + (threadIdx.x>>5);
    int lane = threadIdx.x & 31;
    int b    = p >> 16;
    float lx = loc[2*p], ly = loc[2*p+1];
    int cell = grid_cell(lx, ly, HH, WW);
    int i    = idx_agg[p];
    const float4* src = (const float4*)(x + ((size_t)b*NN + i)*CIN);
    float* dst = g_ssum + ((size_t)b*HH*WW + cell)*CIN;
    float4 v = src[lane];
    red_add4(dst + lane*4, v);
    if (!lane) atomicAdd(&g_cnt[(size_t)b*HH*WW + cell], 1.0f);
}

// normalize map in place AND round to tf32: ssum = tf32(ssum / (cnt + eps))
__global__ void k_norm() {
    size_t i = (size_t)blockIdx.x*256 + threadIdx.x;
    float rcp = 1.f/(g_cnt[i >> 5] + EPSV);
    float4 v = ((float4*)g_ssum)[i];
    v.x*=rcp; v.y*=rcp; v.z*=rcp; v.w*=rcp;
    ((float4*)g_ssum)[i] = tf4(v);
}

// ---- 3x3 stride-2 conv as implicit GEMM on mma.sync TF32, 3-stage cp.async pipeline ----
// CTA: oy=blockIdx.x, b=blockIdx.y. 512 threads / 16 warps, warp tile 32m x 64n.
// M=128 pixels (ox), N=256 couts, K=1152 = 36 x K32.
#define CV_BUF   49152
#define CV_A(i)  ((i)*CV_BUF)
#define CV_B(i)  ((i)*CV_BUF + 16384)
#define CV_BIAS  (3*CV_BUF)
#define CV_SMEM  (CV_BIAS + 1024)

__device__ __forceinline__ void cv_stage(uint32_t sb, int s, int buf,
                                         int oy, const float* __restrict__ xin, int tid) {
    int tap = s >> 2, cinb = (s & 3) * 32;
    int ky = tap / 3, kx = tap - 3*ky;
    int iy = 2*oy - 1 + ky;
    bool iyok = (unsigned)iy < HH;
    int r = tid >> 2, q0 = (tid & 3) * 2;        // 512 threads: 2 A-chunks each
    int ix = 2*r - 1 + kx;
    bool ok = iyok && ((unsigned)ix < WW);
    const float* src = xin + ((size_t)(iyok ? iy : 0)*WW + (ok ? ix : 0))*CIN + cinb;
    uint32_t dstA = sb + CV_A(buf) + r*128;
    int sz = ok ? 16 : 0;
    int sw = r & 7;
    #pragma unroll
    for (int j = 0; j < 2; j++) {
        int q = q0 + j;
        cpa16(dstA + ((q ^ sw) * 16), src + q*4, sz);
    }
    const float4* bsrc = g_wBp + (size_t)s*2048 + tid*4;   // 4 B-chunks each
    uint32_t dstB = sb + CV_B(buf) + tid*64;
    #pragma unroll
    for (int j = 0; j < 4; j++)
        cpa16(dstB + j*16, (const float*)(bsrc + j), 16);
    asm volatile("cp.async.commit_group;" ::: "memory");
}

__device__ __forceinline__ float ldsA(const float* sA, int r, int k) {
    int kk = ((((k >> 2) ^ (r & 7)) << 2) | (k & 3));
    return sA[r*32 + kk];
}

__global__ void __launch_bounds__(512, 1) k_conv(const float* __restrict__ cb) {
    extern __shared__ char smem[];
    uint32_t sb = smem_u32(smem);
    int tid = threadIdx.x, w = tid >> 5, lane = tid & 31;
    int g = lane >> 2, cl = lane & 3;
    int wm = w & 3, wn = w >> 2;                 // warp tile 32m x 64n
    int oy = blockIdx.x, b = blockIdx.y;
    const float* xin = g_ssum + (size_t)b*HH*WW*CIN;

    if (tid < 256) *(float*)(smem + CV_BIAS + tid*4) = cb[tid];

    float acc[2][8][4];
    #pragma unroll
    for (int mt=0;mt<2;mt++) for (int nt=0;nt<8;nt++) for (int r2=0;r2<4;r2++) acc[mt][nt][r2]=0.f;

    cv_stage(sb, 0, 0, oy, xin, tid);
    cv_stage(sb, 1, 1, oy, xin, tid);

    int bufc = 0;                                  // buffer of slab s
    for (int s = 0; s < SLABS; s++) {
        if (s < SLABS-1) asm volatile("cp.async.wait_group 1;" ::: "memory");
        else             asm volatile("cp.async.wait_group 0;" ::: "memory");
        __syncthreads();
        int bufn = bufc + 2; if (bufn >= 3) bufn -= 3;
        if (s + 2 < SLABS) cv_stage(sb, s + 2, bufn, oy, xin, tid);
        const float*  sA = (const float*) (smem + CV_A(bufc));
        const float4* sB = (const float4*)(smem + CV_B(bufc));

        // preload all A fragments for this slab (independent LDS.32 burst)
        float a[2][4][4];
        #pragma unroll
        for (int mt = 0; mt < 2; mt++) {
            int r0 = wm*32 + mt*16 + g;
            #pragma unroll
            for (int j = 0; j < 4; j++) {
                int kc = j*8 + cl;
                a[mt][j][0] = ldsA(sA, r0,     kc);
                a[mt][j][1] = ldsA(sA, r0 + 8, kc);
                a[mt][j][2] = ldsA(sA, r0,     kc + 4);
                a[mt][j][3] = ldsA(sA, r0 + 8, kc + 4);
            }
        }
        // per-nt B load followed immediately by its 4 MMAs -> crossbar/tensor overlap
        #pragma unroll
        for (int h2 = 0; h2 < 2; h2++) {
            #pragma unroll
            for (int nt = 0; nt < 8; nt++) {
                float4 bv = sB[(wn*8 + nt)*64 + h2*32 + g*4 + cl];
                #pragma unroll
                for (int mt = 0; mt < 2; mt++) {
                    mma8(acc[mt][nt][0], acc[mt][nt][1], acc[mt][nt][2], acc[mt][nt][3],
                         a[mt][2*h2][0], a[mt][2*h2][1], a[mt][2*h2][2], a[mt][2*h2][3],
                         bv.x, bv.y);
                    mma8(acc[mt][nt][0], acc[mt][nt][1], acc[mt][nt][2], acc[mt][nt][3],
                         a[mt][2*h2+1][0], a[mt][2*h2+1][1], a[mt][2*h2+1][2], a[mt][2*h2+1][3],
                         bv.z, bv.w);
                }
            }
        }
        bufc++; if (bufc >= 3) bufc = 0;
    }

    // epilogue: D frag (m16n8): d0,d1 @ (g, 2c+{0,1}); d2,d3 @ (g+8, 2c+{0,1})
    const float* bias = (const float*)(smem + CV_BIAS);
    float* ybase = g_y + (((size_t)b*HD + oy)*WD)*COUT;
    #pragma unroll
    for (int mt = 0; mt < 2; mt++) {
        int ox0 = wm*32 + mt*16 + g;
        #pragma unroll
        for (int nt = 0; nt < 8; nt++) {
            int n = wn*64 + nt*8 + cl*2;
            float b0 = bias[n], b1 = bias[n+1];
            *(float2*)(ybase + (size_t)ox0*COUT + n)     = make_float2(acc[mt][nt][0]+b0, acc[mt][nt][1]+b1);
            *(float2*)(ybase + (size_t)(ox0+8)*COUT + n) = make_float2(acc[mt][nt][2]+b0, acc[mt][nt][3]+b1);
        }
    }
}

// bilinear gather from conv map at orig points, weighted scatter to tokens
__global__ void k_map2token(const float* __restrict__ loc, const int* __restrict__ idx_agg,
                            const float* __restrict__ aggw) {
    int p    = blockIdx.x*8 + (threadIdx.x>>5);
    int lane = threadIdx.x & 31;
    int b    = p >> 16;
    float lx = fminf(fmaxf(loc[2*p],   -1.f), 1.f);
    float ly = fminf(fmaxf(loc[2*p+1], -1.f), 1.f);
    float fx = fminf(fmaxf(0.5f*(lx+1.f)*(float)WD - 0.5f, 0.f), (float)(WD-1));
    float fy = fminf(fmaxf(0.5f*(ly+1.f)*(float)HD - 0.5f, 0.f), (float)(HD-1));
    float x0f = floorf(fx), y0f = floorf(fy);
    float wx = fx - x0f, wy = fy - y0f;
    int x0 = (int)x0f, y0 = (int)y0f;
    int x1 = min(x0+1, WD-1), y1 = min(y0+1, HD-1);
    const float* base = g_y + (size_t)b*HD*WD*COUT;
    const float4* r00 = (const float4*)(base + (size_t)(y0*WD+x0)*COUT);
    const float4* r01 = (const float4*)(base + (size_t)(y0*WD+x1)*COUT);
    const float4* r10 = (const float4*)(base + (size_t)(y1*WD+x0)*COUT);
    const float4* r11 = (const float4*)(base + (size_t)(y1*WD+x1)*COUT);
    float w00=(1.f-wx)*(1.f-wy), w01=wx*(1.f-wy), w10=(1.f-wx)*wy, w11=wx*wy;
    float wpt = aggw[p];
    int i = idx_agg[p];
    float* dst = g_num + ((size_t)b*NN + i)*COUT;
    #pragma unroll
    for (int q = 0; q < 2; q++) {
        int c4 = q*32 + lane;
        float4 a = r00[c4], bq = r01[c4], cc = r10[c4], d = r11[c4];
        float4 f;
        f.x = (w00*a.x + w01*bq.x + w10*cc.x + w11*d.x)*wpt;
        f.y = (w00*a.y + w01*bq.y + w10*cc.y + w11*d.y)*wpt;
        f.z = (w00*a.z + w01*bq.z + w10*cc.z + w11*d.z)*wpt;
        f.w = (w00*a.w + w01*bq.w + w10*cc.w + w11*d.w)*wpt;
        red_add4(dst + c4*4, f);
    }
    if (!lane) atomicAdd(&g_den[(size_t)b*NN + i], wpt);
}

// skip GEMM (x @ skip_w^T) fused with tok = num/(den+eps) + skip -> overwrite g_num
__global__ void __launch_bounds__(256) k_skip(const float* __restrict__ x) {
    __shared__ __align__(16) float As2[16][68];
    __shared__ __align__(16) float Bs2[16][64];
    int m0 = blockIdx.x*64, n0 = blockIdx.y*64;
    int tid = threadIdx.x;
    int tx = tid & 15, ty = tid >> 4;
    int m_l = tid >> 2, kq = (tid & 3)*4;
    int kb  = tid >> 4, nb = (tid & 15)*4;
    float acc[4][4] = {};
    const float* arow = x + (size_t)(m0 + m_l)*CIN;
    for (int cc = 0; cc < 8; cc++) {
        float4 va = *(const float4*)(arow + cc*16 + kq);
        __syncthreads();
        As2[kq+0][m_l]=va.x; As2[kq+1][m_l]=va.y; As2[kq+2][m_l]=va.z; As2[kq+3][m_l]=va.w;
        *(float4*)&Bs2[kb][nb] = *(const float4*)(g_wT + (size_t)(cc*16+kb)*COUT + n0 + nb);
        __syncthreads();
        #pragma unroll
        for (int k = 0; k < 16; k++) {
            float4 a  = *(float4*)&As2[k][ty*4];
            float4 bv = *(float4*)&Bs2[k][tx*4];
            acc[0][0]+=a.x*bv.x; acc[0][1]+=a.x*bv.y; acc[0][2]+=a.x*bv.z; acc[0][3]+=a.x*bv.w;
            acc[1][0]+=a.y*bv.x; acc[1][1]+=a.y*bv.y; acc[1][2]+=a.y*bv.z; acc[1][3]+=a.y*bv.w;
            acc[2][0]+=a.z*bv.x; acc[2][1]+=a.z*bv.y; acc[2][2]+=a.z*bv.z; acc[2][3]+=a.z*bv.w;
            acc[3][0]+=a.w*bv.x; acc[3][1]+=a.w*bv.y; acc[3][2]+=a.w*bv.z; acc[3][3]+=a.w*bv.w;
        }
    }
    #pragma unroll
    for (int i2 = 0; i2 < 4; i2++) {
        int row = m0 + ty*4 + i2;
        float rcp = 1.f/(g_den[row] + EPSV);
        float* orow = g_num + (size_t)row*COUT + n0 + tx*4;
        float4 nv = *(float4*)orow;
        float4 o = make_float4(acc[i2][0] + nv.x*rcp, acc[i2][1] + nv.y*rcp,
                               acc[i2][2] + nv.z*rcp, acc[i2][3] + nv.w*rcp);
        *(float4*)orow = o;
    }
}

__global__ void k_bnstats() {
    int c  = threadIdx.x;
    int r0 = blockIdx.x*256;
    double s = 0.0, s2 = 0.0;
    for (int r = 0; r < 256; r++) {
        float v = g_num[(size_t)(r0 + r)*COUT + c];
        s += v; s2 += (double)v*v;
    }
    atomicAdd(&g_bnsum[c], s);
    atomicAdd(&g_bnsq[c],  s2);
}

__global__ void k_bnfinal(const float* __restrict__ gam, const float* __restrict__ bet) {
    int c = threadIdx.x;
    double m  = (double)BB*NN;
    double mu = g_bnsum[c]/m;
    double var = g_bnsq[c]/m - mu*mu;
    float sc = gam[c] * (float)(1.0/sqrt(var + 1e-5));
    g_scale[c] = sc;
    g_shift[c] = bet[c] - (float)mu*sc;
}

__global__ void k_bnconf(const float* __restrict__ cw, const float* __restrict__ cbv,
                         float* __restrict__ out_xout, float* __restrict__ out_conf) {
    int row  = blockIdx.x*8 + (threadIdx.x>>5);
    int lane = threadIdx.x & 31;
    const float4* t  = (const float4*)(g_num  + (size_t)row*COUT);
    float4* tn       = (float4*)(g_tokn + (size_t)row*COUT);
    float4* xo       = (float4*)(out_xout + (size_t)row*COUT);
    float dot = 0.f;
    #pragma unroll
    for (int q = 0; q < 2; q++) {
        int c4 = q*32 + lane;
        float4 v  = t[c4];
        float4 sc = ((const float4*)g_scale)[c4];
        float4 sh = ((const float4*)g_shift)[c4];
        float4 w  = ((const float4*)cw)[c4];
        float4 r = make_float4(v.x*sc.x+sh.x, v.y*sc.y+sh.y, v.z*sc.z+sh.z, v.w*sc.w+sh.w);
        dot += r.x*w.x + r.y*w.y + r.z*w.z + r.w*w.w;
        tn[c4] = r;
        xo[c4] = make_float4(fmaxf(r.x,0.f), fmaxf(r.y,0.f), fmaxf(r.z,0.f), fmaxf(r.w,0.f));
    }
    #pragma unroll
    for (int o = 16; o; o >>= 1) dot += __shfl_xor_sync(0xffffffffu, dot, o);
    if (!lane) {
        float cf = dot + cbv[0];
        out_conf[row] = cf;
        g_wexp[row]   = expf(cf);
    }
}

__global__ void k_cluster(const float* __restrict__ loc, const int* __restrict__ idx_agg,
                          float* __restrict__ out_idx) {
    int p    = blockIdx.x*8 + (threadIdx.x>>5);
    int lane = threadIdx.x & 31;
    int b    = p >> 16;
    int cell = grid_cell(loc[2*p], loc[2*p+1], HC, WC);
    int i    = idx_agg[p];
    float w  = g_wexp[(size_t)b*NN + i];
    const float4* src = (const float4*)(g_tokn + ((size_t)b*NN + i)*COUT);
    float* dst = g_cnum + ((size_t)b*NS + cell)*COUT;
    #pragma unroll
    for (int q = 0; q < 2; q++) {
        int c4 = q*32 + lane;
        float4 v = src[c4];
        red_add4(dst + c4*4, make_float4(v.x*w, v.y*w, v.z*w, v.w*w));
    }
    if (!lane) {
        atomicAdd(&g_cden[(size_t)b*NS + cell], w);
        g_wpt[p]   = w;
        out_idx[p] = (float)cell;
    }
}

__global__ void k_xdown(float* __restrict__ out_xd) {
    int row  = blockIdx.x*8 + (threadIdx.x>>5);
    int lane = threadIdx.x & 31;
    float rcp = 1.f/(g_cden[row] + EPSV);
    const float4* src = (const float4*)(g_cnum + (size_t)row*COUT);
    float4* dst = (float4*)(out_xd + (size_t)row*COUT);
    #pragma unroll
    for (int q = 0; q < 2; q++) {
        int c4 = q*32 + lane;
        float4 v = src[c4];
        dst[c4] = make_float4(fmaxf(v.x*rcp,0.f), fmaxf(v.y*rcp,0.f),
                              fmaxf(v.z*rcp,0.f), fmaxf(v.w*rcp,0.f));
    }
}

__global__ void k_aggmax(const float* __restrict__ loc, const float* __restrict__ aggw) {
    __shared__ float sm[256];
    int p = blockIdx.x*256 + threadIdx.x;
    int b = p >> 16;
    int cell = grid_cell(loc[2*p], loc[2*p+1], HC, WC);
    float aw = aggw[p] * g_wpt[p] / (g_cden[(size_t)b*NS + cell] + EPSV);
    g_wpt[p] = aw;
    sm[threadIdx.x] = aw;
    __syncthreads();
    for (int s = 128; s; s >>= 1) {
        if (threadIdx.x < s) sm[threadIdx.x] = fmaxf(sm[threadIdx.x], sm[threadIdx.x+s]);
        __syncthreads();
    }
    if (!threadIdx.x) atomicMax(&g_maxw[b], __float_as_uint(sm[0]));
}

__global__ void k_aggnorm(float* __restrict__ out_aw) {
    int p = blockIdx.x*256 + threadIdx.x;
    int b = p >> 16;
    out_aw[p] = g_wpt[p] / __uint_as_float(g_maxw[b]);
}

// ---------------- launch ----------------
extern "C" void kernel_launch(void* const* d_in, const int* in_sizes, int n_in,
                              void* d_out, int out_size) {
    const float* x      = (const float*)d_in[0];
    const float* loc    = (const float*)d_in[1];
    const int*   idxa   = (const int*)  d_in[2];
    const float* aggw   = (const float*)d_in[3];
    const float* conv_w = (const float*)d_in[4];
    const float* conv_b = (const float*)d_in[5];
    const float* skip_w = (const float*)d_in[6];
    const float* gamma  = (const float*)d_in[7];
    const float* beta   = (const float*)d_in[8];
    const float* conf_w = (const float*)d_in[9];
    const float* conf_b = (const float*)d_in[10];

    float* out      = (float*)d_out;
    float* out_xd   = out;                                    // [4,4096,256]
    float* out_xout = out + (size_t)BB*NS*COUT;               // [4,16384,256]
    float* out_conf = out_xout + (size_t)BB*NN*COUT;          // [4,16384,1]
    float* out_aw   = out_conf + (size_t)BB*NN;               // [4,65536,1]
    float* out_idx  = out_aw   + (size_t)BB*NP;               // [4,65536]

    cudaFuncSetAttribute(k_conv, cudaFuncAttributeMaxDynamicSharedMemorySize, CV_SMEM);

    k_init<<<2048, 256>>>(skip_w, conv_w);
    k_token2map<<<BB*NP/8, 256>>>(x, loc, idxa);
    k_norm<<<(BB*HH*WW*CIN/4)/256, 256>>>();
    k_conv<<<dim3(HD, BB), 512, CV_SMEM>>>(conv_b);
    k_map2token<<<BB*NP/8, 256>>>(loc, idxa, aggw);
    k_skip<<<dim3(BB*NN/64, COUT/64), 256>>>(x);
    k_bnstats<<<BB*NN/256, 256>>>();
    k_bnfinal<<<1, 256>>>(gamma, beta);
    k_bnconf<<<BB*NN/8, 256>>>(conf_w, conf_b, out_xout, out_conf);
    k_cluster<<<BB*NP/8, 256>>>(loc, idxa, out_idx);
    k_xdown<<<BB*NS/8, 256>>>(out_xd);
    k_aggmax<<<BB*NP/256, 256>>>(loc, aggw);
    k_aggnorm<<<BB*NP/256, 256>>>(out_aw);
}

// round 9
// speedup vs baseline: 1.5174x; 1.5174x over previous
#include <cuda_runtime.h>
#include <math.h>
#include <stdint.h>

#define BB   4
#define NN   16384
#define CIN  128
#define COUT 256
#define HH   256
#define WW   256
#define NP   65536      // N0 = H*W points
#define HD   128
#define WD   128
#define HC   64
#define WC   64
#define NS   4096       // HC*WC
#define EPSV 1e-6f
#define KTOT 1152       // 9*CIN
#define SLABS 36        // KTOT/32

// ---------------- scratch (device globals: no allocation allowed) ----------------
__device__ float  g_ssum[(size_t)BB*HH*WW*CIN];   // token2map sum -> normalized tf32 map (128MB)
__device__ float  g_cnt [(size_t)BB*HH*WW];       // token2map count
__device__ float  g_y   [(size_t)BB*HD*WD*COUT];  // conv output        (64MB)
__device__ float  g_num [(size_t)BB*NN*COUT];     // map2token num -> tok (64MB)
__device__ float  g_den [(size_t)BB*NN];
__device__ float  g_tokn[(size_t)BB*NN*COUT];     // BN-normalized tokens (64MB)
__device__ float  g_wexp[(size_t)BB*NN];          // exp(conf)
__device__ double g_bnsum[COUT];
__device__ double g_bnsq [COUT];
__device__ float  g_scale[COUT];
__device__ float  g_shift[COUT];
__device__ float  g_cnum[(size_t)BB*NS*COUT];     // cluster num (16MB)
__device__ float  g_cden[(size_t)BB*NS];
__device__ float  g_wpt [(size_t)BB*NP];          // per-point weight, reused
__device__ unsigned g_maxw[BB];
__device__ float4 g_wBp [(size_t)SLABS*2048];     // conv weights, pre-swizzled smem image per slab
__device__ float4 g_wSp [(size_t)4*2048];         // skip weights, pre-swizzled smem image (4 slabs)

// ---------------- helpers ----------------
__device__ __forceinline__ void red_add4(float* p, float4 v) {
    asm volatile("red.global.add.v4.f32 [%0], {%1,%2,%3,%4};"
                 :: "l"(__cvta_generic_to_global(p)),
                    "f"(v.x), "f"(v.y), "f"(v.z), "f"(v.w) : "memory");
}

__device__ __forceinline__ int grid_cell(float lx, float ly, int Hg, int Wg) {
    lx = fminf(fmaxf(lx, -1.f), 1.f);
    ly = fminf(fmaxf(ly, -1.f), 1.f);
    int px = min(max(__float2int_rn(0.5f*(lx+1.f)*(float)Wg - 0.5f), 0), Wg-1);
    int py = min(max(__float2int_rn(0.5f*(ly+1.f)*(float)Hg - 0.5f), 0), Hg-1);
    return py*Wg + px;
}

__device__ __forceinline__ float to_tf32(float x) {
    uint32_t u; asm("cvt.rna.tf32.f32 %0, %1;" : "=r"(u) : "f"(x));
    return __uint_as_float(u);
}
__device__ __forceinline__ float4 tf4(float4 v) {
    return make_float4(to_tf32(v.x), to_tf32(v.y), to_tf32(v.z), to_tf32(v.w));
}

__device__ __forceinline__ uint32_t smem_u32(const void* p) {
    uint32_t a;
    asm("{ .reg .u64 t; cvta.to.shared.u64 t, %1; cvt.u32.u64 %0, t; }" : "=r"(a) : "l"(p));
    return a;
}

__device__ __forceinline__ void cpa16(uint32_t dst, const float* src, int srcsz) {
    asm volatile("cp.async.cg.shared.global [%0], [%1], 16, %2;"
                 :: "r"(dst), "l"(__cvta_generic_to_global(src)), "r"(srcsz) : "memory");
}

__device__ __forceinline__ void mma8(float& d0, float& d1, float& d2, float& d3,
                                     float a0, float a1, float a2, float a3,
                                     float b0, float b1) {
    asm volatile("mma.sync.aligned.m16n8k8.row.col.f32.tf32.tf32.f32 "
                 "{%0,%1,%2,%3},{%4,%5,%6,%7},{%8,%9},{%0,%1,%2,%3};"
                 : "+f"(d0), "+f"(d1), "+f"(d2), "+f"(d3)
                 : "r"(__float_as_uint(a0)), "r"(__float_as_uint(a1)),
                   "r"(__float_as_uint(a2)), "r"(__float_as_uint(a3)),
                   "r"(__float_as_uint(b0)), "r"(__float_as_uint(b1)));
}

// ---------------- kernels ----------------
// fused: zero accumulators + build pre-swizzled conv-B and skip-B images
__global__ void k_init(const float* __restrict__ skw, const float* __restrict__ cw) {
    size_t t = (size_t)blockIdx.x*blockDim.x + threadIdx.x;
    size_t stride = (size_t)gridDim.x*blockDim.x;
    float4 z = make_float4(0.f,0.f,0.f,0.f);
    for (size_t i=t; i < (size_t)BB*HH*WW*CIN/4; i+=stride) ((float4*)g_ssum)[i]=z;
    for (size_t i=t; i < (size_t)BB*HH*WW/4;     i+=stride) ((float4*)g_cnt )[i]=z;
    for (size_t i=t; i < (size_t)BB*NN*COUT/4;   i+=stride) ((float4*)g_num )[i]=z;
    for (size_t i=t; i < (size_t)BB*NN/4;        i+=stride) ((float4*)g_den )[i]=z;
    for (size_t i=t; i < (size_t)BB*NS*COUT/4;   i+=stride) ((float4*)g_cnum)[i]=z;
    for (size_t i=t; i < (size_t)BB*NS/4;        i+=stride) ((float4*)g_cden)[i]=z;
    if (t < COUT) { g_bnsum[t]=0.0; g_bnsq[t]=0.0; }
    if (t < BB)   g_maxw[t]=0u;
    if (t < (size_t)SLABS*2048) {
        int fi = (int)t;
        int s  = fi >> 11, r = fi & 2047;
        int nt = r >> 6, h2 = (r >> 5) & 1, g = (r >> 2) & 7, c = r & 3;
        int n  = nt*8 + g;
        int k0 = s*32 + h2*16 + c;
        float4 v = make_float4(cw[(size_t)k0*COUT + n],      cw[(size_t)(k0+4)*COUT + n],
                               cw[(size_t)(k0+8)*COUT + n],  cw[(size_t)(k0+12)*COUT + n]);
        g_wBp[fi] = tf4(v);
    }
    if (t < (size_t)4*2048) {
        int fi = (int)t;
        int s  = fi >> 11, r = fi & 2047;
        int nt = r >> 6, h2 = (r >> 5) & 1, g = (r >> 2) & 7, c = r & 3;
        int n  = nt*8 + g;
        int k0 = s*32 + h2*16 + c;
        const float* wr = skw + (size_t)n*CIN;     // skip_w[n][k]
        float4 v = make_float4(wr[k0], wr[k0+4], wr[k0+8], wr[k0+12]);
        g_wSp[fi] = tf4(v);
    }
}

// scatter token features to H x W map (sum + count)
__global__ void k_token2map(const float* __restrict__ x, const float* __restrict__ loc,
                            const int* __restrict__ idx_agg) {
    int p    = blockIdx.x*8 + (threadIdx.x>>5);
    int lane = threadIdx.x & 31;
    int b    = p >> 16;
    float lx = loc[2*p], ly = loc[2*p+1];
    int cell = grid_cell(lx, ly, HH, WW);
    int i    = idx_agg[p];
    const float4* src = (const float4*)(x + ((size_t)b*NN + i)*CIN);
    float* dst = g_ssum + ((size_t)b*HH*WW + cell)*CIN;
    float4 v = src[lane];
    red_add4(dst + lane*4, v);
    if (!lane) atomicAdd(&g_cnt[(size_t)b*HH*WW + cell], 1.0f);
}

// normalize map in place AND round to tf32: ssum = tf32(ssum / (cnt + eps))
__global__ void k_norm() {
    size_t i = (size_t)blockIdx.x*256 + threadIdx.x;
    float rcp = 1.f/(g_cnt[i >> 5] + EPSV);
    float4 v = ((float4*)g_ssum)[i];
    v.x*=rcp; v.y*=rcp; v.z*=rcp; v.w*=rcp;
    ((float4*)g_ssum)[i] = tf4(v);
}

// ---- 3x3 stride-2 conv as implicit GEMM on mma.sync TF32, 3-stage cp.async pipeline ----
// CTA: oy=blockIdx.x, b=blockIdx.y. 512 threads / 16 warps, warp tile 32m x 64n.
#define CV_BUF   49152
#define CV_A(i)  ((i)*CV_BUF)
#define CV_B(i)  ((i)*CV_BUF + 16384)
#define CV_BIAS  (3*CV_BUF)
#define CV_SMEM  (CV_BIAS + 1024)

__device__ __forceinline__ void cv_stage(uint32_t sb, int s, int buf,
                                         int oy, const float* __restrict__ xin, int tid) {
    int tap = s >> 2, cinb = (s & 3) * 32;
    int ky = tap / 3, kx = tap - 3*ky;
    int iy = 2*oy - 1 + ky;
    bool iyok = (unsigned)iy < HH;
    int r = tid >> 2, q0 = (tid & 3) * 2;        // 512 threads: 2 A-chunks each
    int ix = 2*r - 1 + kx;
    bool ok = iyok && ((unsigned)ix < WW);
    const float* src = xin + ((size_t)(iyok ? iy : 0)*WW + (ok ? ix : 0))*CIN + cinb;
    uint32_t dstA = sb + CV_A(buf) + r*128;
    int sz = ok ? 16 : 0;
    int sw = r & 7;
    #pragma unroll
    for (int j = 0; j < 2; j++) {
        int q = q0 + j;
        cpa16(dstA + ((q ^ sw) * 16), src + q*4, sz);
    }
    const float4* bsrc = g_wBp + (size_t)s*2048 + tid*4;   // 4 B-chunks each
    uint32_t dstB = sb + CV_B(buf) + tid*64;
    #pragma unroll
    for (int j = 0; j < 4; j++)
        cpa16(dstB + j*16, (const float*)(bsrc + j), 16);
    asm volatile("cp.async.commit_group;" ::: "memory");
}

__device__ __forceinline__ float ldsA(const float* sA, int r, int k) {
    int kk = ((((k >> 2) ^ (r & 7)) << 2) | (k & 3));
    return sA[r*32 + kk];
}

__global__ void __launch_bounds__(512, 1) k_conv(const float* __restrict__ cb) {
    extern __shared__ char smem[];
    uint32_t sb = smem_u32(smem);
    int tid = threadIdx.x, w = tid >> 5, lane = tid & 31;
    int g = lane >> 2, cl = lane & 3;
    int wm = w & 3, wn = w >> 2;                 // warp tile 32m x 64n
    int oy = blockIdx.x, b = blockIdx.y;
    const float* xin = g_ssum + (size_t)b*HH*WW*CIN;

    if (tid < 256) *(float*)(smem + CV_BIAS + tid*4) = cb[tid];

    float acc[2][8][4];
    #pragma unroll
    for (int mt=0;mt<2;mt++) for (int nt=0;nt<8;nt++) for (int r2=0;r2<4;r2++) acc[mt][nt][r2]=0.f;

    cv_stage(sb, 0, 0, oy, xin, tid);
    cv_stage(sb, 1, 1, oy, xin, tid);

    int bufc = 0;                                  // buffer of slab s
    for (int s = 0; s < SLABS; s++) {
        if (s < SLABS-1) asm volatile("cp.async.wait_group 1;" ::: "memory");
        else             asm volatile("cp.async.wait_group 0;" ::: "memory");
        __syncthreads();
        int bufn = bufc + 2; if (bufn >= 3) bufn -= 3;
        if (s + 2 < SLABS) cv_stage(sb, s + 2, bufn, oy, xin, tid);
        const float*  sA = (const float*) (smem + CV_A(bufc));
        const float4* sB = (const float4*)(smem + CV_B(bufc));
        #pragma unroll
        for (int h2 = 0; h2 < 2; h2++) {
            float4 bv[8];
            #pragma unroll
            for (int nt = 0; nt < 8; nt++)
                bv[nt] = sB[(wn*8 + nt)*64 + h2*32 + g*4 + cl];
            #pragma unroll
            for (int hh = 0; hh < 2; hh++) {
                int kc = (h2*2 + hh)*8 + cl;
                float a[2][4];
                #pragma unroll
                for (int mt = 0; mt < 2; mt++) {
                    int r0 = wm*32 + mt*16 + g;
                    a[mt][0] = ldsA(sA, r0,     kc);
                    a[mt][1] = ldsA(sA, r0 + 8, kc);
                    a[mt][2] = ldsA(sA, r0,     kc + 4);
                    a[mt][3] = ldsA(sA, r0 + 8, kc + 4);
                }
                #pragma unroll
                for (int mt = 0; mt < 2; mt++)
                    #pragma unroll
                    for (int nt = 0; nt < 8; nt++) {
                        float b0 = hh ? bv[nt].z : bv[nt].x;
                        float b1 = hh ? bv[nt].w : bv[nt].y;
                        mma8(acc[mt][nt][0], acc[mt][nt][1], acc[mt][nt][2], acc[mt][nt][3],
                             a[mt][0], a[mt][1], a[mt][2], a[mt][3], b0, b1);
                    }
            }
        }
        bufc++; if (bufc >= 3) bufc = 0;
    }

    // epilogue: D frag (m16n8): d0,d1 @ (g, 2c+{0,1}); d2,d3 @ (g+8, 2c+{0,1})
    const float* bias = (const float*)(smem + CV_BIAS);
    float* ybase = g_y + (((size_t)b*HD + oy)*WD)*COUT;
    #pragma unroll
    for (int mt = 0; mt < 2; mt++) {
        int ox0 = wm*32 + mt*16 + g;
        #pragma unroll
        for (int nt = 0; nt < 8; nt++) {
            int n = wn*64 + nt*8 + cl*2;
            float b0 = bias[n], b1 = bias[n+1];
            *(float2*)(ybase + (size_t)ox0*COUT + n)     = make_float2(acc[mt][nt][0]+b0, acc[mt][nt][1]+b1);
            *(float2*)(ybase + (size_t)(ox0+8)*COUT + n) = make_float2(acc[mt][nt][2]+b0, acc[mt][nt][3]+b1);
        }
    }
}

// bilinear gather from conv map at orig points, weighted scatter to tokens
__global__ void k_map2token(const float* __restrict__ loc, const int* __restrict__ idx_agg,
                            const float* __restrict__ aggw) {
    int p    = blockIdx.x*8 + (threadIdx.x>>5);
    int lane = threadIdx.x & 31;
    int b    = p >> 16;
    float lx = fminf(fmaxf(loc[2*p],   -1.f), 1.f);
    float ly = fminf(fmaxf(loc[2*p+1], -1.f), 1.f);
    float fx = fminf(fmaxf(0.5f*(lx+1.f)*(float)WD - 0.5f, 0.f), (float)(WD-1));
    float fy = fminf(fmaxf(0.5f*(ly+1.f)*(float)HD - 0.5f, 0.f), (float)(HD-1));
    float x0f = floorf(fx), y0f = floorf(fy);
    float wx = fx - x0f, wy = fy - y0f;
    int x0 = (int)x0f, y0 = (int)y0f;
    int x1 = min(x0+1, WD-1), y1 = min(y0+1, HD-1);
    const float* base = g_y + (size_t)b*HD*WD*COUT;
    const float4* r00 = (const float4*)(base + (size_t)(y0*WD+x0)*COUT);
    const float4* r01 = (const float4*)(base + (size_t)(y0*WD+x1)*COUT);
    const float4* r10 = (const float4*)(base + (size_t)(y1*WD+x0)*COUT);
    const float4* r11 = (const float4*)(base + (size_t)(y1*WD+x1)*COUT);
    float w00=(1.f-wx)*(1.f-wy), w01=wx*(1.f-wy), w10=(1.f-wx)*wy, w11=wx*wy;
    float wpt = aggw[p];
    int i = idx_agg[p];
    float* dst = g_num + ((size_t)b*NN + i)*COUT;
    #pragma unroll
    for (int q = 0; q < 2; q++) {
        int c4 = q*32 + lane;
        float4 a = r00[c4], bq = r01[c4], cc = r10[c4], d = r11[c4];
        float4 f;
        f.x = (w00*a.x + w01*bq.x + w10*cc.x + w11*d.x)*wpt;
        f.y = (w00*a.y + w01*bq.y + w10*cc.y + w11*d.y)*wpt;
        f.z = (w00*a.z + w01*bq.z + w10*cc.z + w11*d.z)*wpt;
        f.w = (w00*a.w + w01*bq.w + w10*cc.w + w11*d.w)*wpt;
        red_add4(dst + c4*4, f);
    }
    if (!lane) atomicAdd(&g_den[(size_t)b*NN + i], wpt);
}

// ---- skip GEMM (x @ skip_w^T) on TF32 mma.sync, fused tok = num/(den+eps) + skip ----
// CTA: 128 rows x 256 cols, K=128 = 4 slabs, 3-buffer cp.async pipeline.
#define SK_BUF   49152
#define SK_A(i)  ((i)*SK_BUF)
#define SK_B(i)  ((i)*SK_BUF + 16384)
#define SK_SMEM  (3*SK_BUF)

__device__ __forceinline__ void sk_stage(uint32_t sb, int s, int buf,
                                         const float* __restrict__ xrow0, int tid) {
    int r = tid >> 2, q0 = (tid & 3) * 2;
    const float* src = xrow0 + (size_t)r*CIN + s*32;
    uint32_t dstA = sb + SK_A(buf) + r*128;
    int sw = r & 7;
    #pragma unroll
    for (int j = 0; j < 2; j++) {
        int q = q0 + j;
        cpa16(dstA + ((q ^ sw) * 16), src + q*4, 16);
    }
    const float4* bsrc = g_wSp + (size_t)s*2048 + tid*4;
    uint32_t dstB = sb + SK_B(buf) + tid*64;
    #pragma unroll
    for (int j = 0; j < 4; j++)
        cpa16(dstB + j*16, (const float*)(bsrc + j), 16);
    asm volatile("cp.async.commit_group;" ::: "memory");
}

__global__ void __launch_bounds__(512, 1) k_skip(const float* __restrict__ x) {
    extern __shared__ char smem[];
    uint32_t sb = smem_u32(smem);
    int tid = threadIdx.x, w = tid >> 5, lane = tid & 31;
    int g = lane >> 2, cl = lane & 3;
    int wm = w & 3, wn = w >> 2;
    int m0 = blockIdx.x * 128;
    const float* xrow0 = x + (size_t)m0*CIN;

    float acc[2][8][4];
    #pragma unroll
    for (int mt=0;mt<2;mt++) for (int nt=0;nt<8;nt++) for (int r2=0;r2<4;r2++) acc[mt][nt][r2]=0.f;

    sk_stage(sb, 0, 0, xrow0, tid);
    sk_stage(sb, 1, 1, xrow0, tid);

    int bufc = 0;
    for (int s = 0; s < 4; s++) {
        if (s < 3) asm volatile("cp.async.wait_group 1;" ::: "memory");
        else       asm volatile("cp.async.wait_group 0;" ::: "memory");
        __syncthreads();
        int bufn = bufc + 2; if (bufn >= 3) bufn -= 3;
        if (s + 2 < 4) sk_stage(sb, s + 2, bufn, xrow0, tid);
        const float*  sA = (const float*) (smem + SK_A(bufc));
        const float4* sB = (const float4*)(smem + SK_B(bufc));
        #pragma unroll
        for (int h2 = 0; h2 < 2; h2++) {
            float4 bv[8];
            #pragma unroll
            for (int nt = 0; nt < 8; nt++)
                bv[nt] = sB[(wn*8 + nt)*64 + h2*32 + g*4 + cl];
            #pragma unroll
            for (int hh = 0; hh < 2; hh++) {
                int kc = (h2*2 + hh)*8 + cl;
                float a[2][4];
                #pragma unroll
                for (int mt = 0; mt < 2; mt++) {
                    int r0 = wm*32 + mt*16 + g;
                    a[mt][0] = to_tf32(ldsA(sA, r0,     kc));
                    a[mt][1] = to_tf32(ldsA(sA, r0 + 8, kc));
                    a[mt][2] = to_tf32(ldsA(sA, r0,     kc + 4));
                    a[mt][3] = to_tf32(ldsA(sA, r0 + 8, kc + 4));
                }
                #pragma unroll
                for (int mt = 0; mt < 2; mt++)
                    #pragma unroll
                    for (int nt = 0; nt < 8; nt++) {
                        float b0 = hh ? bv[nt].z : bv[nt].x;
                        float b1 = hh ? bv[nt].w : bv[nt].y;
                        mma8(acc[mt][nt][0], acc[mt][nt][1], acc[mt][nt][2], acc[mt][nt][3],
                             a[mt][0], a[mt][1], a[mt][2], a[mt][3], b0, b1);
                    }
            }
        }
        bufc++; if (bufc >= 3) bufc = 0;
    }

    // epilogue: tok = acc + num * rcp(den), overwrite g_num
    #pragma unroll
    for (int mt = 0; mt < 2; mt++) {
        int r0 = wm*32 + mt*16 + g;
        int row0 = m0 + r0, row1 = row0 + 8;
        float rcp0 = 1.f/(g_den[row0] + EPSV);
        float rcp1 = 1.f/(g_den[row1] + EPSV);
        float* nb0 = g_num + (size_t)row0*COUT;
        float* nb1 = g_num + (size_t)row1*COUT;
        #pragma unroll
        for (int nt = 0; nt < 8; nt++) {
            int n = wn*64 + nt*8 + cl*2;
            float2 v0 = *(float2*)(nb0 + n);
            float2 v1 = *(float2*)(nb1 + n);
            *(float2*)(nb0 + n) = make_float2(acc[mt][nt][0] + v0.x*rcp0, acc[mt][nt][1] + v0.y*rcp0);
            *(float2*)(nb1 + n) = make_float2(acc[mt][nt][2] + v1.x*rcp1, acc[mt][nt][3] + v1.y*rcp1);
        }
    }
}

__global__ void k_bnstats() {
    int c  = threadIdx.x;
    int r0 = blockIdx.x*256;
    double s = 0.0, s2 = 0.0;
    for (int r = 0; r < 256; r++) {
        float v = g_num[(size_t)(r0 + r)*COUT + c];
        s += v; s2 += (double)v*v;
    }
    atomicAdd(&g_bnsum[c], s);
    atomicAdd(&g_bnsq[c],  s2);
}

__global__ void k_bnfinal(const float* __restrict__ gam, const float* __restrict__ bet) {
    int c = threadIdx.x;
    double m  = (double)BB*NN;
    double mu = g_bnsum[c]/m;
    double var = g_bnsq[c]/m - mu*mu;
    float sc = gam[c] * (float)(1.0/sqrt(var + 1e-5));
    g_scale[c] = sc;
    g_shift[c] = bet[c] - (float)mu*sc;
}

__global__ void k_bnconf(const float* __restrict__ cw, const float* __restrict__ cbv,
                         float* __restrict__ out_xout, float* __restrict__ out_conf) {
    int row  = blockIdx.x*8 + (threadIdx.x>>5);
    int lane = threadIdx.x & 31;
    const float4* t  = (const float4*)(g_num  + (size_t)row*COUT);
    float4* tn       = (float4*)(g_tokn + (size_t)row*COUT);
    float4* xo       = (float4*)(out_xout + (size_t)row*COUT);
    float dot = 0.f;
    #pragma unroll
    for (int q = 0; q < 2; q++) {
        int c4 = q*32 + lane;
        float4 v  = t[c4];
        float4 sc = ((const float4*)g_scale)[c4];
        float4 sh = ((const float4*)g_shift)[c4];
        float4 w  = ((const float4*)cw)[c4];
        float4 r = make_float4(v.x*sc.x+sh.x, v.y*sc.y+sh.y, v.z*sc.z+sh.z, v.w*sc.w+sh.w);
        dot += r.x*w.x + r.y*w.y + r.z*w.z + r.w*w.w;
        tn[c4] = r;
        xo[c4] = make_float4(fmaxf(r.x,0.f), fmaxf(r.y,0.f), fmaxf(r.z,0.f), fmaxf(r.w,0.f));
    }
    #pragma unroll
    for (int o = 16; o; o >>= 1) dot += __shfl_xor_sync(0xffffffffu, dot, o);
    if (!lane) {
        float cf = dot + cbv[0];
        out_conf[row] = cf;
        g_wexp[row]   = expf(cf);
    }
}

__global__ void k_cluster(const float* __restrict__ loc, const int* __restrict__ idx_agg,
                          float* __restrict__ out_idx) {
    int p    = blockIdx.x*8 + (threadIdx.x>>5);
    int lane = threadIdx.x & 31;
    int b    = p >> 16;
    int cell = grid_cell(loc[2*p], loc[2*p+1], HC, WC);
    int i    = idx_agg[p];
    float w  = g_wexp[(size_t)b*NN + i];
    const float4* src = (const float4*)(g_tokn + ((size_t)b*NN + i)*COUT);
    float* dst = g_cnum + ((size_t)b*NS + cell)*COUT;
    #pragma unroll
    for (int q = 0; q < 2; q++) {
        int c4 = q*32 + lane;
        float4 v = src[c4];
        red_add4(dst + c4*4, make_float4(v.x*w, v.y*w, v.z*w, v.w*w));
    }
    if (!lane) {
        atomicAdd(&g_cden[(size_t)b*NS + cell], w);
        g_wpt[p]   = w;
        out_idx[p] = (float)cell;
    }
}

__global__ void k_xdown(float* __restrict__ out_xd) {
    int row  = blockIdx.x*8 + (threadIdx.x>>5);
    int lane = threadIdx.x & 31;
    float rcp = 1.f/(g_cden[row] + EPSV);
    const float4* src = (const float4*)(g_cnum + (size_t)row*COUT);
    float4* dst = (float4*)(out_xd + (size_t)row*COUT);
    #pragma unroll
    for (int q = 0; q < 2; q++) {
        int c4 = q*32 + lane;
        float4 v = src[c4];
        dst[c4] = make_float4(fmaxf(v.x*rcp,0.f), fmaxf(v.y*rcp,0.f),
                              fmaxf(v.z*rcp,0.f), fmaxf(v.w*rcp,0.f));
    }
}

__global__ void k_aggmax(const float* __restrict__ loc, const float* __restrict__ aggw) {
    __shared__ float sm[256];
    int p = blockIdx.x*256 + threadIdx.x;
    int b = p >> 16;
    int cell = grid_cell(loc[2*p], loc[2*p+1], HC, WC);
    float aw = aggw[p] * g_wpt[p] / (g_cden[(size_t)b*NS + cell] + EPSV);
    g_wpt[p] = aw;
    sm[threadIdx.x] = aw;
    __syncthreads();
    for (int s = 128; s; s >>= 1) {
        if (threadIdx.x < s) sm[threadIdx.x] = fmaxf(sm[threadIdx.x], sm[threadIdx.x+s]);
        __syncthreads();
    }
    if (!threadIdx.x) atomicMax(&g_maxw[b], __float_as_uint(sm[0]));
}

__global__ void k_aggnorm(float* __restrict__ out_aw) {
    int p = blockIdx.x*256 + threadIdx.x;
    int b = p >> 16;
    out_aw[p] = g_wpt[p] / __uint_as_float(g_maxw[b]);
}

// ---------------- launch ----------------
extern "C" void kernel_launch(void* const* d_in, const int* in_sizes, int n_in,
                              void* d_out, int out_size) {
    const float* x      = (const float*)d_in[0];
    const float* loc    = (const float*)d_in[1];
    const int*   idxa   = (const int*)  d_in[2];
    const float* aggw   = (const float*)d_in[3];
    const float* conv_w = (const float*)d_in[4];
    const float* conv_b = (const float*)d_in[5];
    const float* skip_w = (const float*)d_in[6];
    const float* gamma  = (const float*)d_in[7];
    const float* beta   = (const float*)d_in[8];
    const float* conf_w = (const float*)d_in[9];
    const float* conf_b = (const float*)d_in[10];

    float* out      = (float*)d_out;
    float* out_xd   = out;                                    // [4,4096,256]
    float* out_xout = out + (size_t)BB*NS*COUT;               // [4,16384,256]
    float* out_conf = out_xout + (size_t)BB*NN*COUT;          // [4,16384,1]
    float* out_aw   = out_conf + (size_t)BB*NN;               // [4,65536,1]
    float* out_idx  = out_aw   + (size_t)BB*NP;               // [4,65536]

    cudaFuncSetAttribute(k_conv, cudaFuncAttributeMaxDynamicSharedMemorySize, CV_SMEM);
    cudaFuncSetAttribute(k_skip, cudaFuncAttributeMaxDynamicSharedMemorySize, SK_SMEM);

    k_init<<<2048, 256>>>(skip_w, conv_w);
    k_token2map<<<BB*NP/8, 256>>>(x, loc, idxa);
    k_norm<<<(BB*HH*WW*CIN/4)/256, 256>>>();
    k_conv<<<dim3(HD, BB), 512, CV_SMEM>>>(conv_b);
    k_map2token<<<BB*NP/8, 256>>>(loc, idxa, aggw);
    k_skip<<<BB*NN/128, 512, SK_SMEM>>>(x);
    k_bnstats<<<BB*NN/256, 256>>>();
    k_bnfinal<<<1, 256>>>(gamma, beta);
    k_bnconf<<<BB*NN/8, 256>>>(conf_w, conf_b, out_xout, out_conf);
    k_cluster<<<BB*NP/8, 256>>>(loc, idxa, out_idx);
    k_xdown<<<BB*NS/8, 256>>>(out_xd);
    k_aggmax<<<BB*NP/256, 256>>>(loc, aggw);
    k_aggnorm<<<BB*NP/256, 256>>>(out_aw);
}

// round 10
// speedup vs baseline: 1.5588x; 1.0273x over previous
#include <cuda_runtime.h>
#include <math.h>
#include <stdint.h>

#define BB   4
#define NN   16384
#define CIN  128
#define COUT 256
#define HH   256
#define WW   256
#define NP   65536      // N0 = H*W points
#define HD   128
#define WD   128
#define HC   64
#define WC   64
#define NS   4096       // HC*WC
#define EPSV 1e-6f
#define KTOT 1152       // 9*CIN
#define SLABS 36        // KTOT/32
#define PHASES 18       // 2 slabs per phase

// ---------------- scratch (device globals: no allocation allowed) ----------------
__device__ float  g_ssum[(size_t)BB*HH*WW*CIN];   // token2map sum -> normalized tf32 map (128MB)
__device__ float  g_cnt [(size_t)BB*HH*WW];       // token2map count
__device__ float  g_y   [(size_t)BB*HD*WD*COUT];  // conv output        (64MB)
__device__ float  g_num [(size_t)BB*NN*COUT];     // map2token num -> tok (64MB)
__device__ float  g_den [(size_t)BB*NN];
__device__ float  g_wexp[(size_t)BB*NN];          // exp(conf)
__device__ double g_bnsum[COUT];
__device__ double g_bnsq [COUT];
__device__ float  g_scale[COUT];
__device__ float  g_shift[COUT];
__device__ float  g_cnum[(size_t)BB*NS*COUT];     // cluster num (16MB)
__device__ float  g_cden[(size_t)BB*NS];
__device__ float  g_wpt [(size_t)BB*NP];          // per-point weight, reused
__device__ unsigned g_maxw[BB];
__device__ float4 g_wBp [(size_t)SLABS*2048];     // conv weights, pre-swizzled smem image per slab
__device__ float4 g_wSp [(size_t)4*2048];         // skip weights, pre-swizzled smem image (4 slabs)

// ---------------- helpers ----------------
__device__ __forceinline__ void red_add4(float* p, float4 v) {
    asm volatile("red.global.add.v4.f32 [%0], {%1,%2,%3,%4};"
                 :: "l"(__cvta_generic_to_global(p)),
                    "f"(v.x), "f"(v.y), "f"(v.z), "f"(v.w) : "memory");
}

__device__ __forceinline__ int grid_cell(float lx, float ly, int Hg, int Wg) {
    lx = fminf(fmaxf(lx, -1.f), 1.f);
    ly = fminf(fmaxf(ly, -1.f), 1.f);
    int px = min(max(__float2int_rn(0.5f*(lx+1.f)*(float)Wg - 0.5f), 0), Wg-1);
    int py = min(max(__float2int_rn(0.5f*(ly+1.f)*(float)Hg - 0.5f), 0), Hg-1);
    return py*Wg + px;
}

__device__ __forceinline__ float to_tf32(float x) {
    uint32_t u; asm("cvt.rna.tf32.f32 %0, %1;" : "=r"(u) : "f"(x));
    return __uint_as_float(u);
}
__device__ __forceinline__ float4 tf4(float4 v) {
    return make_float4(to_tf32(v.x), to_tf32(v.y), to_tf32(v.z), to_tf32(v.w));
}

__device__ __forceinline__ uint32_t smem_u32(const void* p) {
    uint32_t a;
    asm("{ .reg .u64 t; cvta.to.shared.u64 t, %1; cvt.u32.u64 %0, t; }" : "=r"(a) : "l"(p));
    return a;
}

__device__ __forceinline__ void cpa16(uint32_t dst, const float* src, int srcsz) {
    asm volatile("cp.async.cg.shared.global [%0], [%1], 16, %2;"
                 :: "r"(dst), "l"(__cvta_generic_to_global(src)), "r"(srcsz) : "memory");
}

__device__ __forceinline__ void mma8(float& d0, float& d1, float& d2, float& d3,
                                     float a0, float a1, float a2, float a3,
                                     float b0, float b1) {
    asm volatile("mma.sync.aligned.m16n8k8.row.col.f32.tf32.tf32.f32 "
                 "{%0,%1,%2,%3},{%4,%5,%6,%7},{%8,%9},{%0,%1,%2,%3};"
                 : "+f"(d0), "+f"(d1), "+f"(d2), "+f"(d3)
                 : "r"(__float_as_uint(a0)), "r"(__float_as_uint(a1)),
                   "r"(__float_as_uint(a2)), "r"(__float_as_uint(a3)),
                   "r"(__float_as_uint(b0)), "r"(__float_as_uint(b1)));
}

// ---------------- kernels ----------------
// fused: zero accumulators + build pre-swizzled conv-B and skip-B images
__global__ void k_init(const float* __restrict__ skw, const float* __restrict__ cw) {
    size_t t = (size_t)blockIdx.x*blockDim.x + threadIdx.x;
    size_t stride = (size_t)gridDim.x*blockDim.x;
    float4 z = make_float4(0.f,0.f,0.f,0.f);
    for (size_t i=t; i < (size_t)BB*HH*WW*CIN/4; i+=stride) ((float4*)g_ssum)[i]=z;
    for (size_t i=t; i < (size_t)BB*HH*WW/4;     i+=stride) ((float4*)g_cnt )[i]=z;
    for (size_t i=t; i < (size_t)BB*NN*COUT/4;   i+=stride) ((float4*)g_num )[i]=z;
    for (size_t i=t; i < (size_t)BB*NN/4;        i+=stride) ((float4*)g_den )[i]=z;
    for (size_t i=t; i < (size_t)BB*NS*COUT/4;   i+=stride) ((float4*)g_cnum)[i]=z;
    for (size_t i=t; i < (size_t)BB*NS/4;        i+=stride) ((float4*)g_cden)[i]=z;
    if (t < COUT) { g_bnsum[t]=0.0; g_bnsq[t]=0.0; }
    if (t < BB)   g_maxw[t]=0u;
    if (t < (size_t)SLABS*2048) {
        int fi = (int)t;
        int s  = fi >> 11, r = fi & 2047;
        int nt = r >> 6, h2 = (r >> 5) & 1, g = (r >> 2) & 7, c = r & 3;
        int n  = nt*8 + g;
        int k0 = s*32 + h2*16 + c;
        float4 v = make_float4(cw[(size_t)k0*COUT + n],      cw[(size_t)(k0+4)*COUT + n],
                               cw[(size_t)(k0+8)*COUT + n],  cw[(size_t)(k0+12)*COUT + n]);
        g_wBp[fi] = tf4(v);
    }
    if (t < (size_t)4*2048) {
        int fi = (int)t;
        int s  = fi >> 11, r = fi & 2047;
        int nt = r >> 6, h2 = (r >> 5) & 1, g = (r >> 2) & 7, c = r & 3;
        int n  = nt*8 + g;
        int k0 = s*32 + h2*16 + c;
        const float* wr = skw + (size_t)n*CIN;     // skip_w[n][k]
        float4 v = make_float4(wr[k0], wr[k0+4], wr[k0+8], wr[k0+12]);
        g_wSp[fi] = tf4(v);
    }
}

// scatter token features to H x W map (sum + count)
__global__ void k_token2map(const float* __restrict__ x, const float* __restrict__ loc,
                            const int* __restrict__ idx_agg) {
    int p    = blockIdx.x*8 + (threadIdx.x>>5);
    int lane = threadIdx.x & 31;
    int b    = p >> 16;
    float lx = loc[2*p], ly = loc[2*p+1];
    int cell = grid_cell(lx, ly, HH, WW);
    int i    = idx_agg[p];
    const float4* src = (const float4*)(x + ((size_t)b*NN + i)*CIN);
    float* dst = g_ssum + ((size_t)b*HH*WW + cell)*CIN;
    float4 v = src[lane];
    red_add4(dst + lane*4, v);
    if (!lane) atomicAdd(&g_cnt[(size_t)b*HH*WW + cell], 1.0f);
}

// normalize map in place AND round to tf32: ssum = tf32(ssum / (cnt + eps))
__global__ void k_norm() {
    size_t i = (size_t)blockIdx.x*256 + threadIdx.x;
    float rcp = 1.f/(g_cnt[i >> 5] + EPSV);
    float4 v = ((float4*)g_ssum)[i];
    v.x*=rcp; v.y*=rcp; v.z*=rcp; v.w*=rcp;
    ((float4*)g_ssum)[i] = tf4(v);
}

// ---- 3x3 stride-2 conv as implicit GEMM on mma.sync TF32 ----
// K64 phases: 2 slabs per barrier, 2 x 96KB buffers, stage p+1 before compute p.
#define CV_BUF   98304
#define CV_A(i)  ((i)*CV_BUF)
#define CV_B(i)  ((i)*CV_BUF + 32768)
#define CV_BIAS  (2*CV_BUF)
#define CV_SMEM  (CV_BIAS + 1024)

__device__ __forceinline__ void cv_stage2(uint32_t sb, int phase, int buf,
                                          int oy, const float* __restrict__ xin, int tid) {
    int r = tid >> 2, q0 = (tid & 3) * 2;
    int sw = r & 7;
    #pragma unroll
    for (int ks = 0; ks < 2; ks++) {
        int s = phase*2 + ks;
        int tap = s >> 2, cinb = (s & 3) * 32;
        int ky = tap / 3, kx = tap - 3*ky;
        int iy = 2*oy - 1 + ky;
        bool iyok = (unsigned)iy < HH;
        int ix = 2*r - 1 + kx;
        bool ok = iyok && ((unsigned)ix < WW);
        const float* src = xin + ((size_t)(iyok ? iy : 0)*WW + (ok ? ix : 0))*CIN + cinb;
        uint32_t dstA = sb + CV_A(buf) + ks*16384 + r*128;
        int sz = ok ? 16 : 0;
        #pragma unroll
        for (int j = 0; j < 2; j++) {
            int q = q0 + j;
            cpa16(dstA + ((q ^ sw) * 16), src + q*4, sz);
        }
        const float4* bsrc = g_wBp + (size_t)s*2048 + tid*4;
        uint32_t dstB = sb + CV_B(buf) + ks*32768 + tid*64;
        #pragma unroll
        for (int j = 0; j < 4; j++)
            cpa16(dstB + j*16, (const float*)(bsrc + j), 16);
    }
    asm volatile("cp.async.commit_group;" ::: "memory");
}

__device__ __forceinline__ float ldsA(const float* sA, int r, int k) {
    int kk = ((((k >> 2) ^ (r & 7)) << 2) | (k & 3));
    return sA[r*32 + kk];
}

__global__ void __launch_bounds__(512, 1) k_conv(const float* __restrict__ cb) {
    extern __shared__ char smem[];
    uint32_t sb = smem_u32(smem);
    int tid = threadIdx.x, w = tid >> 5, lane = tid & 31;
    int g = lane >> 2, cl = lane & 3;
    int wm = w & 3, wn = w >> 2;                 // warp tile 32m x 64n
    int oy = blockIdx.x, b = blockIdx.y;
    const float* xin = g_ssum + (size_t)b*HH*WW*CIN;

    if (tid < 256) *(float*)(smem + CV_BIAS + tid*4) = cb[tid];

    float acc[2][8][4];
    #pragma unroll
    for (int mt=0;mt<2;mt++) for (int nt=0;nt<8;nt++) for (int r2=0;r2<4;r2++) acc[mt][nt][r2]=0.f;

    cv_stage2(sb, 0, 0, oy, xin, tid);

    for (int p = 0; p < PHASES; p++) {
        asm volatile("cp.async.wait_group 0;" ::: "memory");
        __syncthreads();
        int buf = p & 1;
        if (p + 1 < PHASES) cv_stage2(sb, p + 1, buf ^ 1, oy, xin, tid);
        #pragma unroll
        for (int ks = 0; ks < 2; ks++) {
            const float*  sA = (const float*) (smem + CV_A(buf) + ks*16384);
            const float4* sB = (const float4*)(smem + CV_B(buf) + ks*32768);
            #pragma unroll
            for (int h2 = 0; h2 < 2; h2++) {
                float4 bv[8];
                #pragma unroll
                for (int nt = 0; nt < 8; nt++)
                    bv[nt] = sB[(wn*8 + nt)*64 + h2*32 + g*4 + cl];
                #pragma unroll
                for (int hh = 0; hh < 2; hh++) {
                    int kc = (h2*2 + hh)*8 + cl;
                    float a[2][4];
                    #pragma unroll
                    for (int mt = 0; mt < 2; mt++) {
                        int r0 = wm*32 + mt*16 + g;
                        a[mt][0] = ldsA(sA, r0,     kc);
                        a[mt][1] = ldsA(sA, r0 + 8, kc);
                        a[mt][2] = ldsA(sA, r0,     kc + 4);
                        a[mt][3] = ldsA(sA, r0 + 8, kc + 4);
                    }
                    #pragma unroll
                    for (int mt = 0; mt < 2; mt++)
                        #pragma unroll
                        for (int nt = 0; nt < 8; nt++) {
                            float b0 = hh ? bv[nt].z : bv[nt].x;
                            float b1 = hh ? bv[nt].w : bv[nt].y;
                            mma8(acc[mt][nt][0], acc[mt][nt][1], acc[mt][nt][2], acc[mt][nt][3],
                                 a[mt][0], a[mt][1], a[mt][2], a[mt][3], b0, b1);
                        }
                }
            }
        }
    }

    // epilogue: D frag (m16n8): d0,d1 @ (g, 2c+{0,1}); d2,d3 @ (g+8, 2c+{0,1})
    const float* bias = (const float*)(smem + CV_BIAS);
    float* ybase = g_y + (((size_t)b*HD + oy)*WD)*COUT;
    #pragma unroll
    for (int mt = 0; mt < 2; mt++) {
        int ox0 = wm*32 + mt*16 + g;
        #pragma unroll
        for (int nt = 0; nt < 8; nt++) {
            int n = wn*64 + nt*8 + cl*2;
            float b0 = bias[n], b1 = bias[n+1];
            *(float2*)(ybase + (size_t)ox0*COUT + n)     = make_float2(acc[mt][nt][0]+b0, acc[mt][nt][1]+b1);
            *(float2*)(ybase + (size_t)(ox0+8)*COUT + n) = make_float2(acc[mt][nt][2]+b0, acc[mt][nt][3]+b1);
        }
    }
}

// bilinear gather from conv map at orig points, weighted scatter to tokens
__global__ void k_map2token(const float* __restrict__ loc, const int* __restrict__ idx_agg,
                            const float* __restrict__ aggw) {
    int p    = blockIdx.x*8 + (threadIdx.x>>5);
    int lane = threadIdx.x & 31;
    int b    = p >> 16;
    float lx = fminf(fmaxf(loc[2*p],   -1.f), 1.f);
    float ly = fminf(fmaxf(loc[2*p+1], -1.f), 1.f);
    float fx = fminf(fmaxf(0.5f*(lx+1.f)*(float)WD - 0.5f, 0.f), (float)(WD-1));
    float fy = fminf(fmaxf(0.5f*(ly+1.f)*(float)HD - 0.5f, 0.f), (float)(HD-1));
    float x0f = floorf(fx), y0f = floorf(fy);
    float wx = fx - x0f, wy = fy - y0f;
    int x0 = (int)x0f, y0 = (int)y0f;
    int x1 = min(x0+1, WD-1), y1 = min(y0+1, HD-1);
    const float* base = g_y + (size_t)b*HD*WD*COUT;
    const float4* r00 = (const float4*)(base + (size_t)(y0*WD+x0)*COUT);
    const float4* r01 = (const float4*)(base + (size_t)(y0*WD+x1)*COUT);
    const float4* r10 = (const float4*)(base + (size_t)(y1*WD+x0)*COUT);
    const float4* r11 = (const float4*)(base + (size_t)(y1*WD+x1)*COUT);
    float w00=(1.f-wx)*(1.f-wy), w01=wx*(1.f-wy), w10=(1.f-wx)*wy, w11=wx*wy;
    float wpt = aggw[p];
    int i = idx_agg[p];
    float* dst = g_num + ((size_t)b*NN + i)*COUT;
    #pragma unroll
    for (int q = 0; q < 2; q++) {
        int c4 = q*32 + lane;
        float4 a = r00[c4], bq = r01[c4], cc = r10[c4], d = r11[c4];
        float4 f;
        f.x = (w00*a.x + w01*bq.x + w10*cc.x + w11*d.x)*wpt;
        f.y = (w00*a.y + w01*bq.y + w10*cc.y + w11*d.y)*wpt;
        f.z = (w00*a.z + w01*bq.z + w10*cc.z + w11*d.z)*wpt;
        f.w = (w00*a.w + w01*bq.w + w10*cc.w + w11*d.w)*wpt;
        red_add4(dst + c4*4, f);
    }
    if (!lane) atomicAdd(&g_den[(size_t)b*NN + i], wpt);
}

// ---- skip GEMM (x @ skip_w^T) on TF32 mma.sync, fused tok = num/(den+eps) + skip ----
#define SK_BUF   49152
#define SK_A(i)  ((i)*SK_BUF)
#define SK_B(i)  ((i)*SK_BUF + 16384)
#define SK_SMEM  (3*SK_BUF)

__device__ __forceinline__ void sk_stage(uint32_t sb, int s, int buf,
                                         const float* __restrict__ xrow0, int tid) {
    int r = tid >> 2, q0 = (tid & 3) * 2;
    const float* src = xrow0 + (size_t)r*CIN + s*32;
    uint32_t dstA = sb + SK_A(buf) + r*128;
    int sw = r & 7;
    #pragma unroll
    for (int j = 0; j < 2; j++) {
        int q = q0 + j;
        cpa16(dstA + ((q ^ sw) * 16), src + q*4, 16);
    }
    const float4* bsrc = g_wSp + (size_t)s*2048 + tid*4;
    uint32_t dstB = sb + SK_B(buf) + tid*64;
    #pragma unroll
    for (int j = 0; j < 4; j++)
        cpa16(dstB + j*16, (const float*)(bsrc + j), 16);
    asm volatile("cp.async.commit_group;" ::: "memory");
}

__global__ void __launch_bounds__(512, 1) k_skip(const float* __restrict__ x) {
    extern __shared__ char smem[];
    uint32_t sb = smem_u32(smem);
    int tid = threadIdx.x, w = tid >> 5, lane = tid & 31;
    int g = lane >> 2, cl = lane & 3;
    int wm = w & 3, wn = w >> 2;
    int m0 = blockIdx.x * 128;
    const float* xrow0 = x + (size_t)m0*CIN;

    float acc[2][8][4];
    #pragma unroll
    for (int mt=0;mt<2;mt++) for (int nt=0;nt<8;nt++) for (int r2=0;r2<4;r2++) acc[mt][nt][r2]=0.f;

    sk_stage(sb, 0, 0, xrow0, tid);
    sk_stage(sb, 1, 1, xrow0, tid);

    int bufc = 0;
    for (int s = 0; s < 4; s++) {
        if (s < 3) asm volatile("cp.async.wait_group 1;" ::: "memory");
        else       asm volatile("cp.async.wait_group 0;" ::: "memory");
        __syncthreads();
        int bufn = bufc + 2; if (bufn >= 3) bufn -= 3;
        if (s + 2 < 4) sk_stage(sb, s + 2, bufn, xrow0, tid);
        const float*  sA = (const float*) (smem + SK_A(bufc));
        const float4* sB = (const float4*)(smem + SK_B(bufc));
        #pragma unroll
        for (int h2 = 0; h2 < 2; h2++) {
            float4 bv[8];
            #pragma unroll
            for (int nt = 0; nt < 8; nt++)
                bv[nt] = sB[(wn*8 + nt)*64 + h2*32 + g*4 + cl];
            #pragma unroll
            for (int hh = 0; hh < 2; hh++) {
                int kc = (h2*2 + hh)*8 + cl;
                float a[2][4];
                #pragma unroll
                for (int mt = 0; mt < 2; mt++) {
                    int r0 = wm*32 + mt*16 + g;
                    a[mt][0] = to_tf32(ldsA(sA, r0,     kc));
                    a[mt][1] = to_tf32(ldsA(sA, r0 + 8, kc));
                    a[mt][2] = to_tf32(ldsA(sA, r0,     kc + 4));
                    a[mt][3] = to_tf32(ldsA(sA, r0 + 8, kc + 4));
                }
                #pragma unroll
                for (int mt = 0; mt < 2; mt++)
                    #pragma unroll
                    for (int nt = 0; nt < 8; nt++) {
                        float b0 = hh ? bv[nt].z : bv[nt].x;
                        float b1 = hh ? bv[nt].w : bv[nt].y;
                        mma8(acc[mt][nt][0], acc[mt][nt][1], acc[mt][nt][2], acc[mt][nt][3],
                             a[mt][0], a[mt][1], a[mt][2], a[mt][3], b0, b1);
                    }
            }
        }
        bufc++; if (bufc >= 3) bufc = 0;
    }

    // epilogue: tok = acc + num * rcp(den), overwrite g_num
    #pragma unroll
    for (int mt = 0; mt < 2; mt++) {
        int r0 = wm*32 + mt*16 + g;
        int row0 = m0 + r0, row1 = row0 + 8;
        float rcp0 = 1.f/(g_den[row0] + EPSV);
        float rcp1 = 1.f/(g_den[row1] + EPSV);
        float* nb0 = g_num + (size_t)row0*COUT;
        float* nb1 = g_num + (size_t)row1*COUT;
        #pragma unroll
        for (int nt = 0; nt < 8; nt++) {
            int n = wn*64 + nt*8 + cl*2;
            float2 v0 = *(float2*)(nb0 + n);
            float2 v1 = *(float2*)(nb1 + n);
            *(float2*)(nb0 + n) = make_float2(acc[mt][nt][0] + v0.x*rcp0, acc[mt][nt][1] + v0.y*rcp0);
            *(float2*)(nb1 + n) = make_float2(acc[mt][nt][2] + v1.x*rcp1, acc[mt][nt][3] + v1.y*rcp1);
        }
    }
}

__global__ void k_bnstats() {
    int c  = threadIdx.x;
    int r0 = blockIdx.x*256;
    double s = 0.0, s2 = 0.0;
    for (int r = 0; r < 256; r++) {
        float v = g_num[(size_t)(r0 + r)*COUT + c];
        s += v; s2 += (double)v*v;
    }
    atomicAdd(&g_bnsum[c], s);
    atomicAdd(&g_bnsq[c],  s2);
}

__global__ void k_bnfinal(const float* __restrict__ gam, const float* __restrict__ bet) {
    int c = threadIdx.x;
    double m  = (double)BB*NN;
    double mu = g_bnsum[c]/m;
    double var = g_bnsq[c]/m - mu*mu;
    float sc = gam[c] * (float)(1.0/sqrt(var + 1e-5));
    g_scale[c] = sc;
    g_shift[c] = bet[c] - (float)mu*sc;
}

// apply BN on the fly: write x_out = relu(bn(tok)), conf, exp(conf). tokn NOT materialized.
__global__ void k_bnconf(const float* __restrict__ cw, const float* __restrict__ cbv,
                         float* __restrict__ out_xout, float* __restrict__ out_conf) {
    int row  = blockIdx.x*8 + (threadIdx.x>>5);
    int lane = threadIdx.x & 31;
    const float4* t  = (const float4*)(g_num  + (size_t)row*COUT);
    float4* xo       = (float4*)(out_xout + (size_t)row*COUT);
    float dot = 0.f;
    #pragma unroll
    for (int q = 0; q < 2; q++) {
        int c4 = q*32 + lane;
        float4 v  = t[c4];
        float4 sc = ((const float4*)g_scale)[c4];
        float4 sh = ((const float4*)g_shift)[c4];
        float4 w  = ((const float4*)cw)[c4];
        float4 r = make_float4(v.x*sc.x+sh.x, v.y*sc.y+sh.y, v.z*sc.z+sh.z, v.w*sc.w+sh.w);
        dot += r.x*w.x + r.y*w.y + r.z*w.z + r.w*w.w;
        xo[c4] = make_float4(fmaxf(r.x,0.f), fmaxf(r.y,0.f), fmaxf(r.z,0.f), fmaxf(r.w,0.f));
    }
    #pragma unroll
    for (int o = 16; o; o >>= 1) dot += __shfl_xor_sync(0xffffffffu, dot, o);
    if (!lane) {
        float cf = dot + cbv[0];
        out_conf[row] = cf;
        g_wexp[row]   = expf(cf);
    }
}

// gather tok from g_num, apply BN inline, weighted scatter into 64x64 cells
__global__ void k_cluster(const float* __restrict__ loc, const int* __restrict__ idx_agg,
                          float* __restrict__ out_idx) {
    int p    = blockIdx.x*8 + (threadIdx.x>>5);
    int lane = threadIdx.x & 31;
    int b    = p >> 16;
    int cell = grid_cell(loc[2*p], loc[2*p+1], HC, WC);
    int i    = idx_agg[p];
    float w  = g_wexp[(size_t)b*NN + i];
    const float4* src = (const float4*)(g_num + ((size_t)b*NN + i)*COUT);
    float* dst = g_cnum + ((size_t)b*NS + cell)*COUT;
    #pragma unroll
    for (int q = 0; q < 2; q++) {
        int c4 = q*32 + lane;
        float4 v  = src[c4];
        float4 sc = ((const float4*)g_scale)[c4];
        float4 sh = ((const float4*)g_shift)[c4];
        red_add4(dst + c4*4, make_float4((v.x*sc.x+sh.x)*w, (v.y*sc.y+sh.y)*w,
                                         (v.z*sc.z+sh.z)*w, (v.w*sc.w+sh.w)*w));
    }
    if (!lane) {
        atomicAdd(&g_cden[(size_t)b*NS + cell], w);
        g_wpt[p]   = w;
        out_idx[p] = (float)cell;
    }
}

__global__ void k_xdown(float* __restrict__ out_xd) {
    int row  = blockIdx.x*8 + (threadIdx.x>>5);
    int lane = threadIdx.x & 31;
    float rcp = 1.f/(g_cden[row] + EPSV);
    const float4* src = (const float4*)(g_cnum + (size_t)row*COUT);
    float4* dst = (float4*)(out_xd + (size_t)row*COUT);
    #pragma unroll
    for (int q = 0; q < 2; q++) {
        int c4 = q*32 + lane;
        float4 v = src[c4];
        dst[c4] = make_float4(fmaxf(v.x*rcp,0.f), fmaxf(v.y*rcp,0.f),
                              fmaxf(v.z*rcp,0.f), fmaxf(v.w*rcp,0.f));
    }
}

__global__ void k_aggmax(const float* __restrict__ loc, const float* __restrict__ aggw) {
    __shared__ float sm[256];
    int p = blockIdx.x*256 + threadIdx.x;
    int b = p >> 16;
    int cell = grid_cell(loc[2*p], loc[2*p+1], HC, WC);
    float aw = aggw[p] * g_wpt[p] / (g_cden[(size_t)b*NS + cell] + EPSV);
    g_wpt[p] = aw;
    sm[threadIdx.x] = aw;
    __syncthreads();
    for (int s = 128; s; s >>= 1) {
        if (threadIdx.x < s) sm[threadIdx.x] = fmaxf(sm[threadIdx.x], sm[threadIdx.x+s]);
        __syncthreads();
    }
    if (!threadIdx.x) atomicMax(&g_maxw[b], __float_as_uint(sm[0]));
}

__global__ void k_aggnorm(float* __restrict__ out_aw) {
    int p = blockIdx.x*256 + threadIdx.x;
    int b = p >> 16;
    out_aw[p] = g_wpt[p] / __uint_as_float(g_maxw[b]);
}

// ---------------- launch ----------------
extern "C" void kernel_launch(void* const* d_in, const int* in_sizes, int n_in,
                              void* d_out, int out_size) {
    const float* x      = (const float*)d_in[0];
    const float* loc    = (const float*)d_in[1];
    const int*   idxa   = (const int*)  d_in[2];
    const float* aggw   = (const float*)d_in[3];
    const float* conv_w = (const float*)d_in[4];
    const float* conv_b = (const float*)d_in[5];
    const float* skip_w = (const float*)d_in[6];
    const float* gamma  = (const float*)d_in[7];
    const float* beta   = (const float*)d_in[8];
    const float* conf_w = (const float*)d_in[9];
    const float* conf_b = (const float*)d_in[10];

    float* out      = (float*)d_out;
    float* out_xd   = out;                                    // [4,4096,256]
    float* out_xout = out + (size_t)BB*NS*COUT;               // [4,16384,256]
    float* out_conf = out_xout + (size_t)BB*NN*COUT;          // [4,16384,1]
    float* out_aw   = out_conf + (size_t)BB*NN;               // [4,65536,1]
    float* out_idx  = out_aw   + (size_t)BB*NP;               // [4,65536]

    cudaFuncSetAttribute(k_conv, cudaFuncAttributeMaxDynamicSharedMemorySize, CV_SMEM);
    cudaFuncSetAttribute(k_skip, cudaFuncAttributeMaxDynamicSharedMemorySize, SK_SMEM);

    k_init<<<2048, 256>>>(skip_w, conv_w);
    k_token2map<<<BB*NP/8, 256>>>(x, loc, idxa);
    k_norm<<<(BB*HH*WW*CIN/4)/256, 256>>>();
    k_conv<<<dim3(HD, BB), 512, CV_SMEM>>>(conv_b);
    k_map2token<<<BB*NP/8, 256>>>(loc, idxa, aggw);
    k_skip<<<BB*NN/128, 512, SK_SMEM>>>(x);
    k_bnstats<<<BB*NN/256, 256>>>();
    k_bnfinal<<<1, 256>>>(gamma, beta);
    k_bnconf<<<BB*NN/8, 256>>>(conf_w, conf_b, out_xout, out_conf);
    k_cluster<<<BB*NP/8, 256>>>(loc, idxa, out_idx);
    k_xdown<<<BB*NS/8, 256>>>(out_xd);
    k_aggmax<<<BB*NP/256, 256>>>(loc, aggw);
    k_aggnorm<<<BB*NP/256, 256>>>(out_aw);
}

// round 11
// speedup vs baseline: 1.6148x; 1.0359x over previous
#include <cuda_runtime.h>
#include <math.h>
#include <stdint.h>

#define BB   4
#define NN   16384
#define CIN  128
#define COUT 256
#define HH   256
#define WW   256
#define NP   65536      // N0 = H*W points
#define HD   128
#define WD   128
#define HC   64
#define WC   64
#define NS   4096       // HC*WC
#define EPSV 1e-6f
#define KTOT 1152       // 9*CIN
#define SLABS 36        // KTOT/32

// ---------------- scratch (device globals: no allocation allowed) ----------------
__device__ float  g_ssum[(size_t)BB*HH*WW*CIN];   // token2map sum -> normalized tf32 map (128MB)
__device__ float  g_cnt [(size_t)BB*HH*WW];       // token2map count
__device__ float  g_y   [(size_t)BB*HD*WD*COUT];  // conv output        (64MB)
__device__ float  g_num [(size_t)BB*NN*COUT];     // map2token num -> tok (64MB)
__device__ float  g_den [(size_t)BB*NN];
__device__ float  g_wexp[(size_t)BB*NN];          // exp(conf)
__device__ double g_bnsum[COUT];
__device__ double g_bnsq [COUT];
__device__ float  g_scale[COUT];
__device__ float  g_shift[COUT];
__device__ float  g_cnum[(size_t)BB*NS*COUT];     // cluster num (16MB)
__device__ float  g_cden[(size_t)BB*NS];
__device__ float  g_wpt [(size_t)BB*NP];          // per-point weight, reused
__device__ unsigned g_maxw[BB];
__device__ float4 g_wBp [(size_t)SLABS*2048];     // conv weights, pre-swizzled smem image per slab
__device__ float4 g_wSp [(size_t)4*2048];         // skip weights, pre-swizzled smem image (4 slabs)

// ---------------- helpers ----------------
__device__ __forceinline__ void red_add4(float* p, float4 v) {
    asm volatile("red.global.add.v4.f32 [%0], {%1,%2,%3,%4};"
                 :: "l"(__cvta_generic_to_global(p)),
                    "f"(v.x), "f"(v.y), "f"(v.z), "f"(v.w) : "memory");
}

__device__ __forceinline__ int grid_cell(float lx, float ly, int Hg, int Wg) {
    lx = fminf(fmaxf(lx, -1.f), 1.f);
    ly = fminf(fmaxf(ly, -1.f), 1.f);
    int px = min(max(__float2int_rn(0.5f*(lx+1.f)*(float)Wg - 0.5f), 0), Wg-1);
    int py = min(max(__float2int_rn(0.5f*(ly+1.f)*(float)Hg - 0.5f), 0), Hg-1);
    return py*Wg + px;
}

__device__ __forceinline__ float to_tf32(float x) {
    uint32_t u; asm("cvt.rna.tf32.f32 %0, %1;" : "=r"(u) : "f"(x));
    return __uint_as_float(u);
}
__device__ __forceinline__ float4 tf4(float4 v) {
    return make_float4(to_tf32(v.x), to_tf32(v.y), to_tf32(v.z), to_tf32(v.w));
}

__device__ __forceinline__ uint32_t smem_u32(const void* p) {
    uint32_t a;
    asm("{ .reg .u64 t; cvta.to.shared.u64 t, %1; cvt.u32.u64 %0, t; }" : "=r"(a) : "l"(p));
    return a;
}

__device__ __forceinline__ void cpa16(uint32_t dst, const float* src, int srcsz) {
    asm volatile("cp.async.cg.shared.global [%0], [%1], 16, %2;"
                 :: "r"(dst), "l"(__cvta_generic_to_global(src)), "r"(srcsz) : "memory");
}

__device__ __forceinline__ void mma8(float& d0, float& d1, float& d2, float& d3,
                                     float a0, float a1, float a2, float a3,
                                     float b0, float b1) {
    asm volatile("mma.sync.aligned.m16n8k8.row.col.f32.tf32.tf32.f32 "
                 "{%0,%1,%2,%3},{%4,%5,%6,%7},{%8,%9},{%0,%1,%2,%3};"
                 : "+f"(d0), "+f"(d1), "+f"(d2), "+f"(d3)
                 : "r"(__float_as_uint(a0)), "r"(__float_as_uint(a1)),
                   "r"(__float_as_uint(a2)), "r"(__float_as_uint(a3)),
                   "r"(__float_as_uint(b0)), "r"(__float_as_uint(b1)));
}

// ---------------- kernels ----------------
// fused: zero accumulators + build pre-swizzled conv-B and skip-B images
__global__ void k_init(const float* __restrict__ skw, const float* __restrict__ cw) {
    size_t t = (size_t)blockIdx.x*blockDim.x + threadIdx.x;
    size_t stride = (size_t)gridDim.x*blockDim.x;
    float4 z = make_float4(0.f,0.f,0.f,0.f);
    for (size_t i=t; i < (size_t)BB*HH*WW*CIN/4; i+=stride) ((float4*)g_ssum)[i]=z;
    for (size_t i=t; i < (size_t)BB*HH*WW/4;     i+=stride) ((float4*)g_cnt )[i]=z;
    for (size_t i=t; i < (size_t)BB*NN*COUT/4;   i+=stride) ((float4*)g_num )[i]=z;
    for (size_t i=t; i < (size_t)BB*NN/4;        i+=stride) ((float4*)g_den )[i]=z;
    for (size_t i=t; i < (size_t)BB*NS*COUT/4;   i+=stride) ((float4*)g_cnum)[i]=z;
    for (size_t i=t; i < (size_t)BB*NS/4;        i+=stride) ((float4*)g_cden)[i]=z;
    if (t < COUT) { g_bnsum[t]=0.0; g_bnsq[t]=0.0; }
    if (t < BB)   g_maxw[t]=0u;
    if (t < (size_t)SLABS*2048) {
        int fi = (int)t;
        int s  = fi >> 11, r = fi & 2047;
        int nt = r >> 6, h2 = (r >> 5) & 1, g = (r >> 2) & 7, c = r & 3;
        int n  = nt*8 + g;
        int k0 = s*32 + h2*16 + c;
        float4 v = make_float4(cw[(size_t)k0*COUT + n],      cw[(size_t)(k0+4)*COUT + n],
                               cw[(size_t)(k0+8)*COUT + n],  cw[(size_t)(k0+12)*COUT + n]);
        g_wBp[fi] = tf4(v);
    }
    if (t < (size_t)4*2048) {
        int fi = (int)t;
        int s  = fi >> 11, r = fi & 2047;
        int nt = r >> 6, h2 = (r >> 5) & 1, g = (r >> 2) & 7, c = r & 3;
        int n  = nt*8 + g;
        int k0 = s*32 + h2*16 + c;
        const float* wr = skw + (size_t)n*CIN;     // skip_w[n][k]
        float4 v = make_float4(wr[k0], wr[k0+4], wr[k0+8], wr[k0+12]);
        g_wSp[fi] = tf4(v);
    }
}

// scatter token features to H x W map (sum + count)
__global__ void k_token2map(const float* __restrict__ x, const float* __restrict__ loc,
                            const int* __restrict__ idx_agg) {
    int p    = blockIdx.x*8 + (threadIdx.x>>5);
    int lane = threadIdx.x & 31;
    int b    = p >> 16;
    float lx = loc[2*p], ly = loc[2*p+1];
    int cell = grid_cell(lx, ly, HH, WW);
    int i    = idx_agg[p];
    const float4* src = (const float4*)(x + ((size_t)b*NN + i)*CIN);
    float* dst = g_ssum + ((size_t)b*HH*WW + cell)*CIN;
    float4 v = src[lane];
    red_add4(dst + lane*4, v);
    if (!lane) atomicAdd(&g_cnt[(size_t)b*HH*WW + cell], 1.0f);
}

// normalize map in place AND round to tf32: ssum = tf32(ssum / (cnt + eps))
__global__ void k_norm() {
    size_t i = (size_t)blockIdx.x*256 + threadIdx.x;
    float rcp = 1.f/(g_cnt[i >> 5] + EPSV);
    float4 v = ((float4*)g_ssum)[i];
    v.x*=rcp; v.y*=rcp; v.z*=rcp; v.w*=rcp;
    ((float4*)g_ssum)[i] = tf4(v);
}

// ---- 3x3 stride-2 conv as implicit GEMM on mma.sync TF32 ----
// 2 CTAs/SM: CTA = 128m x 128n (N-half), 256 thr / 8 warps, 3-buffer K32 pipeline.
#define CV_BUF   32768
#define CV_A(i)  ((i)*CV_BUF)
#define CV_B(i)  ((i)*CV_BUF + 16384)
#define CV_BIAS  (3*CV_BUF)
#define CV_SMEM  (CV_BIAS + 512)

__device__ __forceinline__ void cv_stage(uint32_t sb, int s, int buf, int oy, int nh,
                                         const float* __restrict__ xin, int tid) {
    int tap = s >> 2, cinb = (s & 3) * 32;
    int ky = tap / 3, kx = tap - 3*ky;
    int iy = 2*oy - 1 + ky;
    bool iyok = (unsigned)iy < HH;
    int r = tid >> 1, q0 = (tid & 1) * 4;        // 256 threads: 4 A-chunks each
    int ix = 2*r - 1 + kx;
    bool ok = iyok && ((unsigned)ix < WW);
    const float* src = xin + ((size_t)(iyok ? iy : 0)*WW + (ok ? ix : 0))*CIN + cinb;
    uint32_t dstA = sb + CV_A(buf) + r*128;
    int sz = ok ? 16 : 0;
    int sw = r & 7;
    #pragma unroll
    for (int j = 0; j < 4; j++) {
        int q = q0 + j;
        cpa16(dstA + ((q ^ sw) * 16), src + q*4, sz);
    }
    const float4* bsrc = g_wBp + (size_t)s*2048 + nh*1024 + tid*4;   // this N-half's slice
    uint32_t dstB = sb + CV_B(buf) + tid*64;
    #pragma unroll
    for (int j = 0; j < 4; j++)
        cpa16(dstB + j*16, (const float*)(bsrc + j), 16);
    asm volatile("cp.async.commit_group;" ::: "memory");
}

__device__ __forceinline__ float ldsA(const float* sA, int r, int k) {
    int kk = ((((k >> 2) ^ (r & 7)) << 2) | (k & 3));
    return sA[r*32 + kk];
}

__global__ void __launch_bounds__(256, 2) k_conv(const float* __restrict__ cb) {
    extern __shared__ char smem[];
    uint32_t sb = smem_u32(smem);
    int tid = threadIdx.x, w = tid >> 5, lane = tid & 31;
    int g = lane >> 2, cl = lane & 3;
    int wm = w & 3, wn = w >> 2;                 // warp tile 32m x 64n (wn 0..1)
    int oy = blockIdx.x, nh = blockIdx.y, b = blockIdx.z;
    const float* xin = g_ssum + (size_t)b*HH*WW*CIN;

    if (tid < 128) *(float*)(smem + CV_BIAS + tid*4) = cb[nh*128 + tid];

    float acc[2][8][4];
    #pragma unroll
    for (int mt=0;mt<2;mt++) for (int nt=0;nt<8;nt++) for (int r2=0;r2<4;r2++) acc[mt][nt][r2]=0.f;

    cv_stage(sb, 0, 0, oy, nh, xin, tid);
    cv_stage(sb, 1, 1, oy, nh, xin, tid);

    int bufc = 0;
    for (int s = 0; s < SLABS; s++) {
        if (s < SLABS-1) asm volatile("cp.async.wait_group 1;" ::: "memory");
        else             asm volatile("cp.async.wait_group 0;" ::: "memory");
        __syncthreads();
        int bufn = bufc + 2; if (bufn >= 3) bufn -= 3;
        if (s + 2 < SLABS) cv_stage(sb, s + 2, bufn, oy, nh, xin, tid);
        const float*  sA = (const float*) (smem + CV_A(bufc));
        const float4* sB = (const float4*)(smem + CV_B(bufc));
        #pragma unroll
        for (int h2 = 0; h2 < 2; h2++) {
            float4 bv[8];
            #pragma unroll
            for (int nt = 0; nt < 8; nt++)
                bv[nt] = sB[(wn*8 + nt)*64 + h2*32 + g*4 + cl];
            #pragma unroll
            for (int hh = 0; hh < 2; hh++) {
                int kc = (h2*2 + hh)*8 + cl;
                float a[2][4];
                #pragma unroll
                for (int mt = 0; mt < 2; mt++) {
                    int r0 = wm*32 + mt*16 + g;
                    a[mt][0] = ldsA(sA, r0,     kc);
                    a[mt][1] = ldsA(sA, r0 + 8, kc);
                    a[mt][2] = ldsA(sA, r0,     kc + 4);
                    a[mt][3] = ldsA(sA, r0 + 8, kc + 4);
                }
                #pragma unroll
                for (int mt = 0; mt < 2; mt++)
                    #pragma unroll
                    for (int nt = 0; nt < 8; nt++) {
                        float b0 = hh ? bv[nt].z : bv[nt].x;
                        float b1 = hh ? bv[nt].w : bv[nt].y;
                        mma8(acc[mt][nt][0], acc[mt][nt][1], acc[mt][nt][2], acc[mt][nt][3],
                             a[mt][0], a[mt][1], a[mt][2], a[mt][3], b0, b1);
                    }
            }
        }
        bufc++; if (bufc >= 3) bufc = 0;
    }

    // epilogue
    const float* bias = (const float*)(smem + CV_BIAS);
    float* ybase = g_y + (((size_t)b*HD + oy)*WD)*COUT + nh*128;
    #pragma unroll
    for (int mt = 0; mt < 2; mt++) {
        int ox0 = wm*32 + mt*16 + g;
        #pragma unroll
        for (int nt = 0; nt < 8; nt++) {
            int n = wn*64 + nt*8 + cl*2;
            float b0 = bias[n], b1 = bias[n+1];
            *(float2*)(ybase + (size_t)ox0*COUT + n)     = make_float2(acc[mt][nt][0]+b0, acc[mt][nt][1]+b1);
            *(float2*)(ybase + (size_t)(ox0+8)*COUT + n) = make_float2(acc[mt][nt][2]+b0, acc[mt][nt][3]+b1);
        }
    }
}

// bilinear gather from conv map at orig points, weighted scatter to tokens
__global__ void k_map2token(const float* __restrict__ loc, const int* __restrict__ idx_agg,
                            const float* __restrict__ aggw) {
    int p    = blockIdx.x*8 + (threadIdx.x>>5);
    int lane = threadIdx.x & 31;
    int b    = p >> 16;
    float lx = fminf(fmaxf(loc[2*p],   -1.f), 1.f);
    float ly = fminf(fmaxf(loc[2*p+1], -1.f), 1.f);
    float fx = fminf(fmaxf(0.5f*(lx+1.f)*(float)WD - 0.5f, 0.f), (float)(WD-1));
    float fy = fminf(fmaxf(0.5f*(ly+1.f)*(float)HD - 0.5f, 0.f), (float)(HD-1));
    float x0f = floorf(fx), y0f = floorf(fy);
    float wx = fx - x0f, wy = fy - y0f;
    int x0 = (int)x0f, y0 = (int)y0f;
    int x1 = min(x0+1, WD-1), y1 = min(y0+1, HD-1);
    const float* base = g_y + (size_t)b*HD*WD*COUT;
    const float4* r00 = (const float4*)(base + (size_t)(y0*WD+x0)*COUT);
    const float4* r01 = (const float4*)(base + (size_t)(y0*WD+x1)*COUT);
    const float4* r10 = (const float4*)(base + (size_t)(y1*WD+x0)*COUT);
    const float4* r11 = (const float4*)(base + (size_t)(y1*WD+x1)*COUT);
    float w00=(1.f-wx)*(1.f-wy), w01=wx*(1.f-wy), w10=(1.f-wx)*wy, w11=wx*wy;
    float wpt = aggw[p];
    int i = idx_agg[p];
    float* dst = g_num + ((size_t)b*NN + i)*COUT;
    #pragma unroll
    for (int q = 0; q < 2; q++) {
        int c4 = q*32 + lane;
        float4 a = r00[c4], bq = r01[c4], cc = r10[c4], d = r11[c4];
        float4 f;
        f.x = (w00*a.x + w01*bq.x + w10*cc.x + w11*d.x)*wpt;
        f.y = (w00*a.y + w01*bq.y + w10*cc.y + w11*d.y)*wpt;
        f.z = (w00*a.z + w01*bq.z + w10*cc.z + w11*d.z)*wpt;
        f.w = (w00*a.w + w01*bq.w + w10*cc.w + w11*d.w)*wpt;
        red_add4(dst + c4*4, f);
    }
    if (!lane) atomicAdd(&g_den[(size_t)b*NN + i], wpt);
}

// ---- skip GEMM (x @ skip_w^T) on TF32 mma.sync, fused tok = num/(den+eps) + skip ----
#define SK_BUF   49152
#define SK_A(i)  ((i)*SK_BUF)
#define SK_B(i)  ((i)*SK_BUF + 16384)
#define SK_SMEM  (3*SK_BUF)

__device__ __forceinline__ void sk_stage(uint32_t sb, int s, int buf,
                                         const float* __restrict__ xrow0, int tid) {
    int r = tid >> 2, q0 = (tid & 3) * 2;
    const float* src = xrow0 + (size_t)r*CIN + s*32;
    uint32_t dstA = sb + SK_A(buf) + r*128;
    int sw = r & 7;
    #pragma unroll
    for (int j = 0; j < 2; j++) {
        int q = q0 + j;
        cpa16(dstA + ((q ^ sw) * 16), src + q*4, 16);
    }
    const float4* bsrc = g_wSp + (size_t)s*2048 + tid*4;
    uint32_t dstB = sb + SK_B(buf) + tid*64;
    #pragma unroll
    for (int j = 0; j < 4; j++)
        cpa16(dstB + j*16, (const float*)(bsrc + j), 16);
    asm volatile("cp.async.commit_group;" ::: "memory");
}

__global__ void __launch_bounds__(512, 1) k_skip(const float* __restrict__ x) {
    extern __shared__ char smem[];
    uint32_t sb = smem_u32(smem);
    int tid = threadIdx.x, w = tid >> 5, lane = tid & 31;
    int g = lane >> 2, cl = lane & 3;
    int wm = w & 3, wn = w >> 2;
    int m0 = blockIdx.x * 128;
    const float* xrow0 = x + (size_t)m0*CIN;

    float acc[2][8][4];
    #pragma unroll
    for (int mt=0;mt<2;mt++) for (int nt=0;nt<8;nt++) for (int r2=0;r2<4;r2++) acc[mt][nt][r2]=0.f;

    sk_stage(sb, 0, 0, xrow0, tid);
    sk_stage(sb, 1, 1, xrow0, tid);

    int bufc = 0;
    for (int s = 0; s < 4; s++) {
        if (s < 3) asm volatile("cp.async.wait_group 1;" ::: "memory");
        else       asm volatile("cp.async.wait_group 0;" ::: "memory");
        __syncthreads();
        int bufn = bufc + 2; if (bufn >= 3) bufn -= 3;
        if (s + 2 < 4) sk_stage(sb, s + 2, bufn, xrow0, tid);
        const float*  sA = (const float*) (smem + SK_A(bufc));
        const float4* sB = (const float4*)(smem + SK_B(bufc));
        #pragma unroll
        for (int h2 = 0; h2 < 2; h2++) {
            float4 bv[8];
            #pragma unroll
            for (int nt = 0; nt < 8; nt++)
                bv[nt] = sB[(wn*8 + nt)*64 + h2*32 + g*4 + cl];
            #pragma unroll
            for (int hh = 0; hh < 2; hh++) {
                int kc = (h2*2 + hh)*8 + cl;
                float a[2][4];
                #pragma unroll
                for (int mt = 0; mt < 2; mt++) {
                    int r0 = wm*32 + mt*16 + g;
                    a[mt][0] = to_tf32(ldsA(sA, r0,     kc));
                    a[mt][1] = to_tf32(ldsA(sA, r0 + 8, kc));
                    a[mt][2] = to_tf32(ldsA(sA, r0,     kc + 4));
                    a[mt][3] = to_tf32(ldsA(sA, r0 + 8, kc + 4));
                }
                #pragma unroll
                for (int mt = 0; mt < 2; mt++)
                    #pragma unroll
                    for (int nt = 0; nt < 8; nt++) {
                        float b0 = hh ? bv[nt].z : bv[nt].x;
                        float b1 = hh ? bv[nt].w : bv[nt].y;
                        mma8(acc[mt][nt][0], acc[mt][nt][1], acc[mt][nt][2], acc[mt][nt][3],
                             a[mt][0], a[mt][1], a[mt][2], a[mt][3], b0, b1);
                    }
            }
        }
        bufc++; if (bufc >= 3) bufc = 0;
    }

    // epilogue: tok = acc + num * rcp(den), overwrite g_num
    #pragma unroll
    for (int mt = 0; mt < 2; mt++) {
        int r0 = wm*32 + mt*16 + g;
        int row0 = m0 + r0, row1 = row0 + 8;
        float rcp0 = 1.f/(g_den[row0] + EPSV);
        float rcp1 = 1.f/(g_den[row1] + EPSV);
        float* nb0 = g_num + (size_t)row0*COUT;
        float* nb1 = g_num + (size_t)row1*COUT;
        #pragma unroll
        for (int nt = 0; nt < 8; nt++) {
            int n = wn*64 + nt*8 + cl*2;
            float2 v0 = *(float2*)(nb0 + n);
            float2 v1 = *(float2*)(nb1 + n);
            *(float2*)(nb0 + n) = make_float2(acc[mt][nt][0] + v0.x*rcp0, acc[mt][nt][1] + v0.y*rcp0);
            *(float2*)(nb1 + n) = make_float2(acc[mt][nt][2] + v1.x*rcp1, acc[mt][nt][3] + v1.y*rcp1);
        }
    }
}

__global__ void k_bnstats() {
    int c  = threadIdx.x;
    int r0 = blockIdx.x*256;
    double s = 0.0, s2 = 0.0;
    for (int r = 0; r < 256; r++) {
        float v = g_num[(size_t)(r0 + r)*COUT + c];
        s += v; s2 += (double)v*v;
    }
    atomicAdd(&g_bnsum[c], s);
    atomicAdd(&g_bnsq[c],  s2);
}

__global__ void k_bnfinal(const float* __restrict__ gam, const float* __restrict__ bet) {
    int c = threadIdx.x;
    double m  = (double)BB*NN;
    double mu = g_bnsum[c]/m;
    double var = g_bnsq[c]/m - mu*mu;
    float sc = gam[c] * (float)(1.0/sqrt(var + 1e-5));
    g_scale[c] = sc;
    g_shift[c] = bet[c] - (float)mu*sc;
}

// apply BN on the fly: write x_out = relu(bn(tok)), conf, exp(conf). tokn NOT materialized.
__global__ void k_bnconf(const float* __restrict__ cw, const float* __restrict__ cbv,
                         float* __restrict__ out_xout, float* __restrict__ out_conf) {
    int row  = blockIdx.x*8 + (threadIdx.x>>5);
    int lane = threadIdx.x & 31;
    const float4* t  = (const float4*)(g_num  + (size_t)row*COUT);
    float4* xo       = (float4*)(out_xout + (size_t)row*COUT);
    float dot = 0.f;
    #pragma unroll
    for (int q = 0; q < 2; q++) {
        int c4 = q*32 + lane;
        float4 v  = t[c4];
        float4 sc = ((const float4*)g_scale)[c4];
        float4 sh = ((const float4*)g_shift)[c4];
        float4 w  = ((const float4*)cw)[c4];
        float4 r = make_float4(v.x*sc.x+sh.x, v.y*sc.y+sh.y, v.z*sc.z+sh.z, v.w*sc.w+sh.w);
        dot += r.x*w.x + r.y*w.y + r.z*w.z + r.w*w.w;
        xo[c4] = make_float4(fmaxf(r.x,0.f), fmaxf(r.y,0.f), fmaxf(r.z,0.f), fmaxf(r.w,0.f));
    }
    #pragma unroll
    for (int o = 16; o; o >>= 1) dot += __shfl_xor_sync(0xffffffffu, dot, o);
    if (!lane) {
        float cf = dot + cbv[0];
        out_conf[row] = cf;
        g_wexp[row]   = expf(cf);
    }
}

// gather tok from g_num, apply BN inline, weighted scatter into 64x64 cells
__global__ void k_cluster(const float* __restrict__ loc, const int* __restrict__ idx_agg,
                          float* __restrict__ out_idx) {
    int p    = blockIdx.x*8 + (threadIdx.x>>5);
    int lane = threadIdx.x & 31;
    int b    = p >> 16;
    int cell = grid_cell(loc[2*p], loc[2*p+1], HC, WC);
    int i    = idx_agg[p];
    float w  = g_wexp[(size_t)b*NN + i];
    const float4* src = (const float4*)(g_num + ((size_t)b*NN + i)*COUT);
    float* dst = g_cnum + ((size_t)b*NS + cell)*COUT;
    #pragma unroll
    for (int q = 0; q < 2; q++) {
        int c4 = q*32 + lane;
        float4 v  = src[c4];
        float4 sc = ((const float4*)g_scale)[c4];
        float4 sh = ((const float4*)g_shift)[c4];
        red_add4(dst + c4*4, make_float4((v.x*sc.x+sh.x)*w, (v.y*sc.y+sh.y)*w,
                                         (v.z*sc.z+sh.z)*w, (v.w*sc.w+sh.w)*w));
    }
    if (!lane) {
        atomicAdd(&g_cden[(size_t)b*NS + cell], w);
        g_wpt[p]   = w;
        out_idx[p] = (float)cell;
    }
}

__global__ void k_xdown(float* __restrict__ out_xd) {
    int row  = blockIdx.x*8 + (threadIdx.x>>5);
    int lane = threadIdx.x & 31;
    float rcp = 1.f/(g_cden[row] + EPSV);
    const float4* src = (const float4*)(g_cnum + (size_t)row*COUT);
    float4* dst = (float4*)(out_xd + (size_t)row*COUT);
    #pragma unroll
    for (int q = 0; q < 2; q++) {
        int c4 = q*32 + lane;
        float4 v = src[c4];
        dst[c4] = make_float4(fmaxf(v.x*rcp,0.f), fmaxf(v.y*rcp,0.f),
                              fmaxf(v.z*rcp,0.f), fmaxf(v.w*rcp,0.f));
    }
}

__global__ void k_aggmax(const float* __restrict__ loc, const float* __restrict__ aggw) {
    __shared__ float sm[256];
    int p = blockIdx.x*256 + threadIdx.x;
    int b = p >> 16;
    int cell = grid_cell(loc[2*p], loc[2*p+1], HC, WC);
    float aw = aggw[p] * g_wpt[p] / (g_cden[(size_t)b*NS + cell] + EPSV);
    g_wpt[p] = aw;
    sm[threadIdx.x] = aw;
    __syncthreads();
    for (int s = 128; s; s >>= 1) {
        if (threadIdx.x < s) sm[threadIdx.x] = fmaxf(sm[threadIdx.x], sm[threadIdx.x+s]);
        __syncthreads();
    }
    if (!threadIdx.x) atomicMax(&g_maxw[b], __float_as_uint(sm[0]));
}

__global__ void k_aggnorm(float* __restrict__ out_aw) {
    int p = blockIdx.x*256 + threadIdx.x;
    int b = p >> 16;
    out_aw[p] = g_wpt[p] / __uint_as_float(g_maxw[b]);
}

// ---------------- launch ----------------
extern "C" void kernel_launch(void* const* d_in, const int* in_sizes, int n_in,
                              void* d_out, int out_size) {
    const float* x      = (const float*)d_in[0];
    const float* loc    = (const float*)d_in[1];
    const int*   idxa   = (const int*)  d_in[2];
    const float* aggw   = (const float*)d_in[3];
    const float* conv_w = (const float*)d_in[4];
    const float* conv_b = (const float*)d_in[5];
    const float* skip_w = (const float*)d_in[6];
    const float* gamma  = (const float*)d_in[7];
    const float* beta   = (const float*)d_in[8];
    const float* conf_w = (const float*)d_in[9];
    const float* conf_b = (const float*)d_in[10];

    float* out      = (float*)d_out;
    float* out_xd   = out;                                    // [4,4096,256]
    float* out_xout = out + (size_t)BB*NS*COUT;               // [4,16384,256]
    float* out_conf = out_xout + (size_t)BB*NN*COUT;          // [4,16384,1]
    float* out_aw   = out_conf + (size_t)BB*NN;               // [4,65536,1]
    float* out_idx  = out_aw   + (size_t)BB*NP;               // [4,65536]

    cudaFuncSetAttribute(k_conv, cudaFuncAttributeMaxDynamicSharedMemorySize, CV_SMEM);
    cudaFuncSetAttribute(k_skip, cudaFuncAttributeMaxDynamicSharedMemorySize, SK_SMEM);

    k_init<<<2048, 256>>>(skip_w, conv_w);
    k_token2map<<<BB*NP/8, 256>>>(x, loc, idxa);
    k_norm<<<(BB*HH*WW*CIN/4)/256, 256>>>();
    k_conv<<<dim3(HD, 2, BB), 256, CV_SMEM>>>(conv_b);
    k_map2token<<<BB*NP/8, 256>>>(loc, idxa, aggw);
    k_skip<<<BB*NN/128, 512, SK_SMEM>>>(x);
    k_bnstats<<<BB*NN/256, 256>>>();
    k_bnfinal<<<1, 256>>>(gamma, beta);
    k_bnconf<<<BB*NN/8, 256>>>(conf_w, conf_b, out_xout, out_conf);
    k_cluster<<<BB*NP/8, 256>>>(loc, idxa, out_idx);
    k_xdown<<<BB*NS/8, 256>>>(out_xd);
    k_aggmax<<<BB*NP/256, 256>>>(loc, aggw);
    k_aggnorm<<<BB*NP/256, 256>>>(out_aw);
}

// round 12
// speedup vs baseline: 2.0538x; 1.2719x over previous
#include <cuda_runtime.h>
#include <cuda_fp16.h>
#include <math.h>
#include <stdint.h>

#define BB   4
#define NN   16384
#define CIN  128
#define COUT 256
#define HH   256
#define WW   256
#define NP   65536      // N0 = H*W points
#define HD   128
#define WD   128
#define HC   64
#define WC   64
#define NS   4096       // HC*WC
#define EPSV 1e-6f
#define KTOT 1152       // 9*CIN
#define SLABS 36        // KTOT/32

// ---------------- scratch (device globals: no allocation allowed) ----------------
__device__ float  g_ssum[(size_t)BB*HH*WW*CIN];   // token2map sum (fp32, unnormalized) (128MB)
__device__ float  g_cnt [(size_t)BB*HH*WW];       // token2map count
__device__ uint2  g_mapH[(size_t)BB*HH*WW*CIN/4]; // normalized fp16 map (64MB)
__device__ float  g_y   [(size_t)BB*HD*WD*COUT];  // conv output        (64MB)
__device__ float  g_num [(size_t)BB*NN*COUT];     // map2token num -> tok (64MB)
__device__ float  g_den [(size_t)BB*NN];
__device__ float  g_wexp[(size_t)BB*NN];          // exp(conf)
__device__ double g_bnsum[COUT];
__device__ double g_bnsq [COUT];
__device__ float  g_scale[COUT];
__device__ float  g_shift[COUT];
__device__ float  g_cnum[(size_t)BB*NS*COUT];     // cluster num (16MB)
__device__ float  g_cden[(size_t)BB*NS];
__device__ float  g_wpt [(size_t)BB*NP];          // per-point weight, reused
__device__ unsigned g_maxw[BB];
__device__ uint2  g_wBh [(size_t)SLABS*2048];     // conv weights fp16 frag image per slab (576KB)
__device__ float4 g_wSp [(size_t)4*2048];         // skip weights tf32 smem image (4 slabs)

// ---------------- helpers ----------------
__device__ __forceinline__ void red_add4(float* p, float4 v) {
    asm volatile("red.global.add.v4.f32 [%0], {%1,%2,%3,%4};"
                 :: "l"(__cvta_generic_to_global(p)),
                    "f"(v.x), "f"(v.y), "f"(v.z), "f"(v.w) : "memory");
}

__device__ __forceinline__ int grid_cell(float lx, float ly, int Hg, int Wg) {
    lx = fminf(fmaxf(lx, -1.f), 1.f);
    ly = fminf(fmaxf(ly, -1.f), 1.f);
    int px = min(max(__float2int_rn(0.5f*(lx+1.f)*(float)Wg - 0.5f), 0), Wg-1);
    int py = min(max(__float2int_rn(0.5f*(ly+1.f)*(float)Hg - 0.5f), 0), Hg-1);
    return py*Wg + px;
}

__device__ __forceinline__ float to_tf32(float x) {
    uint32_t u; asm("cvt.rna.tf32.f32 %0, %1;" : "=r"(u) : "f"(x));
    return __uint_as_float(u);
}
__device__ __forceinline__ float4 tf4(float4 v) {
    return make_float4(to_tf32(v.x), to_tf32(v.y), to_tf32(v.z), to_tf32(v.w));
}
__device__ __forceinline__ uint32_t packh2(float lo, float hi) {
    __half2 h = __floats2half2_rn(lo, hi);
    return *(uint32_t*)&h;
}

__device__ __forceinline__ uint32_t smem_u32(const void* p) {
    uint32_t a;
    asm("{ .reg .u64 t; cvta.to.shared.u64 t, %1; cvt.u32.u64 %0, t; }" : "=r"(a) : "l"(p));
    return a;
}

__device__ __forceinline__ void cpa16(uint32_t dst, const void* src, int srcsz) {
    asm volatile("cp.async.cg.shared.global [%0], [%1], 16, %2;"
                 :: "r"(dst), "l"(__cvta_generic_to_global(src)), "r"(srcsz) : "memory");
}

__device__ __forceinline__ void mma8(float& d0, float& d1, float& d2, float& d3,
                                     float a0, float a1, float a2, float a3,
                                     float b0, float b1) {
    asm volatile("mma.sync.aligned.m16n8k8.row.col.f32.tf32.tf32.f32 "
                 "{%0,%1,%2,%3},{%4,%5,%6,%7},{%8,%9},{%0,%1,%2,%3};"
                 : "+f"(d0), "+f"(d1), "+f"(d2), "+f"(d3)
                 : "r"(__float_as_uint(a0)), "r"(__float_as_uint(a1)),
                   "r"(__float_as_uint(a2)), "r"(__float_as_uint(a3)),
                   "r"(__float_as_uint(b0)), "r"(__float_as_uint(b1)));
}

__device__ __forceinline__ void mma16(float& d0, float& d1, float& d2, float& d3,
                                      uint32_t a0, uint32_t a1, uint32_t a2, uint32_t a3,
                                      uint32_t b0, uint32_t b1) {
    asm volatile("mma.sync.aligned.m16n8k16.row.col.f32.f16.f16.f32 "
                 "{%0,%1,%2,%3},{%4,%5,%6,%7},{%8,%9},{%0,%1,%2,%3};"
                 : "+f"(d0), "+f"(d1), "+f"(d2), "+f"(d3)
                 : "r"(a0), "r"(a1), "r"(a2), "r"(a3), "r"(b0), "r"(b1));
}

// ---------------- kernels ----------------
// fused: zero accumulators + build fp16 conv-B image + tf32 skip-B image
__global__ void k_init(const float* __restrict__ skw, const float* __restrict__ cw) {
    size_t t = (size_t)blockIdx.x*blockDim.x + threadIdx.x;
    size_t stride = (size_t)gridDim.x*blockDim.x;
    float4 z = make_float4(0.f,0.f,0.f,0.f);
    for (size_t i=t; i < (size_t)BB*HH*WW*CIN/4; i+=stride) ((float4*)g_ssum)[i]=z;
    for (size_t i=t; i < (size_t)BB*HH*WW/4;     i+=stride) ((float4*)g_cnt )[i]=z;
    for (size_t i=t; i < (size_t)BB*NN*COUT/4;   i+=stride) ((float4*)g_num )[i]=z;
    for (size_t i=t; i < (size_t)BB*NN/4;        i+=stride) ((float4*)g_den )[i]=z;
    for (size_t i=t; i < (size_t)BB*NS*COUT/4;   i+=stride) ((float4*)g_cnum)[i]=z;
    for (size_t i=t; i < (size_t)BB*NS/4;        i+=stride) ((float4*)g_cden)[i]=z;
    if (t < COUT) { g_bnsum[t]=0.0; g_bnsq[t]=0.0; }
    if (t < BB)   g_maxw[t]=0u;
    if (t < (size_t)SLABS*2048) {
        // fp16 B frag image: fi -> [s][nh][ntFull][h16][g][cl]
        int fi = (int)t;
        int s   = fi >> 11, r = fi & 2047;
        int nh  = r >> 10;  int r2 = r & 1023;
        int ntF = r2 >> 6, h16 = (r2 >> 5) & 1, g = (r2 >> 2) & 7, cl = r2 & 3;
        int n   = nh*128 + ntF*8 + g;
        int k0  = s*32 + h16*16 + 2*cl;
        uint2 v;
        v.x = packh2(cw[(size_t)k0*COUT + n],     cw[(size_t)(k0+1)*COUT + n]);
        v.y = packh2(cw[(size_t)(k0+8)*COUT + n], cw[(size_t)(k0+9)*COUT + n]);
        g_wBh[fi] = v;
    }
    if (t < (size_t)4*2048) {
        int fi = (int)t;
        int s  = fi >> 11, r = fi & 2047;
        int nt = r >> 6, h2 = (r >> 5) & 1, g = (r >> 2) & 7, c = r & 3;
        int n  = nt*8 + g;
        int k0 = s*32 + h2*16 + c;
        const float* wr = skw + (size_t)n*CIN;     // skip_w[n][k]
        float4 v = make_float4(wr[k0], wr[k0+4], wr[k0+8], wr[k0+12]);
        g_wSp[fi] = tf4(v);
    }
}

// scatter token features to H x W map (sum + count)
__global__ void k_token2map(const float* __restrict__ x, const float* __restrict__ loc,
                            const int* __restrict__ idx_agg) {
    int p    = blockIdx.x*8 + (threadIdx.x>>5);
    int lane = threadIdx.x & 31;
    int b    = p >> 16;
    float lx = loc[2*p], ly = loc[2*p+1];
    int cell = grid_cell(lx, ly, HH, WW);
    int i    = idx_agg[p];
    const float4* src = (const float4*)(x + ((size_t)b*NN + i)*CIN);
    float* dst = g_ssum + ((size_t)b*HH*WW + cell)*CIN;
    float4 v = src[lane];
    red_add4(dst + lane*4, v);
    if (!lane) atomicAdd(&g_cnt[(size_t)b*HH*WW + cell], 1.0f);
}

// normalize and convert to fp16 map: mapH = fp16(ssum / (cnt + eps))
__global__ void k_norm() {
    size_t i = (size_t)blockIdx.x*256 + threadIdx.x;
    float rcp = 1.f/(g_cnt[i >> 5] + EPSV);
    float4 v = ((float4*)g_ssum)[i];
    uint2 h;
    h.x = packh2(v.x*rcp, v.y*rcp);
    h.y = packh2(v.z*rcp, v.w*rcp);
    g_mapH[i] = h;
}

// ---- 3x3 stride-2 conv as implicit GEMM on mma.sync FP16 (m16n8k16) ----
// 2 CTAs/SM: CTA = 128m x 128n, 256 thr / 8 warps, 3-buffer K32 pipeline.
// smem per buffer: A 8KB (fp16, swizzled 16B chunks) + B 8KB (fp16 frag image)
#define CV_BUF   16384
#define CV_A(i)  ((i)*CV_BUF)
#define CV_B(i)  ((i)*CV_BUF + 8192)
#define CV_BIAS  (3*CV_BUF)
#define CV_SMEM  (CV_BIAS + 1024)

__device__ __forceinline__ int aswz(int r, int c) {      // chunk swizzle
    return c ^ (r & 3) ^ ((r >> 2) & 1);
}

__device__ __forceinline__ void cv_stage(uint32_t sb, int s, int buf, int oy, int nh,
                                         int tid) {
    int tap = s >> 2, cinb = (s & 3) * 32;
    int ky = tap / 3, kx = tap - 3*ky;
    int iy = 2*oy - 1 + ky;
    bool iyok = (unsigned)iy < HH;
    int r = tid >> 1, c0 = (tid & 1) * 2;       // 2 chunks of 16B per thread
    int ix = 2*r - 1 + kx;
    bool ok = iyok && ((unsigned)ix < WW);
    const __half* src = (const __half*)g_mapH
        + ((size_t)(iyok ? iy : 0)*WW + (ok ? ix : 0))*CIN + cinb;
    uint32_t dstA = sb + CV_A(buf) + r*64;
    int sz = ok ? 16 : 0;
    #pragma unroll
    for (int j = 0; j < 2; j++) {
        int c = c0 + j;
        cpa16(dstA + aswz(r, c)*16, src + c*8, sz);
    }
    const uint2* bsrc = g_wBh + (size_t)s*2048 + nh*1024 + tid*4;
    uint32_t dstB = sb + CV_B(buf) + tid*32;
    cpa16(dstB,      bsrc,     16);
    cpa16(dstB + 16, bsrc + 2, 16);
    asm volatile("cp.async.commit_group;" ::: "memory");
}

__device__ __forceinline__ uint32_t a_word(const char* sA, int r, int w) {  // w 0..15
    int off = r*64 + aswz(r, w >> 2)*16 + (w & 3)*4;
    return *(const uint32_t*)(sA + off);
}

__global__ void __launch_bounds__(256, 2) k_conv(const float* __restrict__ cb) {
    extern __shared__ char smem[];
    uint32_t sb = smem_u32(smem);
    int tid = threadIdx.x, w = tid >> 5, lane = tid & 31;
    int g = lane >> 2, cl = lane & 3;
    int wm = w & 3, wn = w >> 2;                 // warp tile 32m x 64n
    int oy = blockIdx.x, nh = blockIdx.y, b = blockIdx.z;
    int tb = b;                                  // batch offset folded into mapH addressing
    const size_t mapOfs = (size_t)tb*HH*WW*CIN;  // in halves
    (void)mapOfs;

    if (tid < 128) *(float*)(smem + CV_BIAS + tid*4) = cb[nh*128 + tid];

    float acc[2][8][4];
    #pragma unroll
    for (int mt=0;mt<2;mt++) for (int nt=0;nt<8;nt++) for (int r2=0;r2<4;r2++) acc[mt][nt][r2]=0.f;

    // batch handled by offsetting the staging source: fold b into oy path via pointer math
    // cv_stage uses g_mapH directly; add batch offset by biasing iy row index:
    // simplest: use a wrapper that adds b*HH rows
    // (we inline: stage with oy' such that iy index includes batch)
    // -> implement by temporarily treating map as [(b*HH + iy), WW, CIN]
    // cv_stage computes iy from oy; add b*HH inside by passing adjusted base below.

    // stage slabs 0,1
    {
        // we re-implement staging inline with batch offset
    }
    // NOTE: to keep cv_stage simple it reads g_mapH without batch; we shift via oyb trick:
    // iy_global = b*HH + iy. Since iy = 2*oy-1+ky and rows are contiguous, pass oyb = oy + b*HH/2
    // only valid because HH is even and boundary checks must use local iy. So instead we
    // duplicate staging here with explicit batch base.
    auto stage = [&](int s, int buf) {
        int tap = s >> 2, cinb = (s & 3) * 32;
        int ky = tap / 3, kx = tap - 3*ky;
        int iy = 2*oy - 1 + ky;
        bool iyok = (unsigned)iy < HH;
        int r = tid >> 1, c0 = (tid & 1) * 2;
        int ix = 2*r - 1 + kx;
        bool ok = iyok && ((unsigned)ix < WW);
        const __half* src = (const __half*)g_mapH
            + ((size_t)b*HH*WW + (size_t)(iyok ? iy : 0)*WW + (ok ? ix : 0))*CIN + cinb;
        uint32_t dstA = sb + CV_A(buf) + r*64;
        int sz = ok ? 16 : 0;
        #pragma unroll
        for (int j = 0; j < 2; j++) {
            int c = c0 + j;
            cpa16(dstA + aswz(r, c)*16, src + c*8, sz);
        }
        const uint2* bsrc = g_wBh + (size_t)s*2048 + nh*1024 + tid*4;
        uint32_t dstB = sb + CV_B(buf) + tid*32;
        cpa16(dstB,      bsrc,     16);
        cpa16(dstB + 16, bsrc + 2, 16);
        asm volatile("cp.async.commit_group;" ::: "memory");
    };

    stage(0, 0);
    stage(1, 1);

    int bufc = 0;
    for (int s = 0; s < SLABS; s++) {
        if (s < SLABS-1) asm volatile("cp.async.wait_group 1;" ::: "memory");
        else             asm volatile("cp.async.wait_group 0;" ::: "memory");
        __syncthreads();
        int bufn = bufc + 2; if (bufn >= 3) bufn -= 3;
        if (s + 2 < SLABS) stage(s + 2, bufn);
        const char*  sA = smem + CV_A(bufc);
        const uint2* sB = (const uint2*)(smem + CV_B(bufc));
        #pragma unroll
        for (int h16 = 0; h16 < 2; h16++) {
            uint2 bv[8];
            #pragma unroll
            for (int nt = 0; nt < 8; nt++)
                bv[nt] = sB[(wn*8 + nt)*64 + h16*32 + g*4 + cl];
            uint32_t a[2][4];
            #pragma unroll
            for (int mt = 0; mt < 2; mt++) {
                int r0 = wm*32 + mt*16 + g;
                a[mt][0] = a_word(sA, r0,     h16*8 + cl);
                a[mt][1] = a_word(sA, r0 + 8, h16*8 + cl);
                a[mt][2] = a_word(sA, r0,     h16*8 + cl + 4);
                a[mt][3] = a_word(sA, r0 + 8, h16*8 + cl + 4);
            }
            #pragma unroll
            for (int mt = 0; mt < 2; mt++)
                #pragma unroll
                for (int nt = 0; nt < 8; nt++)
                    mma16(acc[mt][nt][0], acc[mt][nt][1], acc[mt][nt][2], acc[mt][nt][3],
                          a[mt][0], a[mt][1], a[mt][2], a[mt][3],
                          bv[nt].x, bv[nt].y);
        }
        bufc++; if (bufc >= 3) bufc = 0;
    }

    // epilogue
    const float* bias = (const float*)(smem + CV_BIAS);
    float* ybase = g_y + (((size_t)b*HD + oy)*WD)*COUT + nh*128;
    #pragma unroll
    for (int mt = 0; mt < 2; mt++) {
        int ox0 = wm*32 + mt*16 + g;
        #pragma unroll
        for (int nt = 0; nt < 8; nt++) {
            int n = wn*64 + nt*8 + cl*2;
            float b0 = bias[n], b1 = bias[n+1];
            *(float2*)(ybase + (size_t)ox0*COUT + n)     = make_float2(acc[mt][nt][0]+b0, acc[mt][nt][1]+b1);
            *(float2*)(ybase + (size_t)(ox0+8)*COUT + n) = make_float2(acc[mt][nt][2]+b0, acc[mt][nt][3]+b1);
        }
    }
}

// bilinear gather from conv map at orig points, weighted scatter to tokens
__global__ void k_map2token(const float* __restrict__ loc, const int* __restrict__ idx_agg,
                            const float* __restrict__ aggw) {
    int p    = blockIdx.x*8 + (threadIdx.x>>5);
    int lane = threadIdx.x & 31;
    int b    = p >> 16;
    float lx = fminf(fmaxf(loc[2*p],   -1.f), 1.f);
    float ly = fminf(fmaxf(loc[2*p+1], -1.f), 1.f);
    float fx = fminf(fmaxf(0.5f*(lx+1.f)*(float)WD - 0.5f, 0.f), (float)(WD-1));
    float fy = fminf(fmaxf(0.5f*(ly+1.f)*(float)HD - 0.5f, 0.f), (float)(HD-1));
    float x0f = floorf(fx), y0f = floorf(fy);
    float wx = fx - x0f, wy = fy - y0f;
    int x0 = (int)x0f, y0 = (int)y0f;
    int x1 = min(x0+1, WD-1), y1 = min(y0+1, HD-1);
    const float* base = g_y + (size_t)b*HD*WD*COUT;
    const float4* r00 = (const float4*)(base + (size_t)(y0*WD+x0)*COUT);
    const float4* r01 = (const float4*)(base + (size_t)(y0*WD+x1)*COUT);
    const float4* r10 = (const float4*)(base + (size_t)(y1*WD+x0)*COUT);
    const float4* r11 = (const float4*)(base + (size_t)(y1*WD+x1)*COUT);
    float w00=(1.f-wx)*(1.f-wy), w01=wx*(1.f-wy), w10=(1.f-wx)*wy, w11=wx*wy;
    float wpt = aggw[p];
    int i = idx_agg[p];
    float* dst = g_num + ((size_t)b*NN + i)*COUT;
    #pragma unroll
    for (int q = 0; q < 2; q++) {
        int c4 = q*32 + lane;
        float4 a = r00[c4], bq = r01[c4], cc = r10[c4], d = r11[c4];
        float4 f;
        f.x = (w00*a.x + w01*bq.x + w10*cc.x + w11*d.x)*wpt;
        f.y = (w00*a.y + w01*bq.y + w10*cc.y + w11*d.y)*wpt;
        f.z = (w00*a.z + w01*bq.z + w10*cc.z + w11*d.z)*wpt;
        f.w = (w00*a.w + w01*bq.w + w10*cc.w + w11*d.w)*wpt;
        red_add4(dst + c4*4, f);
    }
    if (!lane) atomicAdd(&g_den[(size_t)b*NN + i], wpt);
}

// ---- skip GEMM (x @ skip_w^T) on TF32 mma.sync, fused tok = num/(den+eps) + skip ----
#define SK_BUF   49152
#define SK_A(i)  ((i)*SK_BUF)
#define SK_B(i)  ((i)*SK_BUF + 16384)
#define SK_SMEM  (3*SK_BUF)

__device__ __forceinline__ float ldsA(const float* sA, int r, int k) {
    int kk = ((((k >> 2) ^ (r & 7)) << 2) | (k & 3));
    return sA[r*32 + kk];
}

__device__ __forceinline__ void sk_stage(uint32_t sb, int s, int buf,
                                         const float* __restrict__ xrow0, int tid) {
    int r = tid >> 2, q0 = (tid & 3) * 2;
    const float* src = xrow0 + (size_t)r*CIN + s*32;
    uint32_t dstA = sb + SK_A(buf) + r*128;
    int sw = r & 7;
    #pragma unroll
    for (int j = 0; j < 2; j++) {
        int q = q0 + j;
        cpa16(dstA + ((q ^ sw) * 16), src + q*4, 16);
    }
    const float4* bsrc = g_wSp + (size_t)s*2048 + tid*4;
    uint32_t dstB = sb + SK_B(buf) + tid*64;
    #pragma unroll
    for (int j = 0; j < 4; j++)
        cpa16(dstB + j*16, (const float*)(bsrc + j), 16);
    asm volatile("cp.async.commit_group;" ::: "memory");
}

__global__ void __launch_bounds__(512, 1) k_skip(const float* __restrict__ x) {
    extern __shared__ char smem[];
    uint32_t sb = smem_u32(smem);
    int tid = threadIdx.x, w = tid >> 5, lane = tid & 31;
    int g = lane >> 2, cl = lane & 3;
    int wm = w & 3, wn = w >> 2;
    int m0 = blockIdx.x * 128;
    const float* xrow0 = x + (size_t)m0*CIN;

    float acc[2][8][4];
    #pragma unroll
    for (int mt=0;mt<2;mt++) for (int nt=0;nt<8;nt++) for (int r2=0;r2<4;r2++) acc[mt][nt][r2]=0.f;

    sk_stage(sb, 0, 0, xrow0, tid);
    sk_stage(sb, 1, 1, xrow0, tid);

    int bufc = 0;
    for (int s = 0; s < 4; s++) {
        if (s < 3) asm volatile("cp.async.wait_group 1;" ::: "memory");
        else       asm volatile("cp.async.wait_group 0;" ::: "memory");
        __syncthreads();
        int bufn = bufc + 2; if (bufn >= 3) bufn -= 3;
        if (s + 2 < 4) sk_stage(sb, s + 2, bufn, xrow0, tid);
        const float*  sA = (const float*) (smem + SK_A(bufc));
        const float4* sB = (const float4*)(smem + SK_B(bufc));
        #pragma unroll
        for (int h2 = 0; h2 < 2; h2++) {
            float4 bv[8];
            #pragma unroll
            for (int nt = 0; nt < 8; nt++)
                bv[nt] = sB[(wn*8 + nt)*64 + h2*32 + g*4 + cl];
            #pragma unroll
            for (int hh = 0; hh < 2; hh++) {
                int kc = (h2*2 + hh)*8 + cl;
                float a[2][4];
                #pragma unroll
                for (int mt = 0; mt < 2; mt++) {
                    int r0 = wm*32 + mt*16 + g;
                    a[mt][0] = to_tf32(ldsA(sA, r0,     kc));
                    a[mt][1] = to_tf32(ldsA(sA, r0 + 8, kc));
                    a[mt][2] = to_tf32(ldsA(sA, r0,     kc + 4));
                    a[mt][3] = to_tf32(ldsA(sA, r0 + 8, kc + 4));
                }
                #pragma unroll
                for (int mt = 0; mt < 2; mt++)
                    #pragma unroll
                    for (int nt = 0; nt < 8; nt++) {
                        float b0 = hh ? bv[nt].z : bv[nt].x;
                        float b1 = hh ? bv[nt].w : bv[nt].y;
                        mma8(acc[mt][nt][0], acc[mt][nt][1], acc[mt][nt][2], acc[mt][nt][3],
                             a[mt][0], a[mt][1], a[mt][2], a[mt][3], b0, b1);
                    }
            }
        }
        bufc++; if (bufc >= 3) bufc = 0;
    }

    // epilogue: tok = acc + num * rcp(den), overwrite g_num
    #pragma unroll
    for (int mt = 0; mt < 2; mt++) {
        int r0 = wm*32 + mt*16 + g;
        int row0 = m0 + r0, row1 = row0 + 8;
        float rcp0 = 1.f/(g_den[row0] + EPSV);
        float rcp1 = 1.f/(g_den[row1] + EPSV);
        float* nb0 = g_num + (size_t)row0*COUT;
        float* nb1 = g_num + (size_t)row1*COUT;
        #pragma unroll
        for (int nt = 0; nt < 8; nt++) {
            int n = wn*64 + nt*8 + cl*2;
            float2 v0 = *(float2*)(nb0 + n);
            float2 v1 = *(float2*)(nb1 + n);
            *(float2*)(nb0 + n) = make_float2(acc[mt][nt][0] + v0.x*rcp0, acc[mt][nt][1] + v0.y*rcp0);
            *(float2*)(nb1 + n) = make_float2(acc[mt][nt][2] + v1.x*rcp1, acc[mt][nt][3] + v1.y*rcp1);
        }
    }
}

__global__ void k_bnstats() {
    int c  = threadIdx.x;
    int r0 = blockIdx.x*256;
    double s = 0.0, s2 = 0.0;
    for (int r = 0; r < 256; r++) {
        float v = g_num[(size_t)(r0 + r)*COUT + c];
        s += v; s2 += (double)v*v;
    }
    atomicAdd(&g_bnsum[c], s);
    atomicAdd(&g_bnsq[c],  s2);
}

__global__ void k_bnfinal(const float* __restrict__ gam, const float* __restrict__ bet) {
    int c = threadIdx.x;
    double m  = (double)BB*NN;
    double mu = g_bnsum[c]/m;
    double var = g_bnsq[c]/m - mu*mu;
    float sc = gam[c] * (float)(1.0/sqrt(var + 1e-5));
    g_scale[c] = sc;
    g_shift[c] = bet[c] - (float)mu*sc;
}

// apply BN on the fly: write x_out = relu(bn(tok)), conf, exp(conf). tokn NOT materialized.
__global__ void k_bnconf(const float* __restrict__ cw, const float* __restrict__ cbv,
                         float* __restrict__ out_xout, float* __restrict__ out_conf) {
    int row  = blockIdx.x*8 + (threadIdx.x>>5);
    int lane = threadIdx.x & 31;
    const float4* t  = (const float4*)(g_num  + (size_t)row*COUT);
    float4* xo       = (float4*)(out_xout + (size_t)row*COUT);
    float dot = 0.f;
    #pragma unroll
    for (int q = 0; q < 2; q++) {
        int c4 = q*32 + lane;
        float4 v  = t[c4];
        float4 sc = ((const float4*)g_scale)[c4];
        float4 sh = ((const float4*)g_shift)[c4];
        float4 w  = ((const float4*)cw)[c4];
        float4 r = make_float4(v.x*sc.x+sh.x, v.y*sc.y+sh.y, v.z*sc.z+sh.z, v.w*sc.w+sh.w);
        dot += r.x*w.x + r.y*w.y + r.z*w.z + r.w*w.w;
        xo[c4] = make_float4(fmaxf(r.x,0.f), fmaxf(r.y,0.f), fmaxf(r.z,0.f), fmaxf(r.w,0.f));
    }
    #pragma unroll
    for (int o = 16; o; o >>= 1) dot += __shfl_xor_sync(0xffffffffu, dot, o);
    if (!lane) {
        float cf = dot + cbv[0];
        out_conf[row] = cf;
        g_wexp[row]   = expf(cf);
    }
}

// gather tok from g_num, apply BN inline, weighted scatter into 64x64 cells
__global__ void k_cluster(const float* __restrict__ loc, const int* __restrict__ idx_agg,
                          float* __restrict__ out_idx) {
    int p    = blockIdx.x*8 + (threadIdx.x>>5);
    int lane = threadIdx.x & 31;
    int b    = p >> 16;
    int cell = grid_cell(loc[2*p], loc[2*p+1], HC, WC);
    int i    = idx_agg[p];
    float w  = g_wexp[(size_t)b*NN + i];
    const float4* src = (const float4*)(g_num + ((size_t)b*NN + i)*COUT);
    float* dst = g_cnum + ((size_t)b*NS + cell)*COUT;
    #pragma unroll
    for (int q = 0; q < 2; q++) {
        int c4 = q*32 + lane;
        float4 v  = src[c4];
        float4 sc = ((const float4*)g_scale)[c4];
        float4 sh = ((const float4*)g_shift)[c4];
        red_add4(dst + c4*4, make_float4((v.x*sc.x+sh.x)*w, (v.y*sc.y+sh.y)*w,
                                         (v.z*sc.z+sh.z)*w, (v.w*sc.w+sh.w)*w));
    }
    if (!lane) {
        atomicAdd(&g_cden[(size_t)b*NS + cell], w);
        g_wpt[p]   = w;
        out_idx[p] = (float)cell;
    }
}

__global__ void k_xdown(float* __restrict__ out_xd) {
    int row  = blockIdx.x*8 + (threadIdx.x>>5);
    int lane = threadIdx.x & 31;
    float rcp = 1.f/(g_cden[row] + EPSV);
    const float4* src = (const float4*)(g_cnum + (size_t)row*COUT);
    float4* dst = (float4*)(out_xd + (size_t)row*COUT);
    #pragma unroll
    for (int q = 0; q < 2; q++) {
        int c4 = q*32 + lane;
        float4 v = src[c4];
        dst[c4] = make_float4(fmaxf(v.x*rcp,0.f), fmaxf(v.y*rcp,0.f),
                              fmaxf(v.z*rcp,0.f), fmaxf(v.w*rcp,0.f));
    }
}

__global__ void k_aggmax(const float* __restrict__ loc, const float* __restrict__ aggw) {
    __shared__ float sm[256];
    int p = blockIdx.x*256 + threadIdx.x;
    int b = p >> 16;
    int cell = grid_cell(loc[2*p], loc[2*p+1], HC, WC);
    float aw = aggw[p] * g_wpt[p] / (g_cden[(size_t)b*NS + cell] + EPSV);
    g_wpt[p] = aw;
    sm[threadIdx.x] = aw;
    __syncthreads();
    for (int s = 128; s; s >>= 1) {
        if (threadIdx.x < s) sm[threadIdx.x] = fmaxf(sm[threadIdx.x], sm[threadIdx.x+s]);
        __syncthreads();
    }
    if (!threadIdx.x) atomicMax(&g_maxw[b], __float_as_uint(sm[0]));
}

__global__ void k_aggnorm(float* __restrict__ out_aw) {
    int p = blockIdx.x*256 + threadIdx.x;
    int b = p >> 16;
    out_aw[p] = g_wpt[p] / __uint_as_float(g_maxw[b]);
}

// ---------------- launch ----------------
extern "C" void kernel_launch(void* const* d_in, const int* in_sizes, int n_in,
                              void* d_out, int out_size) {
    const float* x      = (const float*)d_in[0];
    const float* loc    = (const float*)d_in[1];
    const int*   idxa   = (const int*)  d_in[2];
    const float* aggw   = (const float*)d_in[3];
    const float* conv_w = (const float*)d_in[4];
    const float* conv_b = (const float*)d_in[5];
    const float* skip_w = (const float*)d_in[6];
    const float* gamma  = (const float*)d_in[7];
    const float* beta   = (const float*)d_in[8];
    const float* conf_w = (const float*)d_in[9];
    const float* conf_b = (const float*)d_in[10];

    float* out      = (float*)d_out;
    float* out_xd   = out;                                    // [4,4096,256]
    float* out_xout = out + (size_t)BB*NS*COUT;               // [4,16384,256]
    float* out_conf = out_xout + (size_t)BB*NN*COUT;          // [4,16384,1]
    float* out_aw   = out_conf + (size_t)BB*NN;               // [4,65536,1]
    float* out_idx  = out_aw   + (size_t)BB*NP;               // [4,65536]

    cudaFuncSetAttribute(k_conv, cudaFuncAttributeMaxDynamicSharedMemorySize, CV_SMEM);
    cudaFuncSetAttribute(k_skip, cudaFuncAttributeMaxDynamicSharedMemorySize, SK_SMEM);

    k_init<<<2048, 256>>>(skip_w, conv_w);
    k_token2map<<<BB*NP/8, 256>>>(x, loc, idxa);
    k_norm<<<(BB*HH*WW*CIN/4)/256, 256>>>();
    k_conv<<<dim3(HD, 2, BB), 256, CV_SMEM>>>(conv_b);
    k_map2token<<<BB*NP/8, 256>>>(loc, idxa, aggw);
    k_skip<<<BB*NN/128, 512, SK_SMEM>>>(x);
    k_bnstats<<<BB*NN/256, 256>>>();
    k_bnfinal<<<1, 256>>>(gamma, beta);
    k_bnconf<<<BB*NN/8, 256>>>(conf_w, conf_b, out_xout, out_conf);
    k_cluster<<<BB*NP/8, 256>>>(loc, idxa, out_idx);
    k_xdown<<<BB*NS/8, 256>>>(out_xd);
    k_aggmax<<<BB*NP/256, 256>>>(loc, aggw);
    k_aggnorm<<<BB*NP/256, 256>>>(out_aw);
}

// round 13
// speedup vs baseline: 2.2240x; 1.0829x over previous
#include <cuda_runtime.h>
#include <cuda_fp16.h>
#include <math.h>
#include <stdint.h>

#define BB   4
#define NN   16384
#define CIN  128
#define COUT 256
#define HH   256
#define WW   256
#define NP   65536      // N0 = H*W points
#define HD   128
#define WD   128
#define HC   64
#define WC   64
#define NS   4096       // HC*WC
#define EPSV 1e-6f
#define KTOT 1152       // 9*CIN
#define SLABS 36        // KTOT/32

// ---------------- scratch (device globals: no allocation allowed) ----------------
__device__ float  g_ssum[(size_t)BB*HH*WW*CIN];   // token2map sum (fp32) (128MB)
__device__ float  g_cnt [(size_t)BB*HH*WW];       // token2map count
__device__ uint2  g_mapH[(size_t)BB*HH*WW*CIN/4]; // normalized fp16 map (64MB)
__device__ __half g_yH  [(size_t)BB*HD*WD*COUT];  // conv output fp16 (32MB)
__device__ uint2  g_xH  [(size_t)BB*NN*CIN/4];    // x in fp16 (16MB)
__device__ float  g_num [(size_t)BB*NN*COUT];     // map2token num -> tok (64MB)
__device__ float  g_den [(size_t)BB*NN];
__device__ float  g_wexp[(size_t)BB*NN];          // exp(conf)
__device__ double g_bnsum[COUT];
__device__ double g_bnsq [COUT];
__device__ float  g_scale[COUT];
__device__ float  g_shift[COUT];
__device__ float  g_cnum[(size_t)BB*NS*COUT];     // cluster num (16MB)
__device__ float  g_cden[(size_t)BB*NS];
__device__ float  g_wpt [(size_t)BB*NP];          // per-point weight, reused
__device__ unsigned g_maxw[BB];
__device__ uint2  g_wBh [(size_t)SLABS*2048];     // conv weights fp16 frag image per slab
__device__ uint2  g_wSh [(size_t)4*2048];         // skip weights fp16 frag image (4 slabs)

// ---------------- helpers ----------------
__device__ __forceinline__ void red_add4(float* p, float4 v) {
    asm volatile("red.global.add.v4.f32 [%0], {%1,%2,%3,%4};"
                 :: "l"(__cvta_generic_to_global(p)),
                    "f"(v.x), "f"(v.y), "f"(v.z), "f"(v.w) : "memory");
}

__device__ __forceinline__ int grid_cell(float lx, float ly, int Hg, int Wg) {
    lx = fminf(fmaxf(lx, -1.f), 1.f);
    ly = fminf(fmaxf(ly, -1.f), 1.f);
    int px = min(max(__float2int_rn(0.5f*(lx+1.f)*(float)Wg - 0.5f), 0), Wg-1);
    int py = min(max(__float2int_rn(0.5f*(ly+1.f)*(float)Hg - 0.5f), 0), Hg-1);
    return py*Wg + px;
}

__device__ __forceinline__ uint32_t packh2(float lo, float hi) {
    __half2 h = __floats2half2_rn(lo, hi);
    return *(uint32_t*)&h;
}

__device__ __forceinline__ uint32_t smem_u32(const void* p) {
    uint32_t a;
    asm("{ .reg .u64 t; cvta.to.shared.u64 t, %1; cvt.u32.u64 %0, t; }" : "=r"(a) : "l"(p));
    return a;
}

__device__ __forceinline__ void cpa16(uint32_t dst, const void* src, int srcsz) {
    asm volatile("cp.async.cg.shared.global [%0], [%1], 16, %2;"
                 :: "r"(dst), "l"(__cvta_generic_to_global(src)), "r"(srcsz) : "memory");
}

__device__ __forceinline__ void mma16(float& d0, float& d1, float& d2, float& d3,
                                      uint32_t a0, uint32_t a1, uint32_t a2, uint32_t a3,
                                      uint32_t b0, uint32_t b1) {
    asm volatile("mma.sync.aligned.m16n8k16.row.col.f32.f16.f16.f32 "
                 "{%0,%1,%2,%3},{%4,%5,%6,%7},{%8,%9},{%0,%1,%2,%3};"
                 : "+f"(d0), "+f"(d1), "+f"(d2), "+f"(d3)
                 : "r"(a0), "r"(a1), "r"(a2), "r"(a3), "r"(b0), "r"(b1));
}

__device__ __forceinline__ int aswz(int r, int c) {      // 16B-chunk swizzle
    return c ^ (r & 3) ^ ((r >> 2) & 1);
}
__device__ __forceinline__ uint32_t a_word(const char* sA, int r, int w) {  // w 0..15
    int off = r*64 + aswz(r, w >> 2)*16 + (w & 3)*4;
    return *(const uint32_t*)(sA + off);
}

// ---------------- kernels ----------------
// fused: zero accumulators + fp16 conv/skip B images + fp16 copy of x
__global__ void k_init(const float* __restrict__ x, const float* __restrict__ skw,
                       const float* __restrict__ cw) {
    size_t t = (size_t)blockIdx.x*blockDim.x + threadIdx.x;
    size_t stride = (size_t)gridDim.x*blockDim.x;
    float4 z = make_float4(0.f,0.f,0.f,0.f);
    for (size_t i=t; i < (size_t)BB*HH*WW*CIN/4; i+=stride) ((float4*)g_ssum)[i]=z;
    for (size_t i=t; i < (size_t)BB*HH*WW/4;     i+=stride) ((float4*)g_cnt )[i]=z;
    for (size_t i=t; i < (size_t)BB*NN*COUT/4;   i+=stride) ((float4*)g_num )[i]=z;
    for (size_t i=t; i < (size_t)BB*NN/4;        i+=stride) ((float4*)g_den )[i]=z;
    for (size_t i=t; i < (size_t)BB*NS*COUT/4;   i+=stride) ((float4*)g_cnum)[i]=z;
    for (size_t i=t; i < (size_t)BB*NS/4;        i+=stride) ((float4*)g_cden)[i]=z;
    for (size_t i=t; i < (size_t)BB*NN*CIN/4;    i+=stride) {
        float4 v = ((const float4*)x)[i];
        uint2 h; h.x = packh2(v.x, v.y); h.y = packh2(v.z, v.w);
        g_xH[i] = h;
    }
    if (t < COUT) { g_bnsum[t]=0.0; g_bnsq[t]=0.0; }
    if (t < BB)   g_maxw[t]=0u;
    if (t < (size_t)SLABS*2048) {
        int fi = (int)t;
        int s   = fi >> 11, r = fi & 2047;
        int nh  = r >> 10;  int r2 = r & 1023;
        int ntF = r2 >> 6, h16 = (r2 >> 5) & 1, g = (r2 >> 2) & 7, cl = r2 & 3;
        int n   = nh*128 + ntF*8 + g;
        int k0  = s*32 + h16*16 + 2*cl;
        uint2 v;
        v.x = packh2(cw[(size_t)k0*COUT + n],     cw[(size_t)(k0+1)*COUT + n]);
        v.y = packh2(cw[(size_t)(k0+8)*COUT + n], cw[(size_t)(k0+9)*COUT + n]);
        g_wBh[fi] = v;
    }
    if (t < (size_t)4*2048) {
        int fi = (int)t;
        int s   = fi >> 11, r = fi & 2047;
        int nh  = r >> 10;  int r2 = r & 1023;
        int ntF = r2 >> 6, h16 = (r2 >> 5) & 1, g = (r2 >> 2) & 7, cl = r2 & 3;
        int n   = nh*128 + ntF*8 + g;
        int k0  = s*32 + h16*16 + 2*cl;
        const float* wr = skw + (size_t)n*CIN;     // skip_w[n][k]
        uint2 v;
        v.x = packh2(wr[k0],   wr[k0+1]);
        v.y = packh2(wr[k0+8], wr[k0+9]);
        g_wSh[fi] = v;
    }
}

// scatter token features to H x W map (sum + count)
__global__ void k_token2map(const float* __restrict__ x, const float* __restrict__ loc,
                            const int* __restrict__ idx_agg) {
    int p    = blockIdx.x*8 + (threadIdx.x>>5);
    int lane = threadIdx.x & 31;
    int b    = p >> 16;
    float lx = loc[2*p], ly = loc[2*p+1];
    int cell = grid_cell(lx, ly, HH, WW);
    int i    = idx_agg[p];
    const float4* src = (const float4*)(x + ((size_t)b*NN + i)*CIN);
    float* dst = g_ssum + ((size_t)b*HH*WW + cell)*CIN;
    float4 v = src[lane];
    red_add4(dst + lane*4, v);
    if (!lane) atomicAdd(&g_cnt[(size_t)b*HH*WW + cell], 1.0f);
}

// normalize and convert to fp16 map
__global__ void k_norm() {
    size_t i = (size_t)blockIdx.x*256 + threadIdx.x;
    float rcp = 1.f/(g_cnt[i >> 5] + EPSV);
    float4 v = ((float4*)g_ssum)[i];
    uint2 h;
    h.x = packh2(v.x*rcp, v.y*rcp);
    h.y = packh2(v.z*rcp, v.w*rcp);
    g_mapH[i] = h;
}

// ---- 3x3 stride-2 conv as implicit GEMM on mma.sync FP16 (m16n8k16) ----
#define CV_BUF   16384
#define CV_A(i)  ((i)*CV_BUF)
#define CV_B(i)  ((i)*CV_BUF + 8192)
#define CV_BIAS  (3*CV_BUF)
#define CV_SMEM  (CV_BIAS + 1024)

__global__ void __launch_bounds__(256, 2) k_conv(const float* __restrict__ cb) {
    extern __shared__ char smem[];
    uint32_t sb = smem_u32(smem);
    int tid = threadIdx.x, w = tid >> 5, lane = tid & 31;
    int g = lane >> 2, cl = lane & 3;
    int wm = w & 3, wn = w >> 2;                 // warp tile 32m x 64n
    int oy = blockIdx.x, nh = blockIdx.y, b = blockIdx.z;

    if (tid < 128) *(float*)(smem + CV_BIAS + tid*4) = cb[nh*128 + tid];

    float acc[2][8][4];
    #pragma unroll
    for (int mt=0;mt<2;mt++) for (int nt=0;nt<8;nt++) for (int r2=0;r2<4;r2++) acc[mt][nt][r2]=0.f;

    auto stage = [&](int s, int buf) {
        int tap = s >> 2, cinb = (s & 3) * 32;
        int ky = tap / 3, kx = tap - 3*ky;
        int iy = 2*oy - 1 + ky;
        bool iyok = (unsigned)iy < HH;
        int r = tid >> 1, c0 = (tid & 1) * 2;
        int ix = 2*r - 1 + kx;
        bool ok = iyok && ((unsigned)ix < WW);
        const __half* src = (const __half*)g_mapH
            + ((size_t)b*HH*WW + (size_t)(iyok ? iy : 0)*WW + (ok ? ix : 0))*CIN + cinb;
        uint32_t dstA = sb + CV_A(buf) + r*64;
        int sz = ok ? 16 : 0;
        #pragma unroll
        for (int j = 0; j < 2; j++) {
            int c = c0 + j;
            cpa16(dstA + aswz(r, c)*16, src + c*8, sz);
        }
        const uint2* bsrc = g_wBh + (size_t)s*2048 + nh*1024 + tid*4;
        uint32_t dstB = sb + CV_B(buf) + tid*32;
        cpa16(dstB,      bsrc,     16);
        cpa16(dstB + 16, bsrc + 2, 16);
        asm volatile("cp.async.commit_group;" ::: "memory");
    };

    stage(0, 0);
    stage(1, 1);

    int bufc = 0;
    for (int s = 0; s < SLABS; s++) {
        if (s < SLABS-1) asm volatile("cp.async.wait_group 1;" ::: "memory");
        else             asm volatile("cp.async.wait_group 0;" ::: "memory");
        __syncthreads();
        int bufn = bufc + 2; if (bufn >= 3) bufn -= 3;
        if (s + 2 < SLABS) stage(s + 2, bufn);
        const char*  sA = smem + CV_A(bufc);
        const uint2* sB = (const uint2*)(smem + CV_B(bufc));
        #pragma unroll
        for (int h16 = 0; h16 < 2; h16++) {
            uint2 bv[8];
            #pragma unroll
            for (int nt = 0; nt < 8; nt++)
                bv[nt] = sB[(wn*8 + nt)*64 + h16*32 + g*4 + cl];
            uint32_t a[2][4];
            #pragma unroll
            for (int mt = 0; mt < 2; mt++) {
                int r0 = wm*32 + mt*16 + g;
                a[mt][0] = a_word(sA, r0,     h16*8 + cl);
                a[mt][1] = a_word(sA, r0 + 8, h16*8 + cl);
                a[mt][2] = a_word(sA, r0,     h16*8 + cl + 4);
                a[mt][3] = a_word(sA, r0 + 8, h16*8 + cl + 4);
            }
            #pragma unroll
            for (int mt = 0; mt < 2; mt++)
                #pragma unroll
                for (int nt = 0; nt < 8; nt++)
                    mma16(acc[mt][nt][0], acc[mt][nt][1], acc[mt][nt][2], acc[mt][nt][3],
                          a[mt][0], a[mt][1], a[mt][2], a[mt][3],
                          bv[nt].x, bv[nt].y);
        }
        bufc++; if (bufc >= 3) bufc = 0;
    }

    // epilogue: write fp16 y
    const float* bias = (const float*)(smem + CV_BIAS);
    __half* ybase = g_yH + (((size_t)b*HD + oy)*WD)*COUT + nh*128;
    #pragma unroll
    for (int mt = 0; mt < 2; mt++) {
        int ox0 = wm*32 + mt*16 + g;
        #pragma unroll
        for (int nt = 0; nt < 8; nt++) {
            int n = wn*64 + nt*8 + cl*2;
            float b0 = bias[n], b1 = bias[n+1];
            *(uint32_t*)(ybase + (size_t)ox0*COUT + n)     = packh2(acc[mt][nt][0]+b0, acc[mt][nt][1]+b1);
            *(uint32_t*)(ybase + (size_t)(ox0+8)*COUT + n) = packh2(acc[mt][nt][2]+b0, acc[mt][nt][3]+b1);
        }
    }
}

// bilinear gather from fp16 conv map at orig points, weighted scatter to tokens
__global__ void k_map2token(const float* __restrict__ loc, const int* __restrict__ idx_agg,
                            const float* __restrict__ aggw) {
    int p    = blockIdx.x*8 + (threadIdx.x>>5);
    int lane = threadIdx.x & 31;
    int b    = p >> 16;
    float lx = fminf(fmaxf(loc[2*p],   -1.f), 1.f);
    float ly = fminf(fmaxf(loc[2*p+1], -1.f), 1.f);
    float fx = fminf(fmaxf(0.5f*(lx+1.f)*(float)WD - 0.5f, 0.f), (float)(WD-1));
    float fy = fminf(fmaxf(0.5f*(ly+1.f)*(float)HD - 0.5f, 0.f), (float)(HD-1));
    float x0f = floorf(fx), y0f = floorf(fy);
    float wx = fx - x0f, wy = fy - y0f;
    int x0 = (int)x0f, y0 = (int)y0f;
    int x1 = min(x0+1, WD-1), y1 = min(y0+1, HD-1);
    const __half* base = g_yH + (size_t)b*HD*WD*COUT;
    const uint2* r00 = (const uint2*)(base + (size_t)(y0*WD+x0)*COUT);
    const uint2* r01 = (const uint2*)(base + (size_t)(y0*WD+x1)*COUT);
    const uint2* r10 = (const uint2*)(base + (size_t)(y1*WD+x0)*COUT);
    const uint2* r11 = (const uint2*)(base + (size_t)(y1*WD+x1)*COUT);
    float w00=(1.f-wx)*(1.f-wy), w01=wx*(1.f-wy), w10=(1.f-wx)*wy, w11=wx*wy;
    float wpt = aggw[p];
    int i = idx_agg[p];
    float* dst = g_num + ((size_t)b*NN + i)*COUT;
    #pragma unroll
    for (int q = 0; q < 2; q++) {
        int c4 = q*32 + lane;
        uint2 ua = r00[c4], ub = r01[c4], uc = r10[c4], ud = r11[c4];
        float2 a0 = __half22float2(*(__half2*)&ua.x), a1 = __half22float2(*(__half2*)&ua.y);
        float2 b0 = __half22float2(*(__half2*)&ub.x), b1 = __half22float2(*(__half2*)&ub.y);
        float2 c0 = __half22float2(*(__half2*)&uc.x), c1 = __half22float2(*(__half2*)&uc.y);
        float2 d0 = __half22float2(*(__half2*)&ud.x), d1 = __half22float2(*(__half2*)&ud.y);
        float4 f;
        f.x = (w00*a0.x + w01*b0.x + w10*c0.x + w11*d0.x)*wpt;
        f.y = (w00*a0.y + w01*b0.y + w10*c0.y + w11*d0.y)*wpt;
        f.z = (w00*a1.x + w01*b1.x + w10*c1.x + w11*d1.x)*wpt;
        f.w = (w00*a1.y + w01*b1.y + w10*c1.y + w11*d1.y)*wpt;
        red_add4(dst + c4*4, f);
    }
    if (!lane) atomicAdd(&g_den[(size_t)b*NN + i], wpt);
}

// ---- skip GEMM (x @ skip_w^T) on FP16 mma.sync, fused tok = num/(den+eps) + skip ----
// same structure as conv: CTA = 128m x 128n, 256 thr, 4 slabs, 3 buffers.
__global__ void __launch_bounds__(256, 2) k_skip() {
    extern __shared__ char smem[];
    uint32_t sb = smem_u32(smem);
    int tid = threadIdx.x, w = tid >> 5, lane = tid & 31;
    int g = lane >> 2, cl = lane & 3;
    int wm = w & 3, wn = w >> 2;
    int m0 = blockIdx.x * 128, nh = blockIdx.y;
    const __half* xrow = (const __half*)g_xH + (size_t)m0*CIN;

    float acc[2][8][4];
    #pragma unroll
    for (int mt=0;mt<2;mt++) for (int nt=0;nt<8;nt++) for (int r2=0;r2<4;r2++) acc[mt][nt][r2]=0.f;

    auto stage = [&](int s, int buf) {
        int r = tid >> 1, c0 = (tid & 1) * 2;
        const __half* src = xrow + (size_t)r*CIN + s*32;
        uint32_t dstA = sb + CV_A(buf) + r*64;
        #pragma unroll
        for (int j = 0; j < 2; j++) {
            int c = c0 + j;
            cpa16(dstA + aswz(r, c)*16, src + c*8, 16);
        }
        const uint2* bsrc = g_wSh + (size_t)s*2048 + nh*1024 + tid*4;
        uint32_t dstB = sb + CV_B(buf) + tid*32;
        cpa16(dstB,      bsrc,     16);
        cpa16(dstB + 16, bsrc + 2, 16);
        asm volatile("cp.async.commit_group;" ::: "memory");
    };

    stage(0, 0);
    stage(1, 1);

    int bufc = 0;
    for (int s = 0; s < 4; s++) {
        if (s < 3) asm volatile("cp.async.wait_group 1;" ::: "memory");
        else       asm volatile("cp.async.wait_group 0;" ::: "memory");
        __syncthreads();
        int bufn = bufc + 2; if (bufn >= 3) bufn -= 3;
        if (s + 2 < 4) stage(s + 2, bufn);
        const char*  sA = smem + CV_A(bufc);
        const uint2* sB = (const uint2*)(smem + CV_B(bufc));
        #pragma unroll
        for (int h16 = 0; h16 < 2; h16++) {
            uint2 bv[8];
            #pragma unroll
            for (int nt = 0; nt < 8; nt++)
                bv[nt] = sB[(wn*8 + nt)*64 + h16*32 + g*4 + cl];
            uint32_t a[2][4];
            #pragma unroll
            for (int mt = 0; mt < 2; mt++) {
                int r0 = wm*32 + mt*16 + g;
                a[mt][0] = a_word(sA, r0,     h16*8 + cl);
                a[mt][1] = a_word(sA, r0 + 8, h16*8 + cl);
                a[mt][2] = a_word(sA, r0,     h16*8 + cl + 4);
                a[mt][3] = a_word(sA, r0 + 8, h16*8 + cl + 4);
            }
            #pragma unroll
            for (int mt = 0; mt < 2; mt++)
                #pragma unroll
                for (int nt = 0; nt < 8; nt++)
                    mma16(acc[mt][nt][0], acc[mt][nt][1], acc[mt][nt][2], acc[mt][nt][3],
                          a[mt][0], a[mt][1], a[mt][2], a[mt][3],
                          bv[nt].x, bv[nt].y);
        }
        bufc++; if (bufc >= 3) bufc = 0;
    }

    // epilogue: tok = acc + num * rcp(den), overwrite g_num
    #pragma unroll
    for (int mt = 0; mt < 2; mt++) {
        int r0 = wm*32 + mt*16 + g;
        int row0 = m0 + r0, row1 = row0 + 8;
        float rcp0 = 1.f/(g_den[row0] + EPSV);
        float rcp1 = 1.f/(g_den[row1] + EPSV);
        float* nb0 = g_num + (size_t)row0*COUT + nh*128;
        float* nb1 = g_num + (size_t)row1*COUT + nh*128;
        #pragma unroll
        for (int nt = 0; nt < 8; nt++) {
            int n = wn*64 + nt*8 + cl*2;
            float2 v0 = *(float2*)(nb0 + n);
            float2 v1 = *(float2*)(nb1 + n);
            *(float2*)(nb0 + n) = make_float2(acc[mt][nt][0] + v0.x*rcp0, acc[mt][nt][1] + v0.y*rcp0);
            *(float2*)(nb1 + n) = make_float2(acc[mt][nt][2] + v1.x*rcp1, acc[mt][nt][3] + v1.y*rcp1);
        }
    }
}

__global__ void k_bnstats() {
    int c  = threadIdx.x;
    int r0 = blockIdx.x*256;
    double s = 0.0, s2 = 0.0;
    for (int r = 0; r < 256; r++) {
        float v = g_num[(size_t)(r0 + r)*COUT + c];
        s += v; s2 += (double)v*v;
    }
    atomicAdd(&g_bnsum[c], s);
    atomicAdd(&g_bnsq[c],  s2);
}

__global__ void k_bnfinal(const float* __restrict__ gam, const float* __restrict__ bet) {
    int c = threadIdx.x;
    double m  = (double)BB*NN;
    double mu = g_bnsum[c]/m;
    double var = g_bnsq[c]/m - mu*mu;
    float sc = gam[c] * (float)(1.0/sqrt(var + 1e-5));
    g_scale[c] = sc;
    g_shift[c] = bet[c] - (float)mu*sc;
}

// apply BN on the fly: write x_out = relu(bn(tok)), conf, exp(conf)
__global__ void k_bnconf(const float* __restrict__ cw, const float* __restrict__ cbv,
                         float* __restrict__ out_xout, float* __restrict__ out_conf) {
    int row  = blockIdx.x*8 + (threadIdx.x>>5);
    int lane = threadIdx.x & 31;
    const float4* t  = (const float4*)(g_num  + (size_t)row*COUT);
    float4* xo       = (float4*)(out_xout + (size_t)row*COUT);
    float dot = 0.f;
    #pragma unroll
    for (int q = 0; q < 2; q++) {
        int c4 = q*32 + lane;
        float4 v  = t[c4];
        float4 sc = ((const float4*)g_scale)[c4];
        float4 sh = ((const float4*)g_shift)[c4];
        float4 w  = ((const float4*)cw)[c4];
        float4 r = make_float4(v.x*sc.x+sh.x, v.y*sc.y+sh.y, v.z*sc.z+sh.z, v.w*sc.w+sh.w);
        dot += r.x*w.x + r.y*w.y + r.z*w.z + r.w*w.w;
        xo[c4] = make_float4(fmaxf(r.x,0.f), fmaxf(r.y,0.f), fmaxf(r.z,0.f), fmaxf(r.w,0.f));
    }
    #pragma unroll
    for (int o = 16; o; o >>= 1) dot += __shfl_xor_sync(0xffffffffu, dot, o);
    if (!lane) {
        float cf = dot + cbv[0];
        out_conf[row] = cf;
        g_wexp[row]   = expf(cf);
    }
}

// gather tok from g_num, apply BN inline, weighted scatter into 64x64 cells
__global__ void k_cluster(const float* __restrict__ loc, const int* __restrict__ idx_agg,
                          float* __restrict__ out_idx) {
    int p    = blockIdx.x*8 + (threadIdx.x>>5);
    int lane = threadIdx.x & 31;
    int b    = p >> 16;
    int cell = grid_cell(loc[2*p], loc[2*p+1], HC, WC);
    int i    = idx_agg[p];
    float w  = g_wexp[(size_t)b*NN + i];
    const float4* src = (const float4*)(g_num + ((size_t)b*NN + i)*COUT);
    float* dst = g_cnum + ((size_t)b*NS + cell)*COUT;
    #pragma unroll
    for (int q = 0; q < 2; q++) {
        int c4 = q*32 + lane;
        float4 v  = src[c4];
        float4 sc = ((const float4*)g_scale)[c4];
        float4 sh = ((const float4*)g_shift)[c4];
        red_add4(dst + c4*4, make_float4((v.x*sc.x+sh.x)*w, (v.y*sc.y+sh.y)*w,
                                         (v.z*sc.z+sh.z)*w, (v.w*sc.w+sh.w)*w));
    }
    if (!lane) {
        atomicAdd(&g_cden[(size_t)b*NS + cell], w);
        g_wpt[p]   = w;
        out_idx[p] = (float)cell;
    }
}

__global__ void k_xdown(float* __restrict__ out_xd) {
    int row  = blockIdx.x*8 + (threadIdx.x>>5);
    int lane = threadIdx.x & 31;
    float rcp = 1.f/(g_cden[row] + EPSV);
    const float4* src = (const float4*)(g_cnum + (size_t)row*COUT);
    float4* dst = (float4*)(out_xd + (size_t)row*COUT);
    #pragma unroll
    for (int q = 0; q < 2; q++) {
        int c4 = q*32 + lane;
        float4 v = src[c4];
        dst[c4] = make_float4(fmaxf(v.x*rcp,0.f), fmaxf(v.y*rcp,0.f),
                              fmaxf(v.z*rcp,0.f), fmaxf(v.w*rcp,0.f));
    }
}

__global__ void k_aggmax(const float* __restrict__ loc, const float* __restrict__ aggw) {
    __shared__ float sm[256];
    int p = blockIdx.x*256 + threadIdx.x;
    int b = p >> 16;
    int cell = grid_cell(loc[2*p], loc[2*p+1], HC, WC);
    float aw = aggw[p] * g_wpt[p] / (g_cden[(size_t)b*NS + cell] + EPSV);
    g_wpt[p] = aw;
    sm[threadIdx.x] = aw;
    __syncthreads();
    for (int s = 128; s; s >>= 1) {
        if (threadIdx.x < s) sm[threadIdx.x] = fmaxf(sm[threadIdx.x], sm[threadIdx.x+s]);
        __syncthreads();
    }
    if (!threadIdx.x) atomicMax(&g_maxw[b], __float_as_uint(sm[0]));
}

__global__ void k_aggnorm(float* __restrict__ out_aw) {
    int p = blockIdx.x*256 + threadIdx.x;
    int b = p >> 16;
    out_aw[p] = g_wpt[p] / __uint_as_float(g_maxw[b]);
}

// ---------------- launch ----------------
extern "C" void kernel_launch(void* const* d_in, const int* in_sizes, int n_in,
                              void* d_out, int out_size) {
    const float* x      = (const float*)d_in[0];
    const float* loc    = (const float*)d_in[1];
    const int*   idxa   = (const int*)  d_in[2];
    const float* aggw   = (const float*)d_in[3];
    const float* conv_w = (const float*)d_in[4];
    const float* conv_b = (const float*)d_in[5];
    const float* skip_w = (const float*)d_in[6];
    const float* gamma  = (const float*)d_in[7];
    const float* beta   = (const float*)d_in[8];
    const float* conf_w = (const float*)d_in[9];
    const float* conf_b = (const float*)d_in[10];

    float* out      = (float*)d_out;
    float* out_xd   = out;                                    // [4,4096,256]
    float* out_xout = out + (size_t)BB*NS*COUT;               // [4,16384,256]
    float* out_conf = out_xout + (size_t)BB*NN*COUT;          // [4,16384,1]
    float* out_aw   = out_conf + (size_t)BB*NN;               // [4,65536,1]
    float* out_idx  = out_aw   + (size_t)BB*NP;               // [4,65536]

    cudaFuncSetAttribute(k_conv, cudaFuncAttributeMaxDynamicSharedMemorySize, CV_SMEM);
    cudaFuncSetAttribute(k_skip, cudaFuncAttributeMaxDynamicSharedMemorySize, CV_SMEM);

    k_init<<<2048, 256>>>(x, skip_w, conv_w);
    k_token2map<<<BB*NP/8, 256>>>(x, loc, idxa);
    k_norm<<<(BB*HH*WW*CIN/4)/256, 256>>>();
    k_conv<<<dim3(HD, 2, BB), 256, CV_SMEM>>>(conv_b);
    k_map2token<<<BB*NP/8, 256>>>(loc, idxa, aggw);
    k_skip<<<dim3(BB*NN/128, 2), 256, CV_SMEM>>>();
    k_bnstats<<<BB*NN/256, 256>>>();
    k_bnfinal<<<1, 256>>>(gamma, beta);
    k_bnconf<<<BB*NN/8, 256>>>(conf_w, conf_b, out_xout, out_conf);
    k_cluster<<<BB*NP/8, 256>>>(loc, idxa, out_idx);
    k_xdown<<<BB*NS/8, 256>>>(out_xd);
    k_aggmax<<<BB*NP/256, 256>>>(loc, aggw);
    k_aggnorm<<<BB*NP/256, 256>>>(out_aw);
}

// round 14
// speedup vs baseline: 2.3418x; 1.0530x over previous
#include <cuda_runtime.h>
#include <cuda_fp16.h>
#include <math.h>
#include <stdint.h>

#define BB   4
#define NN   16384
#define CIN  128
#define COUT 256
#define HH   256
#define WW   256
#define NP   65536      // N0 = H*W points
#define HD   128
#define WD   128
#define HC   64
#define WC   64
#define NS   4096       // HC*WC
#define EPSV 1e-6f
#define KTOT 1152       // 9*CIN
#define SLABS 36        // KTOT/32

// ---------------- scratch (device globals: no allocation allowed) ----------------
__device__ float  g_ssum[(size_t)BB*HH*WW*CIN];   // token2map sum (fp32) (128MB)
__device__ float  g_cnt [(size_t)BB*HH*WW];       // token2map count
__device__ uint2  g_mapH[(size_t)BB*HH*WW*CIN/4]; // normalized fp16 map (64MB)
__device__ __half g_yH  [(size_t)BB*HD*WD*COUT];  // conv output fp16 (32MB)
__device__ uint2  g_xH  [(size_t)BB*NN*CIN/4];    // x in fp16 (16MB)
__device__ float  g_num [(size_t)BB*NN*COUT];     // map2token num -> tok (64MB)
__device__ float  g_den [(size_t)BB*NN];
__device__ float  g_wexp[(size_t)BB*NN];          // exp(conf)
__device__ float  g_bnsumF[COUT];
__device__ float  g_bnsqF [COUT];
__device__ float  g_scale[COUT];
__device__ float  g_shift[COUT];
__device__ float  g_cnum[(size_t)BB*NS*COUT];     // cluster num (16MB)
__device__ float  g_cden[(size_t)BB*NS];
__device__ float  g_wpt [(size_t)BB*NP];          // per-point weight, reused
__device__ unsigned g_maxw[BB];
__device__ uint2  g_wBh [(size_t)SLABS*2048];     // conv weights fp16 frag image per slab
__device__ uint2  g_wSh [(size_t)4*2048];         // skip weights fp16 frag image (4 slabs)

// ---------------- helpers ----------------
__device__ __forceinline__ void red_add4(float* p, float4 v) {
    asm volatile("red.global.add.v4.f32 [%0], {%1,%2,%3,%4};"
                 :: "l"(__cvta_generic_to_global(p)),
                    "f"(v.x), "f"(v.y), "f"(v.z), "f"(v.w) : "memory");
}

__device__ __forceinline__ int grid_cell(float lx, float ly, int Hg, int Wg) {
    lx = fminf(fmaxf(lx, -1.f), 1.f);
    ly = fminf(fmaxf(ly, -1.f), 1.f);
    int px = min(max(__float2int_rn(0.5f*(lx+1.f)*(float)Wg - 0.5f), 0), Wg-1);
    int py = min(max(__float2int_rn(0.5f*(ly+1.f)*(float)Hg - 0.5f), 0), Hg-1);
    return py*Wg + px;
}

__device__ __forceinline__ uint32_t packh2(float lo, float hi) {
    __half2 h = __floats2half2_rn(lo, hi);
    return *(uint32_t*)&h;
}

__device__ __forceinline__ uint32_t smem_u32(const void* p) {
    uint32_t a;
    asm("{ .reg .u64 t; cvta.to.shared.u64 t, %1; cvt.u32.u64 %0, t; }" : "=r"(a) : "l"(p));
    return a;
}

__device__ __forceinline__ void cpa16(uint32_t dst, const void* src, int srcsz) {
    asm volatile("cp.async.cg.shared.global [%0], [%1], 16, %2;"
                 :: "r"(dst), "l"(__cvta_generic_to_global(src)), "r"(srcsz) : "memory");
}

__device__ __forceinline__ void mma16(float& d0, float& d1, float& d2, float& d3,
                                      uint32_t a0, uint32_t a1, uint32_t a2, uint32_t a3,
                                      uint32_t b0, uint32_t b1) {
    asm volatile("mma.sync.aligned.m16n8k16.row.col.f32.f16.f16.f32 "
                 "{%0,%1,%2,%3},{%4,%5,%6,%7},{%8,%9},{%0,%1,%2,%3};"
                 : "+f"(d0), "+f"(d1), "+f"(d2), "+f"(d3)
                 : "r"(a0), "r"(a1), "r"(a2), "r"(a3), "r"(b0), "r"(b1));
}

__device__ __forceinline__ int aswz(int r, int c) {      // 16B-chunk swizzle
    return c ^ (r & 3) ^ ((r >> 2) & 1);
}
__device__ __forceinline__ uint32_t a_word(const char* sA, int r, int w) {  // w 0..15
    int off = r*64 + aswz(r, w >> 2)*16 + (w & 3)*4;
    return *(const uint32_t*)(sA + off);
}

// ---------------- kernels ----------------
// fused: zero accumulators + fp16 conv/skip B images + fp16 copy of x
__global__ void k_init(const float* __restrict__ x, const float* __restrict__ skw,
                       const float* __restrict__ cw) {
    size_t t = (size_t)blockIdx.x*blockDim.x + threadIdx.x;
    size_t stride = (size_t)gridDim.x*blockDim.x;
    float4 z = make_float4(0.f,0.f,0.f,0.f);
    for (size_t i=t; i < (size_t)BB*HH*WW*CIN/4; i+=stride) ((float4*)g_ssum)[i]=z;
    for (size_t i=t; i < (size_t)BB*HH*WW/4;     i+=stride) ((float4*)g_cnt )[i]=z;
    for (size_t i=t; i < (size_t)BB*NN*COUT/4;   i+=stride) ((float4*)g_num )[i]=z;
    for (size_t i=t; i < (size_t)BB*NN/4;        i+=stride) ((float4*)g_den )[i]=z;
    for (size_t i=t; i < (size_t)BB*NS*COUT/4;   i+=stride) ((float4*)g_cnum)[i]=z;
    for (size_t i=t; i < (size_t)BB*NS/4;        i+=stride) ((float4*)g_cden)[i]=z;
    for (size_t i=t; i < (size_t)BB*NN*CIN/4;    i+=stride) {
        float4 v = ((const float4*)x)[i];
        uint2 h; h.x = packh2(v.x, v.y); h.y = packh2(v.z, v.w);
        g_xH[i] = h;
    }
    if (t < COUT) { g_bnsumF[t]=0.f; g_bnsqF[t]=0.f; }
    if (t < BB)   g_maxw[t]=0u;
    if (t < (size_t)SLABS*2048) {
        int fi = (int)t;
        int s   = fi >> 11, r = fi & 2047;
        int nh  = r >> 10;  int r2 = r & 1023;
        int ntF = r2 >> 6, h16 = (r2 >> 5) & 1, g = (r2 >> 2) & 7, cl = r2 & 3;
        int n   = nh*128 + ntF*8 + g;
        int k0  = s*32 + h16*16 + 2*cl;
        uint2 v;
        v.x = packh2(cw[(size_t)k0*COUT + n],     cw[(size_t)(k0+1)*COUT + n]);
        v.y = packh2(cw[(size_t)(k0+8)*COUT + n], cw[(size_t)(k0+9)*COUT + n]);
        g_wBh[fi] = v;
    }
    if (t < (size_t)4*2048) {
        int fi = (int)t;
        int s   = fi >> 11, r = fi & 2047;
        int nh  = r >> 10;  int r2 = r & 1023;
        int ntF = r2 >> 6, h16 = (r2 >> 5) & 1, g = (r2 >> 2) & 7, cl = r2 & 3;
        int n   = nh*128 + ntF*8 + g;
        int k0  = s*32 + h16*16 + 2*cl;
        const float* wr = skw + (size_t)n*CIN;     // skip_w[n][k]
        uint2 v;
        v.x = packh2(wr[k0],   wr[k0+1]);
        v.y = packh2(wr[k0+8], wr[k0+9]);
        g_wSh[fi] = v;
    }
}

// scatter token features to H x W map (sum + count)
__global__ void k_token2map(const float* __restrict__ x, const float* __restrict__ loc,
                            const int* __restrict__ idx_agg) {
    int p    = blockIdx.x*8 + (threadIdx.x>>5);
    int lane = threadIdx.x & 31;
    int b    = p >> 16;
    float lx = loc[2*p], ly = loc[2*p+1];
    int cell = grid_cell(lx, ly, HH, WW);
    int i    = idx_agg[p];
    const float4* src = (const float4*)(x + ((size_t)b*NN + i)*CIN);
    float* dst = g_ssum + ((size_t)b*HH*WW + cell)*CIN;
    float4 v = src[lane];
    red_add4(dst + lane*4, v);
    if (!lane) atomicAdd(&g_cnt[(size_t)b*HH*WW + cell], 1.0f);
}

// normalize and convert to fp16 map
__global__ void k_norm() {
    size_t i = (size_t)blockIdx.x*256 + threadIdx.x;
    float rcp = 1.f/(g_cnt[i >> 5] + EPSV);
    float4 v = ((float4*)g_ssum)[i];
    uint2 h;
    h.x = packh2(v.x*rcp, v.y*rcp);
    h.y = packh2(v.z*rcp, v.w*rcp);
    g_mapH[i] = h;
}

// ---- 3x3 stride-2 conv as implicit GEMM on mma.sync FP16 (m16n8k16) ----
#define CV_BUF   16384
#define CV_A(i)  ((i)*CV_BUF)
#define CV_B(i)  ((i)*CV_BUF + 8192)
#define CV_BIAS  (3*CV_BUF)
#define CV_SMEM  (CV_BIAS + 1024)

__global__ void __launch_bounds__(256, 2) k_conv(const float* __restrict__ cb) {
    extern __shared__ char smem[];
    uint32_t sb = smem_u32(smem);
    int tid = threadIdx.x, w = tid >> 5, lane = tid & 31;
    int g = lane >> 2, cl = lane & 3;
    int wm = w & 3, wn = w >> 2;                 // warp tile 32m x 64n
    int oy = blockIdx.x, nh = blockIdx.y, b = blockIdx.z;

    if (tid < 128) *(float*)(smem + CV_BIAS + tid*4) = cb[nh*128 + tid];

    float acc[2][8][4];
    #pragma unroll
    for (int mt=0;mt<2;mt++) for (int nt=0;nt<8;nt++) for (int r2=0;r2<4;r2++) acc[mt][nt][r2]=0.f;

    auto stage = [&](int s, int buf) {
        int tap = s >> 2, cinb = (s & 3) * 32;
        int ky = tap / 3, kx = tap - 3*ky;
        int iy = 2*oy - 1 + ky;
        bool iyok = (unsigned)iy < HH;
        int r = tid >> 1, c0 = (tid & 1) * 2;
        int ix = 2*r - 1 + kx;
        bool ok = iyok && ((unsigned)ix < WW);
        const __half* src = (const __half*)g_mapH
            + ((size_t)b*HH*WW + (size_t)(iyok ? iy : 0)*WW + (ok ? ix : 0))*CIN + cinb;
        uint32_t dstA = sb + CV_A(buf) + r*64;
        int sz = ok ? 16 : 0;
        #pragma unroll
        for (int j = 0; j < 2; j++) {
            int c = c0 + j;
            cpa16(dstA + aswz(r, c)*16, src + c*8, sz);
        }
        const uint2* bsrc = g_wBh + (size_t)s*2048 + nh*1024 + tid*4;
        uint32_t dstB = sb + CV_B(buf) + tid*32;
        cpa16(dstB,      bsrc,     16);
        cpa16(dstB + 16, bsrc + 2, 16);
        asm volatile("cp.async.commit_group;" ::: "memory");
    };

    stage(0, 0);
    stage(1, 1);

    int bufc = 0;
    for (int s = 0; s < SLABS; s++) {
        if (s < SLABS-1) asm volatile("cp.async.wait_group 1;" ::: "memory");
        else             asm volatile("cp.async.wait_group 0;" ::: "memory");
        __syncthreads();
        int bufn = bufc + 2; if (bufn >= 3) bufn -= 3;
        if (s + 2 < SLABS) stage(s + 2, bufn);
        const char*  sA = smem + CV_A(bufc);
        const uint2* sB = (const uint2*)(smem + CV_B(bufc));
        #pragma unroll
        for (int h16 = 0; h16 < 2; h16++) {
            uint2 bv[8];
            #pragma unroll
            for (int nt = 0; nt < 8; nt++)
                bv[nt] = sB[(wn*8 + nt)*64 + h16*32 + g*4 + cl];
            uint32_t a[2][4];
            #pragma unroll
            for (int mt = 0; mt < 2; mt++) {
                int r0 = wm*32 + mt*16 + g;
                a[mt][0] = a_word(sA, r0,     h16*8 + cl);
                a[mt][1] = a_word(sA, r0 + 8, h16*8 + cl);
                a[mt][2] = a_word(sA, r0,     h16*8 + cl + 4);
                a[mt][3] = a_word(sA, r0 + 8, h16*8 + cl + 4);
            }
            #pragma unroll
            for (int mt = 0; mt < 2; mt++)
                #pragma unroll
                for (int nt = 0; nt < 8; nt++)
                    mma16(acc[mt][nt][0], acc[mt][nt][1], acc[mt][nt][2], acc[mt][nt][3],
                          a[mt][0], a[mt][1], a[mt][2], a[mt][3],
                          bv[nt].x, bv[nt].y);
        }
        bufc++; if (bufc >= 3) bufc = 0;
    }

    // epilogue: write fp16 y
    const float* bias = (const float*)(smem + CV_BIAS);
    __half* ybase = g_yH + (((size_t)b*HD + oy)*WD)*COUT + nh*128;
    #pragma unroll
    for (int mt = 0; mt < 2; mt++) {
        int ox0 = wm*32 + mt*16 + g;
        #pragma unroll
        for (int nt = 0; nt < 8; nt++) {
            int n = wn*64 + nt*8 + cl*2;
            float b0 = bias[n], b1 = bias[n+1];
            *(uint32_t*)(ybase + (size_t)ox0*COUT + n)     = packh2(acc[mt][nt][0]+b0, acc[mt][nt][1]+b1);
            *(uint32_t*)(ybase + (size_t)(ox0+8)*COUT + n) = packh2(acc[mt][nt][2]+b0, acc[mt][nt][3]+b1);
        }
    }
}

// bilinear gather from fp16 conv map at orig points, weighted scatter to tokens
__global__ void k_map2token(const float* __restrict__ loc, const int* __restrict__ idx_agg,
                            const float* __restrict__ aggw) {
    int p    = blockIdx.x*8 + (threadIdx.x>>5);
    int lane = threadIdx.x & 31;
    int b    = p >> 16;
    float lx = fminf(fmaxf(loc[2*p],   -1.f), 1.f);
    float ly = fminf(fmaxf(loc[2*p+1], -1.f), 1.f);
    float fx = fminf(fmaxf(0.5f*(lx+1.f)*(float)WD - 0.5f, 0.f), (float)(WD-1));
    float fy = fminf(fmaxf(0.5f*(ly+1.f)*(float)HD - 0.5f, 0.f), (float)(HD-1));
    float x0f = floorf(fx), y0f = floorf(fy);
    float wx = fx - x0f, wy = fy - y0f;
    int x0 = (int)x0f, y0 = (int)y0f;
    int x1 = min(x0+1, WD-1), y1 = min(y0+1, HD-1);
    const __half* base = g_yH + (size_t)b*HD*WD*COUT;
    const uint4* r00 = (const uint4*)(base + (size_t)(y0*WD+x0)*COUT);
    const uint4* r01 = (const uint4*)(base + (size_t)(y0*WD+x1)*COUT);
    const uint4* r10 = (const uint4*)(base + (size_t)(y1*WD+x0)*COUT);
    const uint4* r11 = (const uint4*)(base + (size_t)(y1*WD+x1)*COUT);
    float w00=(1.f-wx)*(1.f-wy), w01=wx*(1.f-wy), w10=(1.f-wx)*wy, w11=wx*wy;
    float wpt = aggw[p];
    int i = idx_agg[p];
    float* dst = g_num + ((size_t)b*NN + i)*COUT + lane*8;
    uint4 ua = r00[lane], ub = r01[lane], uc = r10[lane], ud = r11[lane];
    const uint32_t* pa = (const uint32_t*)&ua;
    const uint32_t* pb = (const uint32_t*)&ub;
    const uint32_t* pc = (const uint32_t*)&uc;
    const uint32_t* pd = (const uint32_t*)&ud;
    #pragma unroll
    for (int q = 0; q < 2; q++) {
        float2 a0 = __half22float2(*(__half2*)&pa[2*q]),   a1 = __half22float2(*(__half2*)&pa[2*q+1]);
        float2 b0 = __half22float2(*(__half2*)&pb[2*q]),   b1 = __half22float2(*(__half2*)&pb[2*q+1]);
        float2 c0 = __half22float2(*(__half2*)&pc[2*q]),   c1 = __half22float2(*(__half2*)&pc[2*q+1]);
        float2 d0 = __half22float2(*(__half2*)&pd[2*q]),   d1 = __half22float2(*(__half2*)&pd[2*q+1]);
        float4 f;
        f.x = (w00*a0.x + w01*b0.x + w10*c0.x + w11*d0.x)*wpt;
        f.y = (w00*a0.y + w01*b0.y + w10*c0.y + w11*d0.y)*wpt;
        f.z = (w00*a1.x + w01*b1.x + w10*c1.x + w11*d1.x)*wpt;
        f.w = (w00*a1.y + w01*b1.y + w10*c1.y + w11*d1.y)*wpt;
        red_add4(dst + q*4, f);
    }
    if (!lane) atomicAdd(&g_den[(size_t)b*NN + i], wpt);
}

// ---- skip GEMM (x @ skip_w^T) on FP16 mma.sync + fused BN partial stats ----
__global__ void __launch_bounds__(256, 2) k_skip() {
    extern __shared__ char smem[];
    uint32_t sb = smem_u32(smem);
    int tid = threadIdx.x, w = tid >> 5, lane = tid & 31;
    int g = lane >> 2, cl = lane & 3;
    int wm = w & 3, wn = w >> 2;
    int m0 = blockIdx.x * 128, nh = blockIdx.y;
    const __half* xrow = (const __half*)g_xH + (size_t)m0*CIN;
    float* s_sum = (float*)(smem + CV_BIAS);        // [128]
    float* s_sq  = (float*)(smem + CV_BIAS + 512);  // [128]

    if (tid < 256) *(float*)(smem + CV_BIAS + tid*4) = 0.f;

    float acc[2][8][4];
    #pragma unroll
    for (int mt=0;mt<2;mt++) for (int nt=0;nt<8;nt++) for (int r2=0;r2<4;r2++) acc[mt][nt][r2]=0.f;

    auto stage = [&](int s, int buf) {
        int r = tid >> 1, c0 = (tid & 1) * 2;
        const __half* src = xrow + (size_t)r*CIN + s*32;
        uint32_t dstA = sb + CV_A(buf) + r*64;
        #pragma unroll
        for (int j = 0; j < 2; j++) {
            int c = c0 + j;
            cpa16(dstA + aswz(r, c)*16, src + c*8, 16);
        }
        const uint2* bsrc = g_wSh + (size_t)s*2048 + nh*1024 + tid*4;
        uint32_t dstB = sb + CV_B(buf) + tid*32;
        cpa16(dstB,      bsrc,     16);
        cpa16(dstB + 16, bsrc + 2, 16);
        asm volatile("cp.async.commit_group;" ::: "memory");
    };

    stage(0, 0);
    stage(1, 1);

    int bufc = 0;
    for (int s = 0; s < 4; s++) {
        if (s < 3) asm volatile("cp.async.wait_group 1;" ::: "memory");
        else       asm volatile("cp.async.wait_group 0;" ::: "memory");
        __syncthreads();
        int bufn = bufc + 2; if (bufn >= 3) bufn -= 3;
        if (s + 2 < 4) stage(s + 2, bufn);
        const char*  sA = smem + CV_A(bufc);
        const uint2* sB = (const uint2*)(smem + CV_B(bufc));
        #pragma unroll
        for (int h16 = 0; h16 < 2; h16++) {
            uint2 bv[8];
            #pragma unroll
            for (int nt = 0; nt < 8; nt++)
                bv[nt] = sB[(wn*8 + nt)*64 + h16*32 + g*4 + cl];
            uint32_t a[2][4];
            #pragma unroll
            for (int mt = 0; mt < 2; mt++) {
                int r0 = wm*32 + mt*16 + g;
                a[mt][0] = a_word(sA, r0,     h16*8 + cl);
                a[mt][1] = a_word(sA, r0 + 8, h16*8 + cl);
                a[mt][2] = a_word(sA, r0,     h16*8 + cl + 4);
                a[mt][3] = a_word(sA, r0 + 8, h16*8 + cl + 4);
            }
            #pragma unroll
            for (int mt = 0; mt < 2; mt++)
                #pragma unroll
                for (int nt = 0; nt < 8; nt++)
                    mma16(acc[mt][nt][0], acc[mt][nt][1], acc[mt][nt][2], acc[mt][nt][3],
                          a[mt][0], a[mt][1], a[mt][2], a[mt][3],
                          bv[nt].x, bv[nt].y);
        }
        bufc++; if (bufc >= 3) bufc = 0;
    }

    // epilogue: tok = acc + num*rcp(den) -> g_num, plus per-channel partial stats
    float rcp[2][2];
    float* nb[2][2];
    #pragma unroll
    for (int mt = 0; mt < 2; mt++) {
        int r0 = wm*32 + mt*16 + g;
        int row0 = m0 + r0, row1 = row0 + 8;
        rcp[mt][0] = 1.f/(g_den[row0] + EPSV);
        rcp[mt][1] = 1.f/(g_den[row1] + EPSV);
        nb[mt][0] = g_num + (size_t)row0*COUT + nh*128;
        nb[mt][1] = g_num + (size_t)row1*COUT + nh*128;
    }
    #pragma unroll
    for (int nt = 0; nt < 8; nt++) {
        int n = wn*64 + nt*8 + cl*2;
        float s0=0.f, s1=0.f, q0=0.f, q1=0.f;
        #pragma unroll
        for (int mt = 0; mt < 2; mt++) {
            float2 v0 = *(float2*)(nb[mt][0] + n);
            float2 v1 = *(float2*)(nb[mt][1] + n);
            float t0 = acc[mt][nt][0] + v0.x*rcp[mt][0];
            float t1 = acc[mt][nt][1] + v0.y*rcp[mt][0];
            float t2 = acc[mt][nt][2] + v1.x*rcp[mt][1];
            float t3 = acc[mt][nt][3] + v1.y*rcp[mt][1];
            *(float2*)(nb[mt][0] + n) = make_float2(t0, t1);
            *(float2*)(nb[mt][1] + n) = make_float2(t2, t3);
            s0 += t0 + t2; s1 += t1 + t3;
            q0 += t0*t0 + t2*t2; q1 += t1*t1 + t3*t3;
        }
        atomicAdd(&s_sum[n],   s0);
        atomicAdd(&s_sum[n+1], s1);
        atomicAdd(&s_sq[n],    q0);
        atomicAdd(&s_sq[n+1],  q1);
    }
    __syncthreads();
    if (tid < 128) {
        atomicAdd(&g_bnsumF[nh*128 + tid], s_sum[tid]);
        atomicAdd(&g_bnsqF [nh*128 + tid], s_sq[tid]);
    }
}

__global__ void k_bnfinal(const float* __restrict__ gam, const float* __restrict__ bet) {
    int c = threadIdx.x;
    float m  = (float)(BB*NN);
    float mu = g_bnsumF[c]/m;
    float var = g_bnsqF[c]/m - mu*mu;
    float sc = gam[c] * rsqrtf(var + 1e-5f);
    g_scale[c] = sc;
    g_shift[c] = bet[c] - mu*sc;
}

// apply BN on the fly: write x_out = relu(bn(tok)), conf, exp(conf)
__global__ void k_bnconf(const float* __restrict__ cw, const float* __restrict__ cbv,
                         float* __restrict__ out_xout, float* __restrict__ out_conf) {
    int row  = blockIdx.x*8 + (threadIdx.x>>5);
    int lane = threadIdx.x & 31;
    const float4* t  = (const float4*)(g_num  + (size_t)row*COUT);
    float4* xo       = (float4*)(out_xout + (size_t)row*COUT);
    float dot = 0.f;
    #pragma unroll
    for (int q = 0; q < 2; q++) {
        int c4 = q*32 + lane;
        float4 v  = t[c4];
        float4 sc = ((const float4*)g_scale)[c4];
        float4 sh = ((const float4*)g_shift)[c4];
        float4 w  = ((const float4*)cw)[c4];
        float4 r = make_float4(v.x*sc.x+sh.x, v.y*sc.y+sh.y, v.z*sc.z+sh.z, v.w*sc.w+sh.w);
        dot += r.x*w.x + r.y*w.y + r.z*w.z + r.w*w.w;
        xo[c4] = make_float4(fmaxf(r.x,0.f), fmaxf(r.y,0.f), fmaxf(r.z,0.f), fmaxf(r.w,0.f));
    }
    #pragma unroll
    for (int o = 16; o; o >>= 1) dot += __shfl_xor_sync(0xffffffffu, dot, o);
    if (!lane) {
        float cf = dot + cbv[0];
        out_conf[row] = cf;
        g_wexp[row]   = expf(cf);
    }
}

// gather tok from g_num, apply BN inline, weighted scatter into 64x64 cells
__global__ void k_cluster(const float* __restrict__ loc, const int* __restrict__ idx_agg,
                          float* __restrict__ out_idx) {
    int p    = blockIdx.x*8 + (threadIdx.x>>5);
    int lane = threadIdx.x & 31;
    int b    = p >> 16;
    int cell = grid_cell(loc[2*p], loc[2*p+1], HC, WC);
    int i    = idx_agg[p];
    float w  = g_wexp[(size_t)b*NN + i];
    const float4* src = (const float4*)(g_num + ((size_t)b*NN + i)*COUT);
    float* dst = g_cnum + ((size_t)b*NS + cell)*COUT;
    #pragma unroll
    for (int q = 0; q < 2; q++) {
        int c4 = q*32 + lane;
        float4 v  = src[c4];
        float4 sc = ((const float4*)g_scale)[c4];
        float4 sh = ((const float4*)g_shift)[c4];
        red_add4(dst + c4*4, make_float4((v.x*sc.x+sh.x)*w, (v.y*sc.y+sh.y)*w,
                                         (v.z*sc.z+sh.z)*w, (v.w*sc.w+sh.w)*w));
    }
    if (!lane) {
        atomicAdd(&g_cden[(size_t)b*NS + cell], w);
        g_wpt[p]   = w;
        out_idx[p] = (float)cell;
    }
}

__global__ void k_xdown(float* __restrict__ out_xd) {
    int row  = blockIdx.x*8 + (threadIdx.x>>5);
    int lane = threadIdx.x & 31;
    float rcp = 1.f/(g_cden[row] + EPSV);
    const float4* src = (const float4*)(g_cnum + (size_t)row*COUT);
    float4* dst = (float4*)(out_xd + (size_t)row*COUT);
    #pragma unroll
    for (int q = 0; q < 2; q++) {
        int c4 = q*32 + lane;
        float4 v = src[c4];
        dst[c4] = make_float4(fmaxf(v.x*rcp,0.f), fmaxf(v.y*rcp,0.f),
                              fmaxf(v.z*rcp,0.f), fmaxf(v.w*rcp,0.f));
    }
}

__global__ void k_aggmax(const float* __restrict__ loc, const float* __restrict__ aggw) {
    __shared__ float sm[256];
    int p = blockIdx.x*256 + threadIdx.x;
    int b = p >> 16;
    int cell = grid_cell(loc[2*p], loc[2*p+1], HC, WC);
    float aw = aggw[p] * g_wpt[p] / (g_cden[(size_t)b*NS + cell] + EPSV);
    g_wpt[p] = aw;
    sm[threadIdx.x] = aw;
    __syncthreads();
    for (int s = 128; s; s >>= 1) {
        if (threadIdx.x < s) sm[threadIdx.x] = fmaxf(sm[threadIdx.x], sm[threadIdx.x+s]);
        __syncthreads();
    }
    if (!threadIdx.x) atomicMax(&g_maxw[b], __float_as_uint(sm[0]));
}

__global__ void k_aggnorm(float* __restrict__ out_aw) {
    int p = blockIdx.x*256 + threadIdx.x;
    int b = p >> 16;
    out_aw[p] = g_wpt[p] / __uint_as_float(g_maxw[b]);
}

// ---------------- launch ----------------
extern "C" void kernel_launch(void* const* d_in, const int* in_sizes, int n_in,
                              void* d_out, int out_size) {
    const float* x      = (const float*)d_in[0];
    const float* loc    = (const float*)d_in[1];
    const int*   idxa   = (const int*)  d_in[2];
    const float* aggw   = (const float*)d_in[3];
    const float* conv_w = (const float*)d_in[4];
    const float* conv_b = (const float*)d_in[5];
    const float* skip_w = (const float*)d_in[6];
    const float* gamma  = (const float*)d_in[7];
    const float* beta   = (const float*)d_in[8];
    const float* conf_w = (const float*)d_in[9];
    const float* conf_b = (const float*)d_in[10];

    float* out      = (float*)d_out;
    float* out_xd   = out;                                    // [4,4096,256]
    float* out_xout = out + (size_t)BB*NS*COUT;               // [4,16384,256]
    float* out_conf = out_xout + (size_t)BB*NN*COUT;          // [4,16384,1]
    float* out_aw   = out_conf + (size_t)BB*NN;               // [4,65536,1]
    float* out_idx  = out_aw   + (size_t)BB*NP;               // [4,65536]

    cudaFuncSetAttribute(k_conv, cudaFuncAttributeMaxDynamicSharedMemorySize, CV_SMEM);
    cudaFuncSetAttribute(k_skip, cudaFuncAttributeMaxDynamicSharedMemorySize, CV_SMEM);

    k_init<<<2048, 256>>>(x, skip_w, conv_w);
    k_token2map<<<BB*NP/8, 256>>>(x, loc, idxa);
    k_norm<<<(BB*HH*WW*CIN/4)/256, 256>>>();
    k_conv<<<dim3(HD, 2, BB), 256, CV_SMEM>>>(conv_b);
    k_map2token<<<BB*NP/8, 256>>>(loc, idxa, aggw);
    k_skip<<<dim3(BB*NN/128, 2), 256, CV_SMEM>>>();
    k_bnfinal<<<1, 256>>>(gamma, beta);
    k_bnconf<<<BB*NN/8, 256>>>(conf_w, conf_b, out_xout, out_conf);
    k_cluster<<<BB*NP/8, 256>>>(loc, idxa, out_idx);
    k_xdown<<<BB*NS/8, 256>>>(out_xd);
    k_aggmax<<<BB*NP/256, 256>>>(loc, aggw);
    k_aggnorm<<<BB*NP/256, 256>>>(out_aw);
}

// round 15
// speedup vs baseline: 2.4191x; 1.0330x over previous
#include <cuda_runtime.h>
#include <cuda_fp16.h>
#include <math.h>
#include <stdint.h>

#define BB   4
#define NN   16384
#define CIN  128
#define COUT 256
#define HH   256
#define WW   256
#define NP   65536      // N0 = H*W points
#define HD   128
#define WD   128
#define HC   64
#define WC   64
#define NS   4096       // HC*WC
#define EPSV 1e-6f
#define KTOT 1152       // 9*CIN
#define SLABS 36        // KTOT/32

// ---------------- scratch (device globals: no allocation allowed) ----------------
__device__ float  g_cnt [(size_t)BB*HH*WW];       // token2map count
__device__ uint2  g_mapH[(size_t)BB*HH*WW*CIN/4]; // fp16 map: accum then normalized (64MB)
__device__ __half g_yH  [(size_t)BB*HD*WD*COUT];  // conv output fp16 (32MB)
__device__ uint2  g_xH  [(size_t)BB*NN*CIN/4];    // x in fp16 (16MB)
__device__ float  g_num [(size_t)BB*NN*COUT];     // map2token num -> tok (64MB)
__device__ float  g_den [(size_t)BB*NN];
__device__ float  g_wexp[(size_t)BB*NN];          // exp(conf)
__device__ float  g_bnsumF[COUT];
__device__ float  g_bnsqF [COUT];
__device__ float  g_scale[COUT];
__device__ float  g_shift[COUT];
__device__ float  g_cnum[(size_t)BB*NS*COUT];     // cluster num (16MB)
__device__ float  g_cden[(size_t)BB*NS];
__device__ float  g_wpt [(size_t)BB*NP];          // per-point weight, reused
__device__ unsigned g_maxw[BB];
__device__ uint2  g_wBh [(size_t)SLABS*2048];     // conv weights fp16 frag image per slab
__device__ uint2  g_wSh [(size_t)4*2048];         // skip weights fp16 frag image (4 slabs)

// ---------------- helpers ----------------
__device__ __forceinline__ void red_add4(float* p, float4 v) {
    asm volatile("red.global.add.v4.f32 [%0], {%1,%2,%3,%4};"
                 :: "l"(__cvta_generic_to_global(p)),
                    "f"(v.x), "f"(v.y), "f"(v.z), "f"(v.w) : "memory");
}

__device__ __forceinline__ int grid_cell(float lx, float ly, int Hg, int Wg) {
    lx = fminf(fmaxf(lx, -1.f), 1.f);
    ly = fminf(fmaxf(ly, -1.f), 1.f);
    int px = min(max(__float2int_rn(0.5f*(lx+1.f)*(float)Wg - 0.5f), 0), Wg-1);
    int py = min(max(__float2int_rn(0.5f*(ly+1.f)*(float)Hg - 0.5f), 0), Hg-1);
    return py*Wg + px;
}

__device__ __forceinline__ uint32_t packh2(float lo, float hi) {
    __half2 h = __floats2half2_rn(lo, hi);
    return *(uint32_t*)&h;
}

__device__ __forceinline__ uint32_t smem_u32(const void* p) {
    uint32_t a;
    asm("{ .reg .u64 t; cvta.to.shared.u64 t, %1; cvt.u32.u64 %0, t; }" : "=r"(a) : "l"(p));
    return a;
}

__device__ __forceinline__ void cpa16(uint32_t dst, const void* src, int srcsz) {
    asm volatile("cp.async.cg.shared.global [%0], [%1], 16, %2;"
                 :: "r"(dst), "l"(__cvta_generic_to_global(src)), "r"(srcsz) : "memory");
}

__device__ __forceinline__ void mma16(float& d0, float& d1, float& d2, float& d3,
                                      uint32_t a0, uint32_t a1, uint32_t a2, uint32_t a3,
                                      uint32_t b0, uint32_t b1) {
    asm volatile("mma.sync.aligned.m16n8k16.row.col.f32.f16.f16.f32 "
                 "{%0,%1,%2,%3},{%4,%5,%6,%7},{%8,%9},{%0,%1,%2,%3};"
                 : "+f"(d0), "+f"(d1), "+f"(d2), "+f"(d3)
                 : "r"(a0), "r"(a1), "r"(a2), "r"(a3), "r"(b0), "r"(b1));
}

__device__ __forceinline__ int aswz(int r, int c) {      // 16B-chunk swizzle
    return c ^ (r & 3) ^ ((r >> 2) & 1);
}
__device__ __forceinline__ uint32_t a_word(const char* sA, int r, int w) {  // w 0..15
    int off = r*64 + aswz(r, w >> 2)*16 + (w & 3)*4;
    return *(const uint32_t*)(sA + off);
}

// ---------------- kernels ----------------
// fused: zero accumulators + fp16 conv/skip B images + fp16 copy of x
__global__ void k_init(const float* __restrict__ x, const float* __restrict__ skw,
                       const float* __restrict__ cw) {
    size_t t = (size_t)blockIdx.x*blockDim.x + threadIdx.x;
    size_t stride = (size_t)gridDim.x*blockDim.x;
    float4 z = make_float4(0.f,0.f,0.f,0.f);
    for (size_t i=t; i < (size_t)BB*HH*WW*CIN/8; i+=stride) ((float4*)g_mapH)[i]=z;
    for (size_t i=t; i < (size_t)BB*HH*WW/4;     i+=stride) ((float4*)g_cnt )[i]=z;
    for (size_t i=t; i < (size_t)BB*NN*COUT/4;   i+=stride) ((float4*)g_num )[i]=z;
    for (size_t i=t; i < (size_t)BB*NN/4;        i+=stride) ((float4*)g_den )[i]=z;
    for (size_t i=t; i < (size_t)BB*NS*COUT/4;   i+=stride) ((float4*)g_cnum)[i]=z;
    for (size_t i=t; i < (size_t)BB*NS/4;        i+=stride) ((float4*)g_cden)[i]=z;
    for (size_t i=t; i < (size_t)BB*NN*CIN/4;    i+=stride) {
        float4 v = ((const float4*)x)[i];
        uint2 h; h.x = packh2(v.x, v.y); h.y = packh2(v.z, v.w);
        g_xH[i] = h;
    }
    if (t < COUT) { g_bnsumF[t]=0.f; g_bnsqF[t]=0.f; }
    if (t < BB)   g_maxw[t]=0u;
    if (t < (size_t)SLABS*2048) {
        int fi = (int)t;
        int s   = fi >> 11, r = fi & 2047;
        int nh  = r >> 10;  int r2 = r & 1023;
        int ntF = r2 >> 6, h16 = (r2 >> 5) & 1, g = (r2 >> 2) & 7, cl = r2 & 3;
        int n   = nh*128 + ntF*8 + g;
        int k0  = s*32 + h16*16 + 2*cl;
        uint2 v;
        v.x = packh2(cw[(size_t)k0*COUT + n],     cw[(size_t)(k0+1)*COUT + n]);
        v.y = packh2(cw[(size_t)(k0+8)*COUT + n], cw[(size_t)(k0+9)*COUT + n]);
        g_wBh[fi] = v;
    }
    if (t < (size_t)4*2048) {
        int fi = (int)t;
        int s   = fi >> 11, r = fi & 2047;
        int nh  = r >> 10;  int r2 = r & 1023;
        int ntF = r2 >> 6, h16 = (r2 >> 5) & 1, g = (r2 >> 2) & 7, cl = r2 & 3;
        int n   = nh*128 + ntF*8 + g;
        int k0  = s*32 + h16*16 + 2*cl;
        const float* wr = skw + (size_t)n*CIN;     // skip_w[n][k]
        uint2 v;
        v.x = packh2(wr[k0],   wr[k0+1]);
        v.y = packh2(wr[k0+8], wr[k0+9]);
        g_wSh[fi] = v;
    }
}

// scatter fp16 token features into fp16 map (sum via f16x2 atomics + count)
__global__ void k_token2map(const float* __restrict__ loc, const int* __restrict__ idx_agg) {
    int p    = blockIdx.x*8 + (threadIdx.x>>5);
    int lane = threadIdx.x & 31;
    int b    = p >> 16;
    float lx = loc[2*p], ly = loc[2*p+1];
    int cell = grid_cell(lx, ly, HH, WW);
    int i    = idx_agg[p];
    uint2 v = g_xH[((size_t)b*NN + i)*CIN/4 + lane];
    __half2* dst = (__half2*)((__half*)g_mapH + ((size_t)b*HH*WW + cell)*CIN + lane*4);
    atomicAdd(dst,     *(__half2*)&v.x);
    atomicAdd(dst + 1, *(__half2*)&v.y);
    if (!lane) atomicAdd(&g_cnt[(size_t)b*HH*WW + cell], 1.0f);
}

// normalize fp16 map in place
__global__ void k_norm() {
    size_t i = (size_t)blockIdx.x*256 + threadIdx.x;
    float rcp = 1.f/(g_cnt[i >> 5] + EPSV);
    uint2 h = g_mapH[i];
    float2 a = __half22float2(*(__half2*)&h.x);
    float2 c = __half22float2(*(__half2*)&h.y);
    uint2 o;
    o.x = packh2(a.x*rcp, a.y*rcp);
    o.y = packh2(c.x*rcp, c.y*rcp);
    g_mapH[i] = o;
}

// ---- 3x3 stride-2 conv as implicit GEMM on mma.sync FP16 (m16n8k16) ----
#define CV_BUF   16384
#define CV_A(i)  ((i)*CV_BUF)
#define CV_B(i)  ((i)*CV_BUF + 8192)
#define CV_BIAS  (3*CV_BUF)
#define CV_SMEM  (CV_BIAS + 1024)

__global__ void __launch_bounds__(256, 2) k_conv(const float* __restrict__ cb) {
    extern __shared__ char smem[];
    uint32_t sb = smem_u32(smem);
    int tid = threadIdx.x, w = tid >> 5, lane = tid & 31;
    int g = lane >> 2, cl = lane & 3;
    int wm = w & 3, wn = w >> 2;                 // warp tile 32m x 64n
    int oy = blockIdx.x, nh = blockIdx.y, b = blockIdx.z;

    if (tid < 128) *(float*)(smem + CV_BIAS + tid*4) = cb[nh*128 + tid];

    float acc[2][8][4];
    #pragma unroll
    for (int mt=0;mt<2;mt++) for (int nt=0;nt<8;nt++) for (int r2=0;r2<4;r2++) acc[mt][nt][r2]=0.f;

    auto stage = [&](int s, int buf) {
        int tap = s >> 2, cinb = (s & 3) * 32;
        int ky = tap / 3, kx = tap - 3*ky;
        int iy = 2*oy - 1 + ky;
        bool iyok = (unsigned)iy < HH;
        int r = tid >> 1, c0 = (tid & 1) * 2;
        int ix = 2*r - 1 + kx;
        bool ok = iyok && ((unsigned)ix < WW);
        const __half* src = (const __half*)g_mapH
            + ((size_t)b*HH*WW + (size_t)(iyok ? iy : 0)*WW + (ok ? ix : 0))*CIN + cinb;
        uint32_t dstA = sb + CV_A(buf) + r*64;
        int sz = ok ? 16 : 0;
        #pragma unroll
        for (int j = 0; j < 2; j++) {
            int c = c0 + j;
            cpa16(dstA + aswz(r, c)*16, src + c*8, sz);
        }
        const uint2* bsrc = g_wBh + (size_t)s*2048 + nh*1024 + tid*4;
        uint32_t dstB = sb + CV_B(buf) + tid*32;
        cpa16(dstB,      bsrc,     16);
        cpa16(dstB + 16, bsrc + 2, 16);
        asm volatile("cp.async.commit_group;" ::: "memory");
    };

    stage(0, 0);
    stage(1, 1);

    int bufc = 0;
    for (int s = 0; s < SLABS; s++) {
        if (s < SLABS-1) asm volatile("cp.async.wait_group 1;" ::: "memory");
        else             asm volatile("cp.async.wait_group 0;" ::: "memory");
        __syncthreads();
        int bufn = bufc + 2; if (bufn >= 3) bufn -= 3;
        if (s + 2 < SLABS) stage(s + 2, bufn);
        const char*  sA = smem + CV_A(bufc);
        const uint2* sB = (const uint2*)(smem + CV_B(bufc));
        #pragma unroll
        for (int h16 = 0; h16 < 2; h16++) {
            uint2 bv[8];
            #pragma unroll
            for (int nt = 0; nt < 8; nt++)
                bv[nt] = sB[(wn*8 + nt)*64 + h16*32 + g*4 + cl];
            uint32_t a[2][4];
            #pragma unroll
            for (int mt = 0; mt < 2; mt++) {
                int r0 = wm*32 + mt*16 + g;
                a[mt][0] = a_word(sA, r0,     h16*8 + cl);
                a[mt][1] = a_word(sA, r0 + 8, h16*8 + cl);
                a[mt][2] = a_word(sA, r0,     h16*8 + cl + 4);
                a[mt][3] = a_word(sA, r0 + 8, h16*8 + cl + 4);
            }
            #pragma unroll
            for (int mt = 0; mt < 2; mt++)
                #pragma unroll
                for (int nt = 0; nt < 8; nt++)
                    mma16(acc[mt][nt][0], acc[mt][nt][1], acc[mt][nt][2], acc[mt][nt][3],
                          a[mt][0], a[mt][1], a[mt][2], a[mt][3],
                          bv[nt].x, bv[nt].y);
        }
        bufc++; if (bufc >= 3) bufc = 0;
    }

    // epilogue: write fp16 y
    const float* bias = (const float*)(smem + CV_BIAS);
    __half* ybase = g_yH + (((size_t)b*HD + oy)*WD)*COUT + nh*128;
    #pragma unroll
    for (int mt = 0; mt < 2; mt++) {
        int ox0 = wm*32 + mt*16 + g;
        #pragma unroll
        for (int nt = 0; nt < 8; nt++) {
            int n = wn*64 + nt*8 + cl*2;
            float b0 = bias[n], b1 = bias[n+1];
            *(uint32_t*)(ybase + (size_t)ox0*COUT + n)     = packh2(acc[mt][nt][0]+b0, acc[mt][nt][1]+b1);
            *(uint32_t*)(ybase + (size_t)(ox0+8)*COUT + n) = packh2(acc[mt][nt][2]+b0, acc[mt][nt][3]+b1);
        }
    }
}

// bilinear gather from fp16 conv map at orig points, weighted scatter to tokens
__global__ void k_map2token(const float* __restrict__ loc, const int* __restrict__ idx_agg,
                            const float* __restrict__ aggw) {
    int p    = blockIdx.x*8 + (threadIdx.x>>5);
    int lane = threadIdx.x & 31;
    int b    = p >> 16;
    float lx = fminf(fmaxf(loc[2*p],   -1.f), 1.f);
    float ly = fminf(fmaxf(loc[2*p+1], -1.f), 1.f);
    float fx = fminf(fmaxf(0.5f*(lx+1.f)*(float)WD - 0.5f, 0.f), (float)(WD-1));
    float fy = fminf(fmaxf(0.5f*(ly+1.f)*(float)HD - 0.5f, 0.f), (float)(HD-1));
    float x0f = floorf(fx), y0f = floorf(fy);
    float wx = fx - x0f, wy = fy - y0f;
    int x0 = (int)x0f, y0 = (int)y0f;
    int x1 = min(x0+1, WD-1), y1 = min(y0+1, HD-1);
    const __half* base = g_yH + (size_t)b*HD*WD*COUT;
    const uint4* r00 = (const uint4*)(base + (size_t)(y0*WD+x0)*COUT);
    const uint4* r01 = (const uint4*)(base + (size_t)(y0*WD+x1)*COUT);
    const uint4* r10 = (const uint4*)(base + (size_t)(y1*WD+x0)*COUT);
    const uint4* r11 = (const uint4*)(base + (size_t)(y1*WD+x1)*COUT);
    float w00=(1.f-wx)*(1.f-wy), w01=wx*(1.f-wy), w10=(1.f-wx)*wy, w11=wx*wy;
    float wpt = aggw[p];
    int i = idx_agg[p];
    float* dst = g_num + ((size_t)b*NN + i)*COUT + lane*8;
    uint4 ua = r00[lane], ub = r01[lane], uc = r10[lane], ud = r11[lane];
    const uint32_t* pa = (const uint32_t*)&ua;
    const uint32_t* pb = (const uint32_t*)&ub;
    const uint32_t* pc = (const uint32_t*)&uc;
    const uint32_t* pd = (const uint32_t*)&ud;
    #pragma unroll
    for (int q = 0; q < 2; q++) {
        float2 a0 = __half22float2(*(__half2*)&pa[2*q]),   a1 = __half22float2(*(__half2*)&pa[2*q+1]);
        float2 b0 = __half22float2(*(__half2*)&pb[2*q]),   b1 = __half22float2(*(__half2*)&pb[2*q+1]);
        float2 c0 = __half22float2(*(__half2*)&pc[2*q]),   c1 = __half22float2(*(__half2*)&pc[2*q+1]);
        float2 d0 = __half22float2(*(__half2*)&pd[2*q]),   d1 = __half22float2(*(__half2*)&pd[2*q+1]);
        float4 f;
        f.x = (w00*a0.x + w01*b0.x + w10*c0.x + w11*d0.x)*wpt;
        f.y = (w00*a0.y + w01*b0.y + w10*c0.y + w11*d0.y)*wpt;
        f.z = (w00*a1.x + w01*b1.x + w10*c1.x + w11*d1.x)*wpt;
        f.w = (w00*a1.y + w01*b1.y + w10*c1.y + w11*d1.y)*wpt;
        red_add4(dst + q*4, f);
    }
    if (!lane) atomicAdd(&g_den[(size_t)b*NN + i], wpt);
}

// ---- skip GEMM (x @ skip_w^T) on FP16 mma.sync + fused BN partial stats ----
__global__ void __launch_bounds__(256, 2) k_skip() {
    extern __shared__ char smem[];
    uint32_t sb = smem_u32(smem);
    int tid = threadIdx.x, w = tid >> 5, lane = tid & 31;
    int g = lane >> 2, cl = lane & 3;
    int wm = w & 3, wn = w >> 2;
    int m0 = blockIdx.x * 128, nh = blockIdx.y;
    const __half* xrow = (const __half*)g_xH + (size_t)m0*CIN;
    float* s_sum = (float*)(smem + CV_BIAS);        // [128]
    float* s_sq  = (float*)(smem + CV_BIAS + 512);  // [128]

    if (tid < 256) *(float*)(smem + CV_BIAS + tid*4) = 0.f;

    float acc[2][8][4];
    #pragma unroll
    for (int mt=0;mt<2;mt++) for (int nt=0;nt<8;nt++) for (int r2=0;r2<4;r2++) acc[mt][nt][r2]=0.f;

    auto stage = [&](int s, int buf) {
        int r = tid >> 1, c0 = (tid & 1) * 2;
        const __half* src = xrow + (size_t)r*CIN + s*32;
        uint32_t dstA = sb + CV_A(buf) + r*64;
        #pragma unroll
        for (int j = 0; j < 2; j++) {
            int c = c0 + j;
            cpa16(dstA + aswz(r, c)*16, src + c*8, 16);
        }
        const uint2* bsrc = g_wSh + (size_t)s*2048 + nh*1024 + tid*4;
        uint32_t dstB = sb + CV_B(buf) + tid*32;
        cpa16(dstB,      bsrc,     16);
        cpa16(dstB + 16, bsrc + 2, 16);
        asm volatile("cp.async.commit_group;" ::: "memory");
    };

    stage(0, 0);
    stage(1, 1);

    int bufc = 0;
    for (int s = 0; s < 4; s++) {
        if (s < 3) asm volatile("cp.async.wait_group 1;" ::: "memory");
        else       asm volatile("cp.async.wait_group 0;" ::: "memory");
        __syncthreads();
        int bufn = bufc + 2; if (bufn >= 3) bufn -= 3;
        if (s + 2 < 4) stage(s + 2, bufn);
        const char*  sA = smem + CV_A(bufc);
        const uint2* sB = (const uint2*)(smem + CV_B(bufc));
        #pragma unroll
        for (int h16 = 0; h16 < 2; h16++) {
            uint2 bv[8];
            #pragma unroll
            for (int nt = 0; nt < 8; nt++)
                bv[nt] = sB[(wn*8 + nt)*64 + h16*32 + g*4 + cl];
            uint32_t a[2][4];
            #pragma unroll
            for (int mt = 0; mt < 2; mt++) {
                int r0 = wm*32 + mt*16 + g;
                a[mt][0] = a_word(sA, r0,     h16*8 + cl);
                a[mt][1] = a_word(sA, r0 + 8, h16*8 + cl);
                a[mt][2] = a_word(sA, r0,     h16*8 + cl + 4);
                a[mt][3] = a_word(sA, r0 + 8, h16*8 + cl + 4);
            }
            #pragma unroll
            for (int mt = 0; mt < 2; mt++)
                #pragma unroll
                for (int nt = 0; nt < 8; nt++)
                    mma16(acc[mt][nt][0], acc[mt][nt][1], acc[mt][nt][2], acc[mt][nt][3],
                          a[mt][0], a[mt][1], a[mt][2], a[mt][3],
                          bv[nt].x, bv[nt].y);
        }
        bufc++; if (bufc >= 3) bufc = 0;
    }

    // epilogue: tok = acc + num*rcp(den) -> g_num, plus per-channel partial stats
    float rcp[2][2];
    float* nb[2][2];
    #pragma unroll
    for (int mt = 0; mt < 2; mt++) {
        int r0 = wm*32 + mt*16 + g;
        int row0 = m0 + r0, row1 = row0 + 8;
        rcp[mt][0] = 1.f/(g_den[row0] + EPSV);
        rcp[mt][1] = 1.f/(g_den[row1] + EPSV);
        nb[mt][0] = g_num + (size_t)row0*COUT + nh*128;
        nb[mt][1] = g_num + (size_t)row1*COUT + nh*128;
    }
    #pragma unroll
    for (int nt = 0; nt < 8; nt++) {
        int n = wn*64 + nt*8 + cl*2;
        float s0=0.f, s1=0.f, q0=0.f, q1=0.f;
        #pragma unroll
        for (int mt = 0; mt < 2; mt++) {
            float2 v0 = *(float2*)(nb[mt][0] + n);
            float2 v1 = *(float2*)(nb[mt][1] + n);
            float t0 = acc[mt][nt][0] + v0.x*rcp[mt][0];
            float t1 = acc[mt][nt][1] + v0.y*rcp[mt][0];
            float t2 = acc[mt][nt][2] + v1.x*rcp[mt][1];
            float t3 = acc[mt][nt][3] + v1.y*rcp[mt][1];
            *(float2*)(nb[mt][0] + n) = make_float2(t0, t1);
            *(float2*)(nb[mt][1] + n) = make_float2(t2, t3);
            s0 += t0 + t2; s1 += t1 + t3;
            q0 += t0*t0 + t2*t2; q1 += t1*t1 + t3*t3;
        }
        atomicAdd(&s_sum[n],   s0);
        atomicAdd(&s_sum[n+1], s1);
        atomicAdd(&s_sq[n],    q0);
        atomicAdd(&s_sq[n+1],  q1);
    }
    __syncthreads();
    if (tid < 128) {
        atomicAdd(&g_bnsumF[nh*128 + tid], s_sum[tid]);
        atomicAdd(&g_bnsqF [nh*128 + tid], s_sq[tid]);
    }
}

__global__ void k_bnfinal(const float* __restrict__ gam, const float* __restrict__ bet) {
    int c = threadIdx.x;
    float m  = (float)(BB*NN);
    float mu = g_bnsumF[c]/m;
    float var = g_bnsqF[c]/m - mu*mu;
    float sc = gam[c] * rsqrtf(var + 1e-5f);
    g_scale[c] = sc;
    g_shift[c] = bet[c] - mu*sc;
}

// apply BN on the fly: write x_out = relu(bn(tok)), conf, exp(conf)
__global__ void k_bnconf(const float* __restrict__ cw, const float* __restrict__ cbv,
                         float* __restrict__ out_xout, float* __restrict__ out_conf) {
    int row  = blockIdx.x*8 + (threadIdx.x>>5);
    int lane = threadIdx.x & 31;
    const float4* t  = (const float4*)(g_num  + (size_t)row*COUT);
    float4* xo       = (float4*)(out_xout + (size_t)row*COUT);
    float dot = 0.f;
    #pragma unroll
    for (int q = 0; q < 2; q++) {
        int c4 = q*32 + lane;
        float4 v  = t[c4];
        float4 sc = ((const float4*)g_scale)[c4];
        float4 sh = ((const float4*)g_shift)[c4];
        float4 w  = ((const float4*)cw)[c4];
        float4 r = make_float4(v.x*sc.x+sh.x, v.y*sc.y+sh.y, v.z*sc.z+sh.z, v.w*sc.w+sh.w);
        dot += r.x*w.x + r.y*w.y + r.z*w.z + r.w*w.w;
        xo[c4] = make_float4(fmaxf(r.x,0.f), fmaxf(r.y,0.f), fmaxf(r.z,0.f), fmaxf(r.w,0.f));
    }
    #pragma unroll
    for (int o = 16; o; o >>= 1) dot += __shfl_xor_sync(0xffffffffu, dot, o);
    if (!lane) {
        float cf = dot + cbv[0];
        out_conf[row] = cf;
        g_wexp[row]   = expf(cf);
    }
}

// gather tok from g_num, apply BN inline, weighted scatter into 64x64 cells
__global__ void k_cluster(const float* __restrict__ loc, const int* __restrict__ idx_agg,
                          float* __restrict__ out_idx) {
    int p    = blockIdx.x*8 + (threadIdx.x>>5);
    int lane = threadIdx.x & 31;
    int b    = p >> 16;
    int cell = grid_cell(loc[2*p], loc[2*p+1], HC, WC);
    int i    = idx_agg[p];
    float w  = g_wexp[(size_t)b*NN + i];
    const float4* src = (const float4*)(g_num + ((size_t)b*NN + i)*COUT);
    float* dst = g_cnum + ((size_t)b*NS + cell)*COUT;
    #pragma unroll
    for (int q = 0; q < 2; q++) {
        int c4 = q*32 + lane;
        float4 v  = src[c4];
        float4 sc = ((const float4*)g_scale)[c4];
        float4 sh = ((const float4*)g_shift)[c4];
        red_add4(dst + c4*4, make_float4((v.x*sc.x+sh.x)*w, (v.y*sc.y+sh.y)*w,
                                         (v.z*sc.z+sh.z)*w, (v.w*sc.w+sh.w)*w));
    }
    if (!lane) {
        atomicAdd(&g_cden[(size_t)b*NS + cell], w);
        g_wpt[p]   = w;
        out_idx[p] = (float)cell;
    }
}

__global__ void k_xdown(float* __restrict__ out_xd) {
    int row  = blockIdx.x*8 + (threadIdx.x>>5);
    int lane = threadIdx.x & 31;
    float rcp = 1.f/(g_cden[row] + EPSV);
    const float4* src = (const float4*)(g_cnum + (size_t)row*COUT);
    float4* dst = (float4*)(out_xd + (size_t)row*COUT);
    #pragma unroll
    for (int q = 0; q < 2; q++) {
        int c4 = q*32 + lane;
        float4 v = src[c4];
        dst[c4] = make_float4(fmaxf(v.x*rcp,0.f), fmaxf(v.y*rcp,0.f),
                              fmaxf(v.z*rcp,0.f), fmaxf(v.w*rcp,0.f));
    }
}

__global__ void k_aggmax(const float* __restrict__ loc, const float* __restrict__ aggw) {
    __shared__ float sm[256];
    int p = blockIdx.x*256 + threadIdx.x;
    int b = p >> 16;
    int cell = grid_cell(loc[2*p], loc[2*p+1], HC, WC);
    float aw = aggw[p] * g_wpt[p] / (g_cden[(size_t)b*NS + cell] + EPSV);
    g_wpt[p] = aw;
    sm[threadIdx.x] = aw;
    __syncthreads();
    for (int s = 128; s; s >>= 1) {
        if (threadIdx.x < s) sm[threadIdx.x] = fmaxf(sm[threadIdx.x], sm[threadIdx.x+s]);
        __syncthreads();
    }
    if (!threadIdx.x) atomicMax(&g_maxw[b], __float_as_uint(sm[0]));
}

__global__ void k_aggnorm(float* __restrict__ out_aw) {
    int p = blockIdx.x*256 + threadIdx.x;
    int b = p >> 16;
    out_aw[p] = g_wpt[p] / __uint_as_float(g_maxw[b]);
}

// ---------------- launch ----------------
extern "C" void kernel_launch(void* const* d_in, const int* in_sizes, int n_in,
                              void* d_out, int out_size) {
    const float* x      = (const float*)d_in[0];
    const float* loc    = (const float*)d_in[1];
    const int*   idxa   = (const int*)  d_in[2];
    const float* aggw   = (const float*)d_in[3];
    const float* conv_w = (const float*)d_in[4];
    const float* conv_b = (const float*)d_in[5];
    const float* skip_w = (const float*)d_in[6];
    const float* gamma  = (const float*)d_in[7];
    const float* beta   = (const float*)d_in[8];
    const float* conf_w = (const float*)d_in[9];
    const float* conf_b = (const float*)d_in[10];

    float* out      = (float*)d_out;
    float* out_xd   = out;                                    // [4,4096,256]
    float* out_xout = out + (size_t)BB*NS*COUT;               // [4,16384,256]
    float* out_conf = out_xout + (size_t)BB*NN*COUT;          // [4,16384,1]
    float* out_aw   = out_conf + (size_t)BB*NN;               // [4,65536,1]
    float* out_idx  = out_aw   + (size_t)BB*NP;               // [4,65536]

    cudaFuncSetAttribute(k_conv, cudaFuncAttributeMaxDynamicSharedMemorySize, CV_SMEM);
    cudaFuncSetAttribute(k_skip, cudaFuncAttributeMaxDynamicSharedMemorySize, CV_SMEM);

    k_init<<<2048, 256>>>(x, skip_w, conv_w);
    k_token2map<<<BB*NP/8, 256>>>(loc, idxa);
    k_norm<<<(BB*HH*WW*CIN/4)/256, 256>>>();
    k_conv<<<dim3(HD, 2, BB), 256, CV_SMEM>>>(conv_b);
    k_map2token<<<BB*NP/8, 256>>>(loc, idxa, aggw);
    k_skip<<<dim3(BB*NN/128, 2), 256, CV_SMEM>>>();
    k_bnfinal<<<1, 256>>>(gamma, beta);
    k_bnconf<<<BB*NN/8, 256>>>(conf_w, conf_b, out_xout, out_conf);
    k_cluster<<<BB*NP/8, 256>>>(loc, idxa, out_idx);
    k_xdown<<<BB*NS/8, 256>>>(out_xd);
    k_aggmax<<<BB*NP/256, 256>>>(loc, aggw);
    k_aggnorm<<<BB*NP/256, 256>>>(out_aw);
}